// round 1
// baseline (speedup 1.0000x reference)
#include <cuda_runtime.h>
#include <cstddef>

// ---------------------------------------------------------------------------
// Problem constants
// ---------------------------------------------------------------------------
#define BB 2
#define SS 2048
#define DD 1024
#define HH 16
#define HDIM 64
#define FF 4096
#define MROWS (BB * SS)          // 4096
#define EPS 1e-6f

// ---------------------------------------------------------------------------
// Device scratch (allocation-free rule: __device__ globals)
// ---------------------------------------------------------------------------
__device__ float g_h   [MROWS * DD];
__device__ float g_q   [MROWS * DD];
__device__ float g_k   [MROWS * DD];
__device__ float g_v   [MROWS * DD];
__device__ float g_attn[MROWS * DD];
__device__ float g_x1  [MROWS * DD];
__device__ float g_h2  [MROWS * DD];
__device__ float g_gate[MROWS * FF];
__device__ float g_up  [MROWS * FF];

// ---------------------------------------------------------------------------
// RMSNorm: one block per row of 1024 floats
// ---------------------------------------------------------------------------
__global__ __launch_bounds__(256) void rmsnorm_k(const float* __restrict__ x,
                                                 const float* __restrict__ w,
                                                 float* __restrict__ o) {
    __shared__ float red[8];
    const int row = blockIdx.x;
    const int tid = threadIdx.x;
    const float4* xr = (const float4*)(x + (size_t)row * DD);
    float4 v = xr[tid];
    float ss = v.x * v.x + v.y * v.y + v.z * v.z + v.w * v.w;
#pragma unroll
    for (int off = 16; off > 0; off >>= 1)
        ss += __shfl_xor_sync(0xffffffffu, ss, off);
    if ((tid & 31) == 0) red[tid >> 5] = ss;
    __syncthreads();
    float tot = 0.f;
#pragma unroll
    for (int i = 0; i < 8; i++) tot += red[i];
    const float inv = rsqrtf(tot * (1.0f / DD) + EPS);
    const float4 wv = ((const float4*)w)[tid];
    float4 ov;
    ov.x = wv.x * (v.x * inv);
    ov.y = wv.y * (v.y * inv);
    ov.z = wv.z * (v.z * inv);
    ov.w = wv.w * (v.w * inv);
    ((float4*)(o + (size_t)row * DD))[tid] = ov;
}

// ---------------------------------------------------------------------------
// Tiled fp32 SGEMM: C[M,N] = A[M,K] @ B[K,N] (+bias[N]) (+res[M,N])
// BM=BN=128, BK=16, 256 threads, 8x8 per-thread microtile.
// All shapes here are multiples of the tile sizes -> no bounds checks.
// ---------------------------------------------------------------------------
template <bool BIAS, bool RES>
__global__ __launch_bounds__(256) void sgemm128(const float* __restrict__ A,
                                                const float* __restrict__ Bm,
                                                const float* __restrict__ bias,
                                                const float* __restrict__ res,
                                                float* __restrict__ C,
                                                int M, int N, int K) {
    constexpr int BM = 128, BN = 128, BK = 16, TM = 8, TN = 8;
    __shared__ float As[BK][BM];
    __shared__ float Bs[BK][BN];

    const int tid  = threadIdx.x;
    const int bx   = blockIdx.x, by = blockIdx.y;
    const int tcol = tid % 16, trow = tid / 16;

    float acc[TM][TN];
#pragma unroll
    for (int i = 0; i < TM; i++)
#pragma unroll
        for (int j = 0; j < TN; j++) acc[i][j] = 0.f;

    const float* Ab = A + (size_t)by * BM * K;
    const float* Bb = Bm + (size_t)bx * BN;

    const int aRow  = tid / 4;          // 0..63 (two iterations: +64)
    const int aCol4 = (tid % 4) * 4;    // 0,4,8,12
    const int bRow  = tid / 32;         // 0..7 (two iterations: +8)
    const int bCol4 = (tid % 32) * 4;   // 0..124

    for (int k0 = 0; k0 < K; k0 += BK) {
#pragma unroll
        for (int i = 0; i < 2; i++) {
            const int r = aRow + i * 64;
            float4 t = *(const float4*)(Ab + (size_t)r * K + k0 + aCol4);
            As[aCol4 + 0][r] = t.x;
            As[aCol4 + 1][r] = t.y;
            As[aCol4 + 2][r] = t.z;
            As[aCol4 + 3][r] = t.w;
        }
#pragma unroll
        for (int i = 0; i < 2; i++) {
            const int r = bRow + i * 8;
            *(float4*)(&Bs[r][bCol4]) =
                *(const float4*)(Bb + (size_t)(k0 + r) * N + bCol4);
        }
        __syncthreads();

#pragma unroll
        for (int kk = 0; kk < BK; kk++) {
            float ra[TM], rb[TN];
#pragma unroll
            for (int i = 0; i < TM; i++) ra[i] = As[kk][trow * TM + i];
#pragma unroll
            for (int j = 0; j < TN; j++) rb[j] = Bs[kk][tcol * TN + j];
#pragma unroll
            for (int i = 0; i < TM; i++)
#pragma unroll
                for (int j = 0; j < TN; j++) acc[i][j] += ra[i] * rb[j];
        }
        __syncthreads();
    }

#pragma unroll
    for (int i = 0; i < TM; i++) {
        const int row = by * BM + trow * TM + i;
        const int col = bx * BN + tcol * TN;
        float* cp = C + (size_t)row * N + col;
        const float* rp = RES ? (res + (size_t)row * N + col) : nullptr;
#pragma unroll
        for (int j = 0; j < TN; j++) {
            float vv = acc[i][j];
            if (BIAS) vv += bias[col + j];
            if (RES)  vv += rp[j];
            cp[j] = vv;
        }
    }
}

// ---------------------------------------------------------------------------
// Flash attention (fp32): 64 queries x 64 keys per tile, HD=64.
// q,k,v stored [B,S,D] with head h at cols [h*64, h*64+64).
// KPs buffer holds K^T during score compute, then is reused for P.
// ---------------------------------------------------------------------------
__global__ __launch_bounds__(256) void flash_attn(const float* __restrict__ Q,
                                                  const float* __restrict__ Kg,
                                                  const float* __restrict__ Vg,
                                                  const int* __restrict__ amask,
                                                  float* __restrict__ O) {
    constexpr int BT = 64;     // tile (queries & keys)
    __shared__ float Qs [BT * HDIM];   // [r][d]
    __shared__ float KPs[BT * HDIM];   // Kt: [d][c]  ->  P: [r][c]
    __shared__ float Vs [BT * HDIM];   // [c][d]

    const int qb = blockIdx.x * BT;
    const int h  = blockIdx.y;
    const int b  = blockIdx.z;
    const int tid = threadIdx.x;
    const int tx = tid % 16, ty = tid / 16;

    const size_t base = ((size_t)b * SS) * DD + (size_t)h * HDIM;

    // Load Q tile: 1024 float4 / 256 threads = 4 per thread
#pragma unroll
    for (int it = 0; it < 4; it++) {
        const int idx = tid + it * 256;
        const int r = idx / 16, c4 = (idx % 16) * 4;
        float4 t = *(const float4*)(Q + base + (size_t)(qb + r) * DD + c4);
        *(float4*)(&Qs[r * HDIM + c4]) = t;
    }

    float m[4], l[4], o[4][4];
#pragma unroll
    for (int i = 0; i < 4; i++) {
        m[i] = -1e30f;
        l[i] = 0.f;
#pragma unroll
        for (int j = 0; j < 4; j++) o[i][j] = 0.f;
    }

    for (int kb = 0; kb <= qb; kb += BT) {
        // Load K (transposed into KPs) and V
#pragma unroll
        for (int it = 0; it < 4; it++) {
            const int idx = tid + it * 256;
            const int c = idx / 16, d4 = (idx % 16) * 4;
            float4 kv = *(const float4*)(Kg + base + (size_t)(kb + c) * DD + d4);
            KPs[(d4 + 0) * BT + c] = kv.x;
            KPs[(d4 + 1) * BT + c] = kv.y;
            KPs[(d4 + 2) * BT + c] = kv.z;
            KPs[(d4 + 3) * BT + c] = kv.w;
            float4 vv = *(const float4*)(Vg + base + (size_t)(kb + c) * DD + d4);
            *(float4*)(&Vs[c * HDIM + d4]) = vv;
        }
        __syncthreads();

        // Scores s = Q @ K^T * scale
        float s[4][4];
#pragma unroll
        for (int i = 0; i < 4; i++)
#pragma unroll
            for (int j = 0; j < 4; j++) s[i][j] = 0.f;

        for (int d = 0; d < HDIM; d++) {
            float ra[4], rc[4];
#pragma unroll
            for (int i = 0; i < 4; i++) ra[i] = Qs[(ty * 4 + i) * HDIM + d];
#pragma unroll
            for (int j = 0; j < 4; j++) rc[j] = KPs[d * BT + tx * 4 + j];
#pragma unroll
            for (int i = 0; i < 4; i++)
#pragma unroll
                for (int j = 0; j < 4; j++) s[i][j] += ra[i] * rc[j];
        }

        // key mask (attention_mask) + causal on diagonal tile
        int mv[4];
#pragma unroll
        for (int j = 0; j < 4; j++) mv[j] = amask[(size_t)b * SS + kb + tx * 4 + j];

#pragma unroll
        for (int i = 0; i < 4; i++) {
            const int qi = qb + ty * 4 + i;
#pragma unroll
            for (int j = 0; j < 4; j++) {
                const int kj = kb + tx * 4 + j;
                float vv = s[i][j] * 0.125f;   // 1/sqrt(64)
                if ((kb == qb && kj > qi) || (mv[j] == 0)) vv = -1e30f;
                s[i][j] = vv;
            }
        }

        // online softmax
#pragma unroll
        for (int i = 0; i < 4; i++) {
            float rm = s[i][0];
#pragma unroll
            for (int j = 1; j < 4; j++) rm = fmaxf(rm, s[i][j]);
#pragma unroll
            for (int off = 8; off > 0; off >>= 1)
                rm = fmaxf(rm, __shfl_xor_sync(0xffffffffu, rm, off));
            const float mn = fmaxf(m[i], rm);
            const float corr = __expf(m[i] - mn);
            float rs = 0.f;
#pragma unroll
            for (int j = 0; j < 4; j++) {
                s[i][j] = __expf(s[i][j] - mn);
                rs += s[i][j];
            }
#pragma unroll
            for (int off = 8; off > 0; off >>= 1)
                rs += __shfl_xor_sync(0xffffffffu, rs, off);
            l[i] = l[i] * corr + rs;
            m[i] = mn;
#pragma unroll
            for (int j = 0; j < 4; j++) o[i][j] *= corr;
        }

        __syncthreads();                 // done reading KPs as K^T
#pragma unroll
        for (int i = 0; i < 4; i++) {
            float4 pv = make_float4(s[i][0], s[i][1], s[i][2], s[i][3]);
            *(float4*)(&KPs[(ty * 4 + i) * BT + tx * 4]) = pv;
        }
        __syncthreads();

        // O += P @ V
        for (int kk = 0; kk < BT; kk++) {
            float rp[4], rv[4];
#pragma unroll
            for (int i = 0; i < 4; i++) rp[i] = KPs[(ty * 4 + i) * BT + kk];
#pragma unroll
            for (int j = 0; j < 4; j++) rv[j] = Vs[kk * HDIM + tx * 4 + j];
#pragma unroll
            for (int i = 0; i < 4; i++)
#pragma unroll
                for (int j = 0; j < 4; j++) o[i][j] += rp[i] * rv[j];
        }
        __syncthreads();                 // before next tile overwrites KPs/Vs
    }

#pragma unroll
    for (int i = 0; i < 4; i++) {
        const float inv = 1.0f / l[i];
        float4 ov = make_float4(o[i][0] * inv, o[i][1] * inv,
                                o[i][2] * inv, o[i][3] * inv);
        *(float4*)(O + base + (size_t)(qb + ty * 4 + i) * DD + tx * 4) = ov;
    }
}

// ---------------------------------------------------------------------------
// act = silu(gate) * up   (elementwise, float4)
// ---------------------------------------------------------------------------
__global__ __launch_bounds__(256) void silu_mul_k(const float* __restrict__ g,
                                                  const float* __restrict__ u,
                                                  float* __restrict__ o) {
    const size_t i = (size_t)blockIdx.x * blockDim.x + threadIdx.x;
    float4 gv = ((const float4*)g)[i];
    float4 uv = ((const float4*)u)[i];
    float4 ov;
    ov.x = gv.x / (1.f + __expf(-gv.x)) * uv.x;
    ov.y = gv.y / (1.f + __expf(-gv.y)) * uv.y;
    ov.z = gv.z / (1.f + __expf(-gv.z)) * uv.z;
    ov.w = gv.w / (1.f + __expf(-gv.w)) * uv.w;
    ((float4*)o)[i] = ov;
}

// ---------------------------------------------------------------------------
// Launch
// ---------------------------------------------------------------------------
extern "C" void kernel_launch(void* const* d_in, const int* in_sizes, int n_in,
                              void* d_out, int out_size) {
    const float* x       = (const float*)d_in[0];
    const int*   amask   = (const int*)  d_in[1];
    const float* w_norm1 = (const float*)d_in[2];
    const float* wq      = (const float*)d_in[3];
    const float* bq      = (const float*)d_in[4];
    const float* wk      = (const float*)d_in[5];
    const float* bk      = (const float*)d_in[6];
    const float* wv      = (const float*)d_in[7];
    const float* bv      = (const float*)d_in[8];
    const float* wo      = (const float*)d_in[9];
    const float* bo      = (const float*)d_in[10];
    const float* w_norm2 = (const float*)d_in[11];
    const float* w_gate  = (const float*)d_in[12];
    const float* w_up    = (const float*)d_in[13];
    const float* w_down  = (const float*)d_in[14];
    float* out = (float*)d_out;

    float *h, *q, *k, *v, *attn, *x1, *h2, *gate, *up;
    cudaGetSymbolAddress((void**)&h,    g_h);
    cudaGetSymbolAddress((void**)&q,    g_q);
    cudaGetSymbolAddress((void**)&k,    g_k);
    cudaGetSymbolAddress((void**)&v,    g_v);
    cudaGetSymbolAddress((void**)&attn, g_attn);
    cudaGetSymbolAddress((void**)&x1,   g_x1);
    cudaGetSymbolAddress((void**)&h2,   g_h2);
    cudaGetSymbolAddress((void**)&gate, g_gate);
    cudaGetSymbolAddress((void**)&up,   g_up);

    const dim3 gD(DD / 128, MROWS / 128);   // N=1024 GEMMs
    const dim3 gF(FF / 128, MROWS / 128);   // N=4096 GEMMs

    // attention sub-block
    rmsnorm_k<<<MROWS, 256>>>(x, w_norm1, h);
    sgemm128<true, false><<<gD, 256>>>(h, wq, bq, nullptr, q, MROWS, DD, DD);
    sgemm128<true, false><<<gD, 256>>>(h, wk, bk, nullptr, k, MROWS, DD, DD);
    sgemm128<true, false><<<gD, 256>>>(h, wv, bv, nullptr, v, MROWS, DD, DD);
    flash_attn<<<dim3(SS / 64, HH, BB), 256>>>(q, k, v, amask, attn);
    sgemm128<true, true><<<gD, 256>>>(attn, wo, bo, x, x1, MROWS, DD, DD);

    // MLP sub-block
    rmsnorm_k<<<MROWS, 256>>>(x1, w_norm2, h2);
    sgemm128<false, false><<<gF, 256>>>(h2, w_gate, nullptr, nullptr, gate, MROWS, FF, DD);
    sgemm128<false, false><<<gF, 256>>>(h2, w_up,   nullptr, nullptr, up,   MROWS, FF, DD);
    silu_mul_k<<<(MROWS * (size_t)FF / 4) / 256, 256>>>(gate, up, gate);
    sgemm128<false, true><<<gD, 256>>>(gate, w_down, nullptr, x1, out, MROWS, DD, FF);
}

// round 3
// speedup vs baseline: 1.8790x; 1.8790x over previous
#include <cuda_runtime.h>
#include <cuda_bf16.h>
#include <cstdint>
#include <cstddef>

// ---------------------------------------------------------------------------
// Problem constants
// ---------------------------------------------------------------------------
#define BB 2
#define SS 2048
#define DD 1024
#define HH 16
#define HDIM 64
#define FF 4096
#define MROWS (BB * SS)          // 4096
#define EPS 1e-6f

// ---------------------------------------------------------------------------
// Device scratch
// ---------------------------------------------------------------------------
__device__ float g_h   [MROWS * DD];
__device__ float g_q   [MROWS * DD];
__device__ float g_k   [MROWS * DD];
__device__ float g_v   [MROWS * DD];
__device__ float g_attn[MROWS * DD];
__device__ float g_x1  [MROWS * DD];
__device__ float g_h2  [MROWS * DD];
__device__ float g_gate[MROWS * FF];
__device__ float g_up  [MROWS * FF];

// ---------------------------------------------------------------------------
// Warp-MMA helpers (sm_80+ ISA only -- no 'a'-suffix features)
// ---------------------------------------------------------------------------
__device__ __forceinline__ uint32_t smem_u32(const void* p) {
    uint32_t a;
    asm("{ .reg .u64 t; cvta.to.shared.u64 t, %1; cvt.u32.u64 %0, t; }"
        : "=r"(a) : "l"(p));
    return a;
}

__device__ __forceinline__ void ldsm4(uint32_t* r, uint32_t addr) {
    asm volatile("ldmatrix.sync.aligned.m8n8.x4.shared.b16 {%0,%1,%2,%3}, [%4];"
                 : "=r"(r[0]), "=r"(r[1]), "=r"(r[2]), "=r"(r[3]) : "r"(addr));
}

__device__ __forceinline__ void ldsm4t(uint32_t* r, uint32_t addr) {
    asm volatile("ldmatrix.sync.aligned.m8n8.x4.trans.shared.b16 {%0,%1,%2,%3}, [%4];"
                 : "=r"(r[0]), "=r"(r[1]), "=r"(r[2]), "=r"(r[3]) : "r"(addr));
}

__device__ __forceinline__ void mma_bf16(float* d, const uint32_t* a,
                                         const uint32_t* b) {
    asm volatile(
        "mma.sync.aligned.m16n8k16.row.col.f32.bf16.bf16.f32 "
        "{%0,%1,%2,%3}, {%4,%5,%6,%7}, {%8,%9}, {%0,%1,%2,%3};"
        : "+f"(d[0]), "+f"(d[1]), "+f"(d[2]), "+f"(d[3])
        : "r"(a[0]), "r"(a[1]), "r"(a[2]), "r"(a[3]), "r"(b[0]), "r"(b[1]));
}

// pack two floats as bf16x2 (x -> low half, y -> high half)
__device__ __forceinline__ uint32_t pk(float x, float y) {
    __nv_bfloat162 h = __floats2bfloat162_rn(x, y);
    return *(uint32_t*)&h;
}

__device__ __forceinline__ void split2(float x, float y, uint32_t& hi, uint32_t& lo) {
    float hx = __bfloat162float(__float2bfloat16_rn(x));
    float hy = __bfloat162float(__float2bfloat16_rn(y));
    hi = pk(x, y);                 // rn(x), rn(y) packed
    lo = pk(x - hx, y - hy);
}

// ---------------------------------------------------------------------------
// bf16x3 tensor-core GEMM: C[M,N] = A[M,K] @ B[K,N] (+bias) (+res)
// CTA 128x128, K-chunk 32, 256 threads (8 warps of 64x32), double-buffered.
// SMEM layout per buffer:
//   Ah[128][40]bf16 (stride 80B)  | Al  | Bh[32][136]bf16 (stride 272B) | Bl
// ---------------------------------------------------------------------------
#define BKC 32
#define ASTRIDE 80                 // bytes per A row (40 bf16)
#define BSTRIDE 272                // bytes per B row (136 bf16)
#define OFF_AH 0
#define OFF_AL 10240
#define OFF_BH 20480
#define OFF_BL 29184
#define BUFSZ  37888
#define GEMM_SMEM (2 * BUFSZ)

template <bool BIAS, bool RES>
__global__ __launch_bounds__(256, 1)
void mmgemm(const float* __restrict__ A, const float* __restrict__ B,
            const float* __restrict__ bias, const float* __restrict__ res,
            float* __restrict__ C, int M, int N, int K) {
    extern __shared__ char smem[];
    const uint32_t sb = smem_u32(smem);

    const int tid  = threadIdx.x;
    const int lane = tid & 31;
    const int wid  = tid >> 5;
    const int m0   = (wid >> 2) * 64;     // warp M offset in tile
    const int n0   = (wid & 3) * 32;      // warp N offset in tile
    const int mBase = blockIdx.y * 128;
    const int nBase = blockIdx.x * 128;

    // per-lane ldmatrix address components
    const uint32_t aoff = (uint32_t)((lane & 15) * ASTRIDE + (lane >> 4) * 16);
    const uint32_t boff = (uint32_t)((lane & 15) * BSTRIDE + (lane >> 4) * 16);

    float acc[4][4][4];
#pragma unroll
    for (int i = 0; i < 4; i++)
#pragma unroll
        for (int j = 0; j < 4; j++)
#pragma unroll
            for (int t = 0; t < 4; t++) acc[i][j][t] = 0.f;

    const int nch = K / BKC;

    // global prefetch registers
    float4 pa[4], pb[4];
    const int ar  = tid >> 3;            // 0..31 (+32*i later? no: idx-based)
    // A: idx = tid + i*256 -> r = idx>>3 (0..127), kc = (idx&7)*4
    // B: idx = tid + i*256 -> kk = idx>>5 (0..31), n4 = (idx&31)*4
    (void)ar;

#define GLOAD(c)                                                              \
    do {                                                                      \
        const int k0_ = (c) * BKC;                                            \
        _Pragma("unroll")                                                     \
        for (int i = 0; i < 4; i++) {                                         \
            const int idx = tid + i * 256;                                    \
            const int r = idx >> 3, kc = (idx & 7) * 4;                       \
            pa[i] = *(const float4*)(A + (size_t)(mBase + r) * K + k0_ + kc); \
        }                                                                     \
        _Pragma("unroll")                                                     \
        for (int i = 0; i < 4; i++) {                                         \
            const int idx = tid + i * 256;                                    \
            const int kk = idx >> 5, n4 = (idx & 31) * 4;                     \
            pb[i] = *(const float4*)(B + (size_t)(k0_ + kk) * N + nBase + n4);\
        }                                                                     \
    } while (0)

#define STS(buf)                                                              \
    do {                                                                      \
        char* bp = smem + (buf) * BUFSZ;                                      \
        _Pragma("unroll")                                                     \
        for (int i = 0; i < 4; i++) {                                         \
            const int idx = tid + i * 256;                                    \
            const int r = idx >> 3, kc = (idx & 7) * 4;                       \
            uint32_t h0, l0, h1, l1;                                          \
            split2(pa[i].x, pa[i].y, h0, l0);                                 \
            split2(pa[i].z, pa[i].w, h1, l1);                                 \
            const int off = r * ASTRIDE + kc * 2;                             \
            *(uint2*)(bp + OFF_AH + off) = make_uint2(h0, h1);                \
            *(uint2*)(bp + OFF_AL + off) = make_uint2(l0, l1);                \
        }                                                                     \
        _Pragma("unroll")                                                     \
        for (int i = 0; i < 4; i++) {                                         \
            const int idx = tid + i * 256;                                    \
            const int kk = idx >> 5, n4 = (idx & 31) * 4;                     \
            uint32_t h0, l0, h1, l1;                                          \
            split2(pb[i].x, pb[i].y, h0, l0);                                 \
            split2(pb[i].z, pb[i].w, h1, l1);                                 \
            const int off = kk * BSTRIDE + n4 * 2;                            \
            *(uint2*)(bp + OFF_BH + off) = make_uint2(h0, h1);                \
            *(uint2*)(bp + OFF_BL + off) = make_uint2(l0, l1);                \
        }                                                                     \
    } while (0)

    GLOAD(0);
    STS(0);
    __syncthreads();

    for (int c = 0; c < nch; c++) {
        if (c + 1 < nch) GLOAD(c + 1);

        const uint32_t bufb = sb + (uint32_t)((c & 1) * BUFSZ);
        const uint32_t ah = bufb + OFF_AH + (uint32_t)(m0 * ASTRIDE) + aoff;
        const uint32_t al = bufb + OFF_AL + (uint32_t)(m0 * ASTRIDE) + aoff;
        const uint32_t bh = bufb + OFF_BH + (uint32_t)(n0 * 2) + boff;
        const uint32_t bl = bufb + OFF_BL + (uint32_t)(n0 * 2) + boff;

#pragma unroll
        for (int ks = 0; ks < 2; ks++) {
            uint32_t fah[4][4], fal[4][4], fbh[2][4], fbl[2][4];
#pragma unroll
            for (int mi = 0; mi < 4; mi++) {
                ldsm4(fah[mi], ah + mi * (16 * ASTRIDE) + ks * 32);
                ldsm4(fal[mi], al + mi * (16 * ASTRIDE) + ks * 32);
            }
#pragma unroll
            for (int np = 0; np < 2; np++) {
                ldsm4t(fbh[np], bh + np * 32 + ks * (16 * BSTRIDE));
                ldsm4t(fbl[np], bl + np * 32 + ks * (16 * BSTRIDE));
            }
#pragma unroll
            for (int mi = 0; mi < 4; mi++)
#pragma unroll
                for (int nj = 0; nj < 4; nj++) {
                    uint32_t* bhp = &fbh[nj >> 1][(nj & 1) * 2];
                    uint32_t* blp = &fbl[nj >> 1][(nj & 1) * 2];
                    mma_bf16(acc[mi][nj], fah[mi], bhp);
                    mma_bf16(acc[mi][nj], fah[mi], blp);
                    mma_bf16(acc[mi][nj], fal[mi], bhp);
                }
        }

        if (c + 1 < nch) STS((c + 1) & 1);
        __syncthreads();
    }

    // epilogue
    const int g  = lane >> 2;
    const int tc = (lane & 3) * 2;
#pragma unroll
    for (int mi = 0; mi < 4; mi++) {
        const int row = mBase + m0 + mi * 16 + g;
#pragma unroll
        for (int nj = 0; nj < 4; nj++) {
            const int col = nBase + n0 + nj * 8 + tc;
            float2 bv = make_float2(0.f, 0.f);
            if (BIAS) bv = *(const float2*)(bias + col);
            float2 r0, r1;
            r0.x = acc[mi][nj][0] + bv.x;
            r0.y = acc[mi][nj][1] + bv.y;
            r1.x = acc[mi][nj][2] + bv.x;
            r1.y = acc[mi][nj][3] + bv.y;
            if (RES) {
                float2 e0 = *(const float2*)(res + (size_t)row * N + col);
                float2 e1 = *(const float2*)(res + (size_t)(row + 8) * N + col);
                r0.x += e0.x; r0.y += e0.y;
                r1.x += e1.x; r1.y += e1.y;
            }
            *(float2*)(C + (size_t)row * N + col)       = r0;
            *(float2*)(C + (size_t)(row + 8) * N + col) = r1;
        }
    }
#undef GLOAD
#undef STS
}

// ---------------------------------------------------------------------------
// RMSNorm
// ---------------------------------------------------------------------------
__global__ __launch_bounds__(256) void rmsnorm_k(const float* __restrict__ x,
                                                 const float* __restrict__ w,
                                                 float* __restrict__ o) {
    __shared__ float red[8];
    const int row = blockIdx.x;
    const int tid = threadIdx.x;
    const float4* xr = (const float4*)(x + (size_t)row * DD);
    float4 v = xr[tid];
    float ss = v.x * v.x + v.y * v.y + v.z * v.z + v.w * v.w;
#pragma unroll
    for (int off = 16; off > 0; off >>= 1)
        ss += __shfl_xor_sync(0xffffffffu, ss, off);
    if ((tid & 31) == 0) red[tid >> 5] = ss;
    __syncthreads();
    float tot = 0.f;
#pragma unroll
    for (int i = 0; i < 8; i++) tot += red[i];
    const float inv = rsqrtf(tot * (1.0f / DD) + EPS);
    const float4 wv = ((const float4*)w)[tid];
    float4 ov;
    ov.x = wv.x * (v.x * inv);
    ov.y = wv.y * (v.y * inv);
    ov.z = wv.z * (v.z * inv);
    ov.w = wv.w * (v.w * inv);
    ((float4*)(o + (size_t)row * DD))[tid] = ov;
}

// ---------------------------------------------------------------------------
// Flash attention (fp32): 64x64 tiles, HD=64 (unchanged from R1)
// ---------------------------------------------------------------------------
__global__ __launch_bounds__(256) void flash_attn(const float* __restrict__ Q,
                                                  const float* __restrict__ Kg,
                                                  const float* __restrict__ Vg,
                                                  const int* __restrict__ amask,
                                                  float* __restrict__ O) {
    constexpr int BT = 64;
    __shared__ float Qs [BT * HDIM];
    __shared__ float KPs[BT * HDIM];
    __shared__ float Vs [BT * HDIM];

    const int qb = blockIdx.x * BT;
    const int h  = blockIdx.y;
    const int b  = blockIdx.z;
    const int tid = threadIdx.x;
    const int tx = tid % 16, ty = tid / 16;

    const size_t base = ((size_t)b * SS) * DD + (size_t)h * HDIM;

#pragma unroll
    for (int it = 0; it < 4; it++) {
        const int idx = tid + it * 256;
        const int r = idx / 16, c4 = (idx % 16) * 4;
        float4 t = *(const float4*)(Q + base + (size_t)(qb + r) * DD + c4);
        *(float4*)(&Qs[r * HDIM + c4]) = t;
    }

    float m[4], l[4], o[4][4];
#pragma unroll
    for (int i = 0; i < 4; i++) {
        m[i] = -1e30f;
        l[i] = 0.f;
#pragma unroll
        for (int j = 0; j < 4; j++) o[i][j] = 0.f;
    }

    for (int kb = 0; kb <= qb; kb += BT) {
#pragma unroll
        for (int it = 0; it < 4; it++) {
            const int idx = tid + it * 256;
            const int c = idx / 16, d4 = (idx % 16) * 4;
            float4 kv = *(const float4*)(Kg + base + (size_t)(kb + c) * DD + d4);
            KPs[(d4 + 0) * BT + c] = kv.x;
            KPs[(d4 + 1) * BT + c] = kv.y;
            KPs[(d4 + 2) * BT + c] = kv.z;
            KPs[(d4 + 3) * BT + c] = kv.w;
            float4 vv = *(const float4*)(Vg + base + (size_t)(kb + c) * DD + d4);
            *(float4*)(&Vs[c * HDIM + d4]) = vv;
        }
        __syncthreads();

        float s[4][4];
#pragma unroll
        for (int i = 0; i < 4; i++)
#pragma unroll
            for (int j = 0; j < 4; j++) s[i][j] = 0.f;

        for (int d = 0; d < HDIM; d++) {
            float ra[4], rc[4];
#pragma unroll
            for (int i = 0; i < 4; i++) ra[i] = Qs[(ty * 4 + i) * HDIM + d];
#pragma unroll
            for (int j = 0; j < 4; j++) rc[j] = KPs[d * BT + tx * 4 + j];
#pragma unroll
            for (int i = 0; i < 4; i++)
#pragma unroll
                for (int j = 0; j < 4; j++) s[i][j] += ra[i] * rc[j];
        }

        int mv[4];
#pragma unroll
        for (int j = 0; j < 4; j++) mv[j] = amask[(size_t)b * SS + kb + tx * 4 + j];

#pragma unroll
        for (int i = 0; i < 4; i++) {
            const int qi = qb + ty * 4 + i;
#pragma unroll
            for (int j = 0; j < 4; j++) {
                const int kj = kb + tx * 4 + j;
                float vv = s[i][j] * 0.125f;
                if ((kb == qb && kj > qi) || (mv[j] == 0)) vv = -1e30f;
                s[i][j] = vv;
            }
        }

#pragma unroll
        for (int i = 0; i < 4; i++) {
            float rm = s[i][0];
#pragma unroll
            for (int j = 1; j < 4; j++) rm = fmaxf(rm, s[i][j]);
#pragma unroll
            for (int off = 8; off > 0; off >>= 1)
                rm = fmaxf(rm, __shfl_xor_sync(0xffffffffu, rm, off));
            const float mn = fmaxf(m[i], rm);
            const float corr = __expf(m[i] - mn);
            float rs = 0.f;
#pragma unroll
            for (int j = 0; j < 4; j++) {
                s[i][j] = __expf(s[i][j] - mn);
                rs += s[i][j];
            }
#pragma unroll
            for (int off = 8; off > 0; off >>= 1)
                rs += __shfl_xor_sync(0xffffffffu, rs, off);
            l[i] = l[i] * corr + rs;
            m[i] = mn;
#pragma unroll
            for (int j = 0; j < 4; j++) o[i][j] *= corr;
        }

        __syncthreads();
#pragma unroll
        for (int i = 0; i < 4; i++) {
            float4 pv = make_float4(s[i][0], s[i][1], s[i][2], s[i][3]);
            *(float4*)(&KPs[(ty * 4 + i) * BT + tx * 4]) = pv;
        }
        __syncthreads();

        for (int kk = 0; kk < BT; kk++) {
            float rp[4], rv[4];
#pragma unroll
            for (int i = 0; i < 4; i++) rp[i] = KPs[(ty * 4 + i) * BT + kk];
#pragma unroll
            for (int j = 0; j < 4; j++) rv[j] = Vs[kk * HDIM + tx * 4 + j];
#pragma unroll
            for (int i = 0; i < 4; i++)
#pragma unroll
                for (int j = 0; j < 4; j++) o[i][j] += rp[i] * rv[j];
        }
        __syncthreads();
    }

#pragma unroll
    for (int i = 0; i < 4; i++) {
        const float inv = 1.0f / l[i];
        float4 ov = make_float4(o[i][0] * inv, o[i][1] * inv,
                                o[i][2] * inv, o[i][3] * inv);
        *(float4*)(O + base + (size_t)(qb + ty * 4 + i) * DD + tx * 4) = ov;
    }
}

// ---------------------------------------------------------------------------
// silu(gate) * up
// ---------------------------------------------------------------------------
__global__ __launch_bounds__(256) void silu_mul_k(const float* __restrict__ g,
                                                  const float* __restrict__ u,
                                                  float* __restrict__ o) {
    const size_t i = (size_t)blockIdx.x * blockDim.x + threadIdx.x;
    float4 gv = ((const float4*)g)[i];
    float4 uv = ((const float4*)u)[i];
    float4 ov;
    ov.x = gv.x / (1.f + __expf(-gv.x)) * uv.x;
    ov.y = gv.y / (1.f + __expf(-gv.y)) * uv.y;
    ov.z = gv.z / (1.f + __expf(-gv.z)) * uv.z;
    ov.w = gv.w / (1.f + __expf(-gv.w)) * uv.w;
    ((float4*)o)[i] = ov;
}

// ---------------------------------------------------------------------------
// Launch
// ---------------------------------------------------------------------------
extern "C" void kernel_launch(void* const* d_in, const int* in_sizes, int n_in,
                              void* d_out, int out_size) {
    const float* x       = (const float*)d_in[0];
    const int*   amask   = (const int*)  d_in[1];
    const float* w_norm1 = (const float*)d_in[2];
    const float* wq      = (const float*)d_in[3];
    const float* bq      = (const float*)d_in[4];
    const float* wk      = (const float*)d_in[5];
    const float* bk      = (const float*)d_in[6];
    const float* wv      = (const float*)d_in[7];
    const float* bv      = (const float*)d_in[8];
    const float* wo      = (const float*)d_in[9];
    const float* bo      = (const float*)d_in[10];
    const float* w_norm2 = (const float*)d_in[11];
    const float* w_gate  = (const float*)d_in[12];
    const float* w_up    = (const float*)d_in[13];
    const float* w_down  = (const float*)d_in[14];
    float* out = (float*)d_out;

    float *h, *q, *k, *v, *attn, *x1, *h2, *gate, *up;
    cudaGetSymbolAddress((void**)&h,    g_h);
    cudaGetSymbolAddress((void**)&q,    g_q);
    cudaGetSymbolAddress((void**)&k,    g_k);
    cudaGetSymbolAddress((void**)&v,    g_v);
    cudaGetSymbolAddress((void**)&attn, g_attn);
    cudaGetSymbolAddress((void**)&x1,   g_x1);
    cudaGetSymbolAddress((void**)&h2,   g_h2);
    cudaGetSymbolAddress((void**)&gate, g_gate);
    cudaGetSymbolAddress((void**)&up,   g_up);

    cudaFuncSetAttribute(mmgemm<true,  false>, cudaFuncAttributeMaxDynamicSharedMemorySize, GEMM_SMEM);
    cudaFuncSetAttribute(mmgemm<true,  true >, cudaFuncAttributeMaxDynamicSharedMemorySize, GEMM_SMEM);
    cudaFuncSetAttribute(mmgemm<false, false>, cudaFuncAttributeMaxDynamicSharedMemorySize, GEMM_SMEM);
    cudaFuncSetAttribute(mmgemm<false, true >, cudaFuncAttributeMaxDynamicSharedMemorySize, GEMM_SMEM);

    const dim3 gD(DD / 128, MROWS / 128);   // (8, 32)
    const dim3 gF(FF / 128, MROWS / 128);   // (32, 32)

    // attention sub-block
    rmsnorm_k<<<MROWS, 256>>>(x, w_norm1, h);
    mmgemm<true, false><<<gD, 256, GEMM_SMEM>>>(h, wq, bq, nullptr, q, MROWS, DD, DD);
    mmgemm<true, false><<<gD, 256, GEMM_SMEM>>>(h, wk, bk, nullptr, k, MROWS, DD, DD);
    mmgemm<true, false><<<gD, 256, GEMM_SMEM>>>(h, wv, bv, nullptr, v, MROWS, DD, DD);
    flash_attn<<<dim3(SS / 64, HH, BB), 256>>>(q, k, v, amask, attn);
    mmgemm<true, true><<<gD, 256, GEMM_SMEM>>>(attn, wo, bo, x, x1, MROWS, DD, DD);

    // MLP sub-block
    rmsnorm_k<<<MROWS, 256>>>(x1, w_norm2, h2);
    mmgemm<false, false><<<gF, 256, GEMM_SMEM>>>(h2, w_gate, nullptr, nullptr, gate, MROWS, FF, DD);
    mmgemm<false, false><<<gF, 256, GEMM_SMEM>>>(h2, w_up,   nullptr, nullptr, up,   MROWS, FF, DD);
    silu_mul_k<<<(MROWS * (size_t)FF / 4) / 256, 256>>>(gate, up, gate);
    mmgemm<false, true><<<gD, 256, GEMM_SMEM>>>(gate, w_down, nullptr, x1, out, MROWS, DD, FF);
}

// round 4
// speedup vs baseline: 2.8148x; 1.4980x over previous
#include <cuda_runtime.h>
#include <cuda_bf16.h>
#include <cstdint>
#include <cstddef>

// ---------------------------------------------------------------------------
// Problem constants
// ---------------------------------------------------------------------------
#define BB 2
#define SS 2048
#define DD 1024
#define HH 16
#define HDIM 64
#define FF 4096
#define MROWS (BB * SS)          // 4096
#define EPS 1e-6f

// ---------------------------------------------------------------------------
// Device scratch
// ---------------------------------------------------------------------------
__device__ float g_gate[MROWS * FF];
__device__ float g_up  [MROWS * FF];
__device__ float g_x1  [MROWS * DD];

__device__ __nv_bfloat16 g_hbh[MROWS * DD],  g_hbl[MROWS * DD];
__device__ __nv_bfloat16 g_qh [MROWS * DD],  g_ql [MROWS * DD];
__device__ __nv_bfloat16 g_kh [MROWS * DD],  g_kl [MROWS * DD];
__device__ __nv_bfloat16 g_vh [MROWS * DD],  g_vl [MROWS * DD];
__device__ __nv_bfloat16 g_ah [MROWS * DD],  g_al [MROWS * DD];
__device__ __nv_bfloat16 g_h2h[MROWS * DD],  g_h2l[MROWS * DD];
__device__ __nv_bfloat16 g_gah[MROWS * FF],  g_gal[MROWS * FF];

__device__ __nv_bfloat16 g_wqh[DD * DD], g_wql[DD * DD];
__device__ __nv_bfloat16 g_wkh[DD * DD], g_wkl[DD * DD];
__device__ __nv_bfloat16 g_wvh[DD * DD], g_wvl[DD * DD];
__device__ __nv_bfloat16 g_woh[DD * DD], g_wol[DD * DD];
__device__ __nv_bfloat16 g_wgh[DD * FF], g_wgl[DD * FF];
__device__ __nv_bfloat16 g_wuh[DD * FF], g_wul[DD * FF];
__device__ __nv_bfloat16 g_wdh[FF * DD], g_wdl[FF * DD];

// ---------------------------------------------------------------------------
// Helpers (sm_80+ ISA only)
// ---------------------------------------------------------------------------
__device__ __forceinline__ uint32_t smem_u32(const void* p) {
    uint32_t a;
    asm("{ .reg .u64 t; cvta.to.shared.u64 t, %1; cvt.u32.u64 %0, t; }"
        : "=r"(a) : "l"(p));
    return a;
}

__device__ __forceinline__ void ldsm4(uint32_t* r, uint32_t addr) {
    asm volatile("ldmatrix.sync.aligned.m8n8.x4.shared.b16 {%0,%1,%2,%3}, [%4];"
                 : "=r"(r[0]), "=r"(r[1]), "=r"(r[2]), "=r"(r[3]) : "r"(addr));
}

__device__ __forceinline__ void ldsm4t(uint32_t* r, uint32_t addr) {
    asm volatile("ldmatrix.sync.aligned.m8n8.x4.trans.shared.b16 {%0,%1,%2,%3}, [%4];"
                 : "=r"(r[0]), "=r"(r[1]), "=r"(r[2]), "=r"(r[3]) : "r"(addr));
}

__device__ __forceinline__ void mma_bf16(float* d, const uint32_t* a,
                                         const uint32_t* b) {
    asm volatile(
        "mma.sync.aligned.m16n8k16.row.col.f32.bf16.bf16.f32 "
        "{%0,%1,%2,%3}, {%4,%5,%6,%7}, {%8,%9}, {%0,%1,%2,%3};"
        : "+f"(d[0]), "+f"(d[1]), "+f"(d[2]), "+f"(d[3])
        : "r"(a[0]), "r"(a[1]), "r"(a[2]), "r"(a[3]), "r"(b[0]), "r"(b[1]));
}

__device__ __forceinline__ uint32_t pk(float x, float y) {
    __nv_bfloat162 h = __floats2bfloat162_rn(x, y);
    return *(uint32_t*)&h;
}

__device__ __forceinline__ float bfv(float x) {
    return __bfloat162float(__float2bfloat16_rn(x));
}

#define CP16(dst, src) \
    asm volatile("cp.async.cg.shared.global [%0], [%1], 16;" \
                 :: "r"(dst), "l"(src) : "memory")
#define CPCOMMIT() asm volatile("cp.async.commit_group;" ::: "memory")

__device__ __forceinline__ void cpwait(int keep) {
    if (keep) asm volatile("cp.async.wait_group 1;" ::: "memory");
    else      asm volatile("cp.async.wait_group 0;" ::: "memory");
}

// ---------------------------------------------------------------------------
// bf16x3 tensor GEMM, cp.async double-buffered, pre-split inputs.
// C[M,N] = A[M,K] @ B[K,N] (+bias) (+res); out fp32 or split bf16 hi/lo.
// CTA 128x128, K-chunk 32, 256 threads (8 warps of 64x32).
// ---------------------------------------------------------------------------
#define BKC 32
#define ASTRIDE 80                 // bytes per A row (data 64B + pad)
#define BSTRIDE 272                // bytes per B row (data 256B + pad)
#define OFF_AH 0
#define OFF_AL 10240
#define OFF_BH 20480
#define OFF_BL 29184
#define BUFSZ  37888
#define GEMM_SMEM (2 * BUFSZ)

template <bool BIAS, bool RES, bool SPLIT>
__global__ __launch_bounds__(256, 2)
void mmgemm(const __nv_bfloat16* __restrict__ Ah, const __nv_bfloat16* __restrict__ Al,
            const __nv_bfloat16* __restrict__ Bh, const __nv_bfloat16* __restrict__ Bl,
            const float* __restrict__ bias, const float* __restrict__ res,
            float* __restrict__ C,
            __nv_bfloat16* __restrict__ Chi, __nv_bfloat16* __restrict__ Clo,
            int M, int N, int K) {
    extern __shared__ char smem[];
    const uint32_t sb = smem_u32(smem);

    const int tid  = threadIdx.x;
    const int lane = tid & 31;
    const int wid  = tid >> 5;
    const int m0   = (wid >> 2) * 64;
    const int n0   = (wid & 3) * 32;
    const int mBase = blockIdx.y * 128;
    const int nBase = blockIdx.x * 128;

    const uint32_t aoff = (uint32_t)((lane & 15) * ASTRIDE + (lane >> 4) * 16);
    const uint32_t boff = (uint32_t)((lane & 15) * BSTRIDE + (lane >> 4) * 16);

    float acc[4][4][4];
#pragma unroll
    for (int i = 0; i < 4; i++)
#pragma unroll
        for (int j = 0; j < 4; j++)
#pragma unroll
            for (int t = 0; t < 4; t++) acc[i][j][t] = 0.f;

    const int nch = K / BKC;

#define ISSUE(c, buf)                                                         \
    do {                                                                      \
        const int k0_ = (c) * BKC;                                            \
        const uint32_t bp = sb + (uint32_t)((buf) * BUFSZ);                   \
        _Pragma("unroll")                                                     \
        for (int i = 0; i < 2; i++) {                                         \
            const int idx = tid + i * 256;                                    \
            const int r = idx >> 2, c16 = idx & 3;                            \
            const size_t so = (size_t)(mBase + r) * K + k0_ + c16 * 8;        \
            const uint32_t d = bp + (uint32_t)(r * ASTRIDE + c16 * 16);       \
            CP16(d + OFF_AH, Ah + so);                                        \
            CP16(d + OFF_AL, Al + so);                                        \
        }                                                                     \
        _Pragma("unroll")                                                     \
        for (int i = 0; i < 2; i++) {                                         \
            const int idx = tid + i * 256;                                    \
            const int kk = idx >> 4, c16 = idx & 15;                          \
            const size_t so = (size_t)(k0_ + kk) * N + nBase + c16 * 8;       \
            const uint32_t d = bp + (uint32_t)(kk * BSTRIDE + c16 * 16);      \
            CP16(d + OFF_BH, Bh + so);                                        \
            CP16(d + OFF_BL, Bl + so);                                        \
        }                                                                     \
        CPCOMMIT();                                                           \
    } while (0)

    ISSUE(0, 0);
    if (nch > 1) ISSUE(1, 1);

    for (int c = 0; c < nch; c++) {
        cpwait(c + 1 < nch);
        __syncthreads();

        const uint32_t bufb = sb + (uint32_t)((c & 1) * BUFSZ);
        const uint32_t ah = bufb + OFF_AH + (uint32_t)(m0 * ASTRIDE) + aoff;
        const uint32_t al = bufb + OFF_AL + (uint32_t)(m0 * ASTRIDE) + aoff;
        const uint32_t bh = bufb + OFF_BH + (uint32_t)(n0 * 2) + boff;
        const uint32_t bl = bufb + OFF_BL + (uint32_t)(n0 * 2) + boff;

#pragma unroll
        for (int ks = 0; ks < 2; ks++) {
            uint32_t fah[4][4], fbh[2][4];
#pragma unroll
            for (int mi = 0; mi < 4; mi++)
                ldsm4(fah[mi], ah + mi * (16 * ASTRIDE) + ks * 32);
#pragma unroll
            for (int np = 0; np < 2; np++)
                ldsm4t(fbh[np], bh + np * 32 + ks * (16 * BSTRIDE));
#pragma unroll
            for (int mi = 0; mi < 4; mi++)
#pragma unroll
                for (int nj = 0; nj < 4; nj++)
                    mma_bf16(acc[mi][nj], fah[mi], &fbh[nj >> 1][(nj & 1) * 2]);

            uint32_t fbl[2][4];
#pragma unroll
            for (int np = 0; np < 2; np++)
                ldsm4t(fbl[np], bl + np * 32 + ks * (16 * BSTRIDE));
#pragma unroll
            for (int mi = 0; mi < 4; mi++)
#pragma unroll
                for (int nj = 0; nj < 4; nj++)
                    mma_bf16(acc[mi][nj], fah[mi], &fbl[nj >> 1][(nj & 1) * 2]);

            uint32_t fal[4][4];
#pragma unroll
            for (int mi = 0; mi < 4; mi++)
                ldsm4(fal[mi], al + mi * (16 * ASTRIDE) + ks * 32);
#pragma unroll
            for (int mi = 0; mi < 4; mi++)
#pragma unroll
                for (int nj = 0; nj < 4; nj++)
                    mma_bf16(acc[mi][nj], fal[mi], &fbh[nj >> 1][(nj & 1) * 2]);
        }

        __syncthreads();
        if (c + 2 < nch) ISSUE(c + 2, c & 1);
    }
#undef ISSUE

    // epilogue
    const int g  = lane >> 2;
    const int tc = (lane & 3) * 2;
#pragma unroll
    for (int mi = 0; mi < 4; mi++) {
        const int row = mBase + m0 + mi * 16 + g;
#pragma unroll
        for (int nj = 0; nj < 4; nj++) {
            const int col = nBase + n0 + nj * 8 + tc;
            float2 bv = make_float2(0.f, 0.f);
            if (BIAS) bv = *(const float2*)(bias + col);
            float v0 = acc[mi][nj][0] + bv.x;
            float v1 = acc[mi][nj][1] + bv.y;
            float v2 = acc[mi][nj][2] + bv.x;
            float v3 = acc[mi][nj][3] + bv.y;
            if (RES) {
                float2 e0 = *(const float2*)(res + (size_t)row * N + col);
                float2 e1 = *(const float2*)(res + (size_t)(row + 8) * N + col);
                v0 += e0.x; v1 += e0.y; v2 += e1.x; v3 += e1.y;
            }
            if (SPLIT) {
                *(uint32_t*)(Chi + (size_t)row * N + col)       = pk(v0, v1);
                *(uint32_t*)(Clo + (size_t)row * N + col)       = pk(v0 - bfv(v0), v1 - bfv(v1));
                *(uint32_t*)(Chi + (size_t)(row + 8) * N + col) = pk(v2, v3);
                *(uint32_t*)(Clo + (size_t)(row + 8) * N + col) = pk(v2 - bfv(v2), v3 - bfv(v3));
            } else {
                *(float2*)(C + (size_t)row * N + col)       = make_float2(v0, v1);
                *(float2*)(C + (size_t)(row + 8) * N + col) = make_float2(v2, v3);
            }
        }
    }
}

// ---------------------------------------------------------------------------
// Tensor-core flash attention: 64q x 64k tiles, HD=64, 128 threads (4 warps).
// Inputs pre-split bf16 hi/lo; QK^T and P@V via bf16x3 mma. Output split bf16.
// ---------------------------------------------------------------------------
#define FQ_STRIDE 144                    // 64 bf16 data (128B) + 16B pad
#define F_OFF_QH 0
#define F_OFF_QL 9216
#define F_OFF_ST 18432                   // stage base
#define F_STAGE  36864                   // Kh,Kl,Vh,Vl (9216 each)
#define F_OFF_MK 92160                   // 2 x 256B mask
#define FLASH_SMEM 92672

__global__ __launch_bounds__(128)
void flash_mma(const __nv_bfloat16* __restrict__ Qh, const __nv_bfloat16* __restrict__ Ql,
               const __nv_bfloat16* __restrict__ Kh, const __nv_bfloat16* __restrict__ Kl,
               const __nv_bfloat16* __restrict__ Vh, const __nv_bfloat16* __restrict__ Vl,
               const int* __restrict__ amask,
               __nv_bfloat16* __restrict__ Oh, __nv_bfloat16* __restrict__ Ol) {
    extern __shared__ char smem[];
    const uint32_t sb = smem_u32(smem);

    const int tid  = threadIdx.x;
    const int lane = tid & 31;
    const int wid  = tid >> 5;
    const int qb   = blockIdx.x * 64;
    const int h    = blockIdx.y;
    const int b    = blockIdx.z;
    const int bS   = b * SS;
    const int hcol = h * HDIM;
    const int nt   = qb / 64 + 1;

    // ---- issue Q loads (part of group 0) ----
#pragma unroll
    for (int i = 0; i < 4; i++) {
        const int idx = tid + i * 128;
        const int r = idx >> 3, c16 = idx & 7;
        const size_t so = (size_t)(bS + qb + r) * DD + hcol + c16 * 8;
        const uint32_t d = sb + (uint32_t)(r * FQ_STRIDE + c16 * 16);
        CP16(d + F_OFF_QH, Qh + so);
        CP16(d + F_OFF_QL, Ql + so);
    }

#define KVISSUE(kt, st)                                                       \
    do {                                                                      \
        const int kb_ = (kt) * 64;                                            \
        const uint32_t stb = sb + F_OFF_ST + (uint32_t)((st) * F_STAGE);      \
        _Pragma("unroll")                                                     \
        for (int i = 0; i < 4; i++) {                                         \
            const int idx = tid + i * 128;                                    \
            const int r = idx >> 3, c16 = idx & 7;                            \
            const size_t so = (size_t)(bS + kb_ + r) * DD + hcol + c16 * 8;   \
            const uint32_t d = stb + (uint32_t)(r * FQ_STRIDE + c16 * 16);    \
            CP16(d + 0,     Kh + so);                                         \
            CP16(d + 9216,  Kl + so);                                         \
            CP16(d + 18432, Vh + so);                                         \
            CP16(d + 27648, Vl + so);                                         \
        }                                                                     \
        if (tid < 16)                                                         \
            CP16(sb + F_OFF_MK + (uint32_t)((st) * 256 + tid * 16),           \
                 amask + bS + kb_ + tid * 4);                                 \
        CPCOMMIT();                                                           \
    } while (0)

    KVISSUE(0, 0);
    if (nt > 1) KVISSUE(1, 1);
    cpwait(nt > 1);
    __syncthreads();

    // ---- load Q fragments (persistent) ----
    const int qr0 = wid * 16;
    const uint32_t qaddr = sb + (uint32_t)((qr0 + (lane & 15)) * FQ_STRIDE + (lane >> 4) * 16);
    uint32_t qfh[4][4], qfl[4][4];
#pragma unroll
    for (int kc = 0; kc < 4; kc++) {
        ldsm4(qfh[kc], qaddr + F_OFF_QH + kc * 32);
        ldsm4(qfl[kc], qaddr + F_OFF_QL + kc * 32);
    }

    const int rloc0 = qr0 + (lane >> 2);          // local q row (0..63)
    const int tc2   = (lane & 3) * 2;
    const int r0g   = qb + rloc0;
    const int r1g   = r0g + 8;

    float o[8][4];
#pragma unroll
    for (int dt = 0; dt < 8; dt++)
#pragma unroll
        for (int e = 0; e < 4; e++) o[dt][e] = 0.f;
    float m0 = -1e30f, m1 = -1e30f, l0 = 0.f, l1 = 0.f;

    for (int kt = 0; kt < nt; kt++) {
        if (kt > 0) { cpwait(kt + 1 < nt); __syncthreads(); }
        const int kb = kt * 64;
        const uint32_t stb = sb + F_OFF_ST + (uint32_t)((kt & 1) * F_STAGE);
        const uint32_t kaddr = stb + (uint32_t)(((lane & 7) + ((lane >> 4) << 3)) * FQ_STRIDE
                                                + ((lane >> 3) & 1) * 16);
        const uint32_t vaddr = stb + 18432u + (uint32_t)((lane & 15) * FQ_STRIDE + (lane >> 4) * 16);
        const int* smk = (const int*)(smem + F_OFF_MK + (kt & 1) * 256);

        // ---- scores = Q @ K^T (bf16x3) ----
        float s[8][4];
#pragma unroll
        for (int jt = 0; jt < 8; jt++)
#pragma unroll
            for (int e = 0; e < 4; e++) s[jt][e] = 0.f;

#pragma unroll
        for (int kc = 0; kc < 4; kc++)
#pragma unroll
            for (int g2 = 0; g2 < 4; g2++) {
                uint32_t kf[4], kfl[4];
                ldsm4(kf,  kaddr + g2 * (16 * FQ_STRIDE) + kc * 32);
                mma_bf16(s[2 * g2],     qfh[kc], kf + 0);
                mma_bf16(s[2 * g2 + 1], qfh[kc], kf + 2);
                ldsm4(kfl, kaddr + 9216 + g2 * (16 * FQ_STRIDE) + kc * 32);
                mma_bf16(s[2 * g2],     qfh[kc], kfl + 0);
                mma_bf16(s[2 * g2 + 1], qfh[kc], kfl + 2);
                mma_bf16(s[2 * g2],     qfl[kc], kf + 0);
                mma_bf16(s[2 * g2 + 1], qfl[kc], kf + 2);
            }

        // ---- scale + causal + key mask ----
#pragma unroll
        for (int jt = 0; jt < 8; jt++) {
            const int c0 = kb + jt * 8 + tc2;
            const int c1 = c0 + 1;
            const bool k0 = smk[jt * 8 + tc2] != 0;
            const bool k1 = smk[jt * 8 + tc2 + 1] != 0;
            s[jt][0] = (c0 <= r0g && k0) ? s[jt][0] * 0.125f : -1e30f;
            s[jt][1] = (c1 <= r0g && k1) ? s[jt][1] * 0.125f : -1e30f;
            s[jt][2] = (c0 <= r1g && k0) ? s[jt][2] * 0.125f : -1e30f;
            s[jt][3] = (c1 <= r1g && k1) ? s[jt][3] * 0.125f : -1e30f;
        }

        // ---- online softmax ----
        float mx0 = -1e30f, mx1 = -1e30f;
#pragma unroll
        for (int jt = 0; jt < 8; jt++) {
            mx0 = fmaxf(mx0, fmaxf(s[jt][0], s[jt][1]));
            mx1 = fmaxf(mx1, fmaxf(s[jt][2], s[jt][3]));
        }
        mx0 = fmaxf(mx0, __shfl_xor_sync(0xffffffffu, mx0, 1));
        mx0 = fmaxf(mx0, __shfl_xor_sync(0xffffffffu, mx0, 2));
        mx1 = fmaxf(mx1, __shfl_xor_sync(0xffffffffu, mx1, 1));
        mx1 = fmaxf(mx1, __shfl_xor_sync(0xffffffffu, mx1, 2));
        const float mn0 = fmaxf(m0, mx0), mn1 = fmaxf(m1, mx1);
        const float cr0 = __expf(m0 - mn0), cr1 = __expf(m1 - mn1);
        float sum0 = 0.f, sum1 = 0.f;
#pragma unroll
        for (int jt = 0; jt < 8; jt++) {
            s[jt][0] = __expf(s[jt][0] - mn0);
            s[jt][1] = __expf(s[jt][1] - mn0);
            s[jt][2] = __expf(s[jt][2] - mn1);
            s[jt][3] = __expf(s[jt][3] - mn1);
            sum0 += s[jt][0] + s[jt][1];
            sum1 += s[jt][2] + s[jt][3];
        }
        sum0 += __shfl_xor_sync(0xffffffffu, sum0, 1);
        sum0 += __shfl_xor_sync(0xffffffffu, sum0, 2);
        sum1 += __shfl_xor_sync(0xffffffffu, sum1, 1);
        sum1 += __shfl_xor_sync(0xffffffffu, sum1, 2);
        l0 = l0 * cr0 + sum0;
        l1 = l1 * cr1 + sum1;
        m0 = mn0; m1 = mn1;
#pragma unroll
        for (int dt = 0; dt < 8; dt++) {
            o[dt][0] *= cr0; o[dt][1] *= cr0;
            o[dt][2] *= cr1; o[dt][3] *= cr1;
        }

        // ---- O += P @ V (bf16x3), P from registers ----
#pragma unroll
        for (int kc2 = 0; kc2 < 4; kc2++) {
            uint32_t ph[4], pl[4];
            {
                const float a0 = s[2 * kc2][0],     a1 = s[2 * kc2][1];
                const float a2 = s[2 * kc2][2],     a3 = s[2 * kc2][3];
                const float a4 = s[2 * kc2 + 1][0], a5 = s[2 * kc2 + 1][1];
                const float a6 = s[2 * kc2 + 1][2], a7 = s[2 * kc2 + 1][3];
                ph[0] = pk(a0, a1); pl[0] = pk(a0 - bfv(a0), a1 - bfv(a1));
                ph[1] = pk(a2, a3); pl[1] = pk(a2 - bfv(a2), a3 - bfv(a3));
                ph[2] = pk(a4, a5); pl[2] = pk(a4 - bfv(a4), a5 - bfv(a5));
                ph[3] = pk(a6, a7); pl[3] = pk(a6 - bfv(a6), a7 - bfv(a7));
            }
#pragma unroll
            for (int g2 = 0; g2 < 4; g2++) {
                uint32_t vf[4], vfl[4];
                ldsm4t(vf,  vaddr + kc2 * (16 * FQ_STRIDE) + g2 * 32);
                mma_bf16(o[2 * g2],     ph, vf + 0);
                mma_bf16(o[2 * g2 + 1], ph, vf + 2);
                ldsm4t(vfl, vaddr + 9216 + kc2 * (16 * FQ_STRIDE) + g2 * 32);
                mma_bf16(o[2 * g2],     ph, vfl + 0);
                mma_bf16(o[2 * g2 + 1], ph, vfl + 2);
                mma_bf16(o[2 * g2],     pl, vf + 0);
                mma_bf16(o[2 * g2 + 1], pl, vf + 2);
            }
        }

        __syncthreads();
        if (kt + 2 < nt) KVISSUE(kt + 2, kt & 1);
    }
#undef KVISSUE

    // ---- finalize + split-store ----
    const float inv0 = 1.f / l0, inv1 = 1.f / l1;
    const size_t e0 = (size_t)(bS + r0g) * DD + hcol;
    const size_t e1 = (size_t)(bS + r1g) * DD + hcol;
#pragma unroll
    for (int dt = 0; dt < 8; dt++) {
        const int col = dt * 8 + tc2;
        float v0 = o[dt][0] * inv0, v1 = o[dt][1] * inv0;
        float v2 = o[dt][2] * inv1, v3 = o[dt][3] * inv1;
        *(uint32_t*)(Oh + e0 + col) = pk(v0, v1);
        *(uint32_t*)(Ol + e0 + col) = pk(v0 - bfv(v0), v1 - bfv(v1));
        *(uint32_t*)(Oh + e1 + col) = pk(v2, v3);
        *(uint32_t*)(Ol + e1 + col) = pk(v2 - bfv(v2), v3 - bfv(v3));
    }
}

// ---------------------------------------------------------------------------
// RMSNorm with split bf16 output
// ---------------------------------------------------------------------------
__global__ __launch_bounds__(256) void rmsnorm_split(const float* __restrict__ x,
                                                     const float* __restrict__ w,
                                                     __nv_bfloat16* __restrict__ ohi,
                                                     __nv_bfloat16* __restrict__ olo) {
    __shared__ float red[8];
    const int row = blockIdx.x;
    const int tid = threadIdx.x;
    float4 v = ((const float4*)(x + (size_t)row * DD))[tid];
    float ss = v.x * v.x + v.y * v.y + v.z * v.z + v.w * v.w;
#pragma unroll
    for (int off = 16; off > 0; off >>= 1)
        ss += __shfl_xor_sync(0xffffffffu, ss, off);
    if ((tid & 31) == 0) red[tid >> 5] = ss;
    __syncthreads();
    float tot = 0.f;
#pragma unroll
    for (int i = 0; i < 8; i++) tot += red[i];
    const float inv = rsqrtf(tot * (1.0f / DD) + EPS);
    const float4 wv = ((const float4*)w)[tid];
    float o0 = wv.x * (v.x * inv), o1 = wv.y * (v.y * inv);
    float o2 = wv.z * (v.z * inv), o3 = wv.w * (v.w * inv);
    const size_t e = (size_t)row * DD + tid * 4;
    *(uint32_t*)(ohi + e)     = pk(o0, o1);
    *(uint32_t*)(ohi + e + 2) = pk(o2, o3);
    *(uint32_t*)(olo + e)     = pk(o0 - bfv(o0), o1 - bfv(o1));
    *(uint32_t*)(olo + e + 2) = pk(o2 - bfv(o2), o3 - bfv(o3));
}

// ---------------------------------------------------------------------------
// silu(gate)*up with split bf16 output
// ---------------------------------------------------------------------------
__global__ __launch_bounds__(256) void silu_split(const float* __restrict__ g,
                                                  const float* __restrict__ u,
                                                  __nv_bfloat16* __restrict__ ohi,
                                                  __nv_bfloat16* __restrict__ olo) {
    const size_t i = (size_t)blockIdx.x * blockDim.x + threadIdx.x;
    float4 gv = ((const float4*)g)[i];
    float4 uv = ((const float4*)u)[i];
    float o0 = gv.x / (1.f + __expf(-gv.x)) * uv.x;
    float o1 = gv.y / (1.f + __expf(-gv.y)) * uv.y;
    float o2 = gv.z / (1.f + __expf(-gv.z)) * uv.z;
    float o3 = gv.w / (1.f + __expf(-gv.w)) * uv.w;
    const size_t e = i * 4;
    *(uint32_t*)(ohi + e)     = pk(o0, o1);
    *(uint32_t*)(ohi + e + 2) = pk(o2, o3);
    *(uint32_t*)(olo + e)     = pk(o0 - bfv(o0), o1 - bfv(o1));
    *(uint32_t*)(olo + e + 2) = pk(o2 - bfv(o2), o3 - bfv(o3));
}

// ---------------------------------------------------------------------------
// fp32 -> bf16 hi/lo split (weights)
// ---------------------------------------------------------------------------
__global__ __launch_bounds__(256) void split_k(const float* __restrict__ s,
                                               __nv_bfloat16* __restrict__ hi,
                                               __nv_bfloat16* __restrict__ lo) {
    const size_t i = (size_t)blockIdx.x * blockDim.x + threadIdx.x;
    float4 v = ((const float4*)s)[i];
    const size_t e = i * 4;
    *(uint32_t*)(hi + e)     = pk(v.x, v.y);
    *(uint32_t*)(hi + e + 2) = pk(v.z, v.w);
    *(uint32_t*)(lo + e)     = pk(v.x - bfv(v.x), v.y - bfv(v.y));
    *(uint32_t*)(lo + e + 2) = pk(v.z - bfv(v.z), v.w - bfv(v.w));
}

// ---------------------------------------------------------------------------
// Launch
// ---------------------------------------------------------------------------
extern "C" void kernel_launch(void* const* d_in, const int* in_sizes, int n_in,
                              void* d_out, int out_size) {
    const float* x       = (const float*)d_in[0];
    const int*   amask   = (const int*)  d_in[1];
    const float* w_norm1 = (const float*)d_in[2];
    const float* wq      = (const float*)d_in[3];
    const float* bq      = (const float*)d_in[4];
    const float* wk      = (const float*)d_in[5];
    const float* bk      = (const float*)d_in[6];
    const float* wv      = (const float*)d_in[7];
    const float* bv      = (const float*)d_in[8];
    const float* wo      = (const float*)d_in[9];
    const float* bo      = (const float*)d_in[10];
    const float* w_norm2 = (const float*)d_in[11];
    const float* w_gate  = (const float*)d_in[12];
    const float* w_up    = (const float*)d_in[13];
    const float* w_down  = (const float*)d_in[14];
    float* out = (float*)d_out;

    float *gate, *up, *x1;
    cudaGetSymbolAddress((void**)&gate, g_gate);
    cudaGetSymbolAddress((void**)&up,   g_up);
    cudaGetSymbolAddress((void**)&x1,   g_x1);

    __nv_bfloat16 *hbh, *hbl, *qh, *ql, *kh, *kl, *vh, *vl, *ah, *al, *h2h, *h2l,
                  *gah, *gal, *wqh, *wql, *wkh, *wkl, *wvh, *wvl, *woh, *wol,
                  *wgh, *wgl, *wuh, *wul, *wdh, *wdl;
    cudaGetSymbolAddress((void**)&hbh, g_hbh);  cudaGetSymbolAddress((void**)&hbl, g_hbl);
    cudaGetSymbolAddress((void**)&qh,  g_qh);   cudaGetSymbolAddress((void**)&ql,  g_ql);
    cudaGetSymbolAddress((void**)&kh,  g_kh);   cudaGetSymbolAddress((void**)&kl,  g_kl);
    cudaGetSymbolAddress((void**)&vh,  g_vh);   cudaGetSymbolAddress((void**)&vl,  g_vl);
    cudaGetSymbolAddress((void**)&ah,  g_ah);   cudaGetSymbolAddress((void**)&al,  g_al);
    cudaGetSymbolAddress((void**)&h2h, g_h2h);  cudaGetSymbolAddress((void**)&h2l, g_h2l);
    cudaGetSymbolAddress((void**)&gah, g_gah);  cudaGetSymbolAddress((void**)&gal, g_gal);
    cudaGetSymbolAddress((void**)&wqh, g_wqh);  cudaGetSymbolAddress((void**)&wql, g_wql);
    cudaGetSymbolAddress((void**)&wkh, g_wkh);  cudaGetSymbolAddress((void**)&wkl, g_wkl);
    cudaGetSymbolAddress((void**)&wvh, g_wvh);  cudaGetSymbolAddress((void**)&wvl, g_wvl);
    cudaGetSymbolAddress((void**)&woh, g_woh);  cudaGetSymbolAddress((void**)&wol, g_wol);
    cudaGetSymbolAddress((void**)&wgh, g_wgh);  cudaGetSymbolAddress((void**)&wgl, g_wgl);
    cudaGetSymbolAddress((void**)&wuh, g_wuh);  cudaGetSymbolAddress((void**)&wul, g_wul);
    cudaGetSymbolAddress((void**)&wdh, g_wdh);  cudaGetSymbolAddress((void**)&wdl, g_wdl);

    cudaFuncSetAttribute(mmgemm<true,  false, true >, cudaFuncAttributeMaxDynamicSharedMemorySize, GEMM_SMEM);
    cudaFuncSetAttribute(mmgemm<true,  true,  false>, cudaFuncAttributeMaxDynamicSharedMemorySize, GEMM_SMEM);
    cudaFuncSetAttribute(mmgemm<false, false, false>, cudaFuncAttributeMaxDynamicSharedMemorySize, GEMM_SMEM);
    cudaFuncSetAttribute(mmgemm<false, true,  false>, cudaFuncAttributeMaxDynamicSharedMemorySize, GEMM_SMEM);
    cudaFuncSetAttribute(flash_mma, cudaFuncAttributeMaxDynamicSharedMemorySize, FLASH_SMEM);

    // weight splits
    split_k<<<DD * DD / 1024, 256>>>(wq, wqh, wql);
    split_k<<<DD * DD / 1024, 256>>>(wk, wkh, wkl);
    split_k<<<DD * DD / 1024, 256>>>(wv, wvh, wvl);
    split_k<<<DD * DD / 1024, 256>>>(wo, woh, wol);
    split_k<<<DD * FF / 1024, 256>>>(w_gate, wgh, wgl);
    split_k<<<DD * FF / 1024, 256>>>(w_up,   wuh, wul);
    split_k<<<FF * DD / 1024, 256>>>(w_down, wdh, wdl);

    const dim3 gD(DD / 128, MROWS / 128);   // (8, 32)
    const dim3 gF(FF / 128, MROWS / 128);   // (32, 32)

    // attention sub-block
    rmsnorm_split<<<MROWS, 256>>>(x, w_norm1, hbh, hbl);
    mmgemm<true, false, true><<<gD, 256, GEMM_SMEM>>>(hbh, hbl, wqh, wql, bq, nullptr,
                                                      nullptr, qh, ql, MROWS, DD, DD);
    mmgemm<true, false, true><<<gD, 256, GEMM_SMEM>>>(hbh, hbl, wkh, wkl, bk, nullptr,
                                                      nullptr, kh, kl, MROWS, DD, DD);
    mmgemm<true, false, true><<<gD, 256, GEMM_SMEM>>>(hbh, hbl, wvh, wvl, bv, nullptr,
                                                      nullptr, vh, vl, MROWS, DD, DD);
    flash_mma<<<dim3(SS / 64, HH, BB), 128, FLASH_SMEM>>>(qh, ql, kh, kl, vh, vl,
                                                          amask, ah, al);
    mmgemm<true, true, false><<<gD, 256, GEMM_SMEM>>>(ah, al, woh, wol, bo, x,
                                                      x1, nullptr, nullptr, MROWS, DD, DD);

    // MLP sub-block
    rmsnorm_split<<<MROWS, 256>>>(x1, w_norm2, h2h, h2l);
    mmgemm<false, false, false><<<gF, 256, GEMM_SMEM>>>(h2h, h2l, wgh, wgl, nullptr, nullptr,
                                                        gate, nullptr, nullptr, MROWS, FF, DD);
    mmgemm<false, false, false><<<gF, 256, GEMM_SMEM>>>(h2h, h2l, wuh, wul, nullptr, nullptr,
                                                        up, nullptr, nullptr, MROWS, FF, DD);
    silu_split<<<MROWS * FF / 1024, 256>>>(gate, up, gah, gal);
    mmgemm<false, true, false><<<gD, 256, GEMM_SMEM>>>(gah, gal, wdh, wdl, nullptr, x1,
                                                       out, nullptr, nullptr, MROWS, DD, FF);
}

// round 5
// speedup vs baseline: 2.9678x; 1.0543x over previous
#include <cuda_runtime.h>
#include <cuda_bf16.h>
#include <cstdint>
#include <cstddef>

// ---------------------------------------------------------------------------
// Problem constants
// ---------------------------------------------------------------------------
#define BB 2
#define SS 2048
#define DD 1024
#define HH 16
#define HDIM 64
#define FF 4096
#define MROWS (BB * SS)          // 4096
#define EPS 1e-6f

// ---------------------------------------------------------------------------
// Device scratch
// ---------------------------------------------------------------------------
__device__ float g_gate[MROWS * FF];
__device__ float g_x1  [MROWS * DD];

__device__ __nv_bfloat16 g_hbh[MROWS * DD],  g_hbl[MROWS * DD];
__device__ __nv_bfloat16 g_qh [MROWS * DD],  g_ql [MROWS * DD];
__device__ __nv_bfloat16 g_kh [MROWS * DD],  g_kl [MROWS * DD];
__device__ __nv_bfloat16 g_vh [MROWS * DD],  g_vl [MROWS * DD];
__device__ __nv_bfloat16 g_ah [MROWS * DD],  g_al [MROWS * DD];
__device__ __nv_bfloat16 g_h2h[MROWS * DD],  g_h2l[MROWS * DD];
__device__ __nv_bfloat16 g_gah[MROWS * FF],  g_gal[MROWS * FF];

__device__ __nv_bfloat16 g_wqh[DD * DD], g_wql[DD * DD];
__device__ __nv_bfloat16 g_wkh[DD * DD], g_wkl[DD * DD];
__device__ __nv_bfloat16 g_wvh[DD * DD], g_wvl[DD * DD];
__device__ __nv_bfloat16 g_woh[DD * DD], g_wol[DD * DD];
__device__ __nv_bfloat16 g_wgh[DD * FF], g_wgl[DD * FF];
__device__ __nv_bfloat16 g_wuh[DD * FF], g_wul[DD * FF];
__device__ __nv_bfloat16 g_wdh[FF * DD], g_wdl[FF * DD];

// ---------------------------------------------------------------------------
// Helpers (sm_80+ ISA only)
// ---------------------------------------------------------------------------
__device__ __forceinline__ uint32_t smem_u32(const void* p) {
    uint32_t a;
    asm("{ .reg .u64 t; cvta.to.shared.u64 t, %1; cvt.u32.u64 %0, t; }"
        : "=r"(a) : "l"(p));
    return a;
}

__device__ __forceinline__ void ldsm4(uint32_t* r, uint32_t addr) {
    asm volatile("ldmatrix.sync.aligned.m8n8.x4.shared.b16 {%0,%1,%2,%3}, [%4];"
                 : "=r"(r[0]), "=r"(r[1]), "=r"(r[2]), "=r"(r[3]) : "r"(addr));
}

__device__ __forceinline__ void ldsm4t(uint32_t* r, uint32_t addr) {
    asm volatile("ldmatrix.sync.aligned.m8n8.x4.trans.shared.b16 {%0,%1,%2,%3}, [%4];"
                 : "=r"(r[0]), "=r"(r[1]), "=r"(r[2]), "=r"(r[3]) : "r"(addr));
}

__device__ __forceinline__ void mma_bf16(float* d, const uint32_t* a,
                                         const uint32_t* b) {
    asm volatile(
        "mma.sync.aligned.m16n8k16.row.col.f32.bf16.bf16.f32 "
        "{%0,%1,%2,%3}, {%4,%5,%6,%7}, {%8,%9}, {%0,%1,%2,%3};"
        : "+f"(d[0]), "+f"(d[1]), "+f"(d[2]), "+f"(d[3])
        : "r"(a[0]), "r"(a[1]), "r"(a[2]), "r"(a[3]), "r"(b[0]), "r"(b[1]));
}

__device__ __forceinline__ uint32_t pk(float x, float y) {
    __nv_bfloat162 h = __floats2bfloat162_rn(x, y);
    return *(uint32_t*)&h;
}

__device__ __forceinline__ float bfv(float x) {
    return __bfloat162float(__float2bfloat16_rn(x));
}

#define CP16(dst, src) \
    asm volatile("cp.async.cg.shared.global [%0], [%1], 16;" \
                 :: "r"(dst), "l"(src) : "memory")
#define CPCOMMIT() asm volatile("cp.async.commit_group;" ::: "memory")

__device__ __forceinline__ void cpwait(int keep) {
    if (keep) asm volatile("cp.async.wait_group 1;" ::: "memory");
    else      asm volatile("cp.async.wait_group 0;" ::: "memory");
}

// ---------------------------------------------------------------------------
// bf16x3 tensor GEMM, 3-stage cp.async pipeline, pre-split inputs.
// C[M,N] = A[M,K] @ B[K,N] (+bias) (+gate-SiLU) (+res); out fp32 or split bf16.
// CTA 128x128, K-chunk 32, 256 threads (8 warps of 64x32).
// ---------------------------------------------------------------------------
#define BKC 32
#define ASTRIDE 80                 // bytes per A row (data 64B + pad)
#define BSTRIDE 272                // bytes per B row (data 256B + pad)
#define OFF_AH 0
#define OFF_AL 10240
#define OFF_BH 20480
#define OFF_BL 29184
#define BUFSZ  37888
#define GEMM_SMEM (3 * BUFSZ)

template <bool BIAS, bool RES, bool SPLIT, bool SILU>
__global__ __launch_bounds__(256, 2)
void mmgemm(const __nv_bfloat16* __restrict__ Ah, const __nv_bfloat16* __restrict__ Al,
            const __nv_bfloat16* __restrict__ Bh, const __nv_bfloat16* __restrict__ Bl,
            const float* __restrict__ bias, const float* __restrict__ res,
            float* __restrict__ C,
            __nv_bfloat16* __restrict__ Chi, __nv_bfloat16* __restrict__ Clo,
            int M, int N, int K) {
    extern __shared__ char smem[];
    const uint32_t sb = smem_u32(smem);

    const int tid  = threadIdx.x;
    const int lane = tid & 31;
    const int wid  = tid >> 5;
    const int m0   = (wid >> 2) * 64;
    const int n0   = (wid & 3) * 32;
    const int mBase = blockIdx.y * 128;
    const int nBase = blockIdx.x * 128;

    const uint32_t aoff = (uint32_t)((lane & 15) * ASTRIDE + (lane >> 4) * 16);
    const uint32_t boff = (uint32_t)((lane & 15) * BSTRIDE + (lane >> 4) * 16);

    float acc[4][4][4];
#pragma unroll
    for (int i = 0; i < 4; i++)
#pragma unroll
        for (int j = 0; j < 4; j++)
#pragma unroll
            for (int t = 0; t < 4; t++) acc[i][j][t] = 0.f;

    const int nch = K / BKC;

#define ISSUE(c, buf)                                                         \
    do {                                                                      \
        const int k0_ = (c) * BKC;                                            \
        const uint32_t bp = sb + (uint32_t)((buf) * BUFSZ);                   \
        _Pragma("unroll")                                                     \
        for (int i = 0; i < 2; i++) {                                         \
            const int idx = tid + i * 256;                                    \
            const int r = idx >> 2, c16 = idx & 3;                            \
            const size_t so = (size_t)(mBase + r) * K + k0_ + c16 * 8;        \
            const uint32_t d = bp + (uint32_t)(r * ASTRIDE + c16 * 16);       \
            CP16(d + OFF_AH, Ah + so);                                        \
            CP16(d + OFF_AL, Al + so);                                        \
        }                                                                     \
        _Pragma("unroll")                                                     \
        for (int i = 0; i < 2; i++) {                                         \
            const int idx = tid + i * 256;                                    \
            const int kk = idx >> 4, c16 = idx & 15;                          \
            const size_t so = (size_t)(k0_ + kk) * N + nBase + c16 * 8;       \
            const uint32_t d = bp + (uint32_t)(kk * BSTRIDE + c16 * 16);      \
            CP16(d + OFF_BH, Bh + so);                                        \
            CP16(d + OFF_BL, Bl + so);                                        \
        }                                                                     \
        CPCOMMIT();                                                           \
    } while (0)

    ISSUE(0, 0);
    if (nch > 1) ISSUE(1, 1);

    int buf = 0;
    for (int c = 0; c < nch; c++) {
        cpwait(c + 1 < nch);
        __syncthreads();
        // safe: every warp has finished reading buffer (c-1)%3 == (c+2)%3
        if (c + 2 < nch) {
            int nb = buf + 2; if (nb >= 3) nb -= 3;
            ISSUE(c + 2, nb);
        }

        const uint32_t bufb = sb + (uint32_t)(buf * BUFSZ);
        const uint32_t ah = bufb + OFF_AH + (uint32_t)(m0 * ASTRIDE) + aoff;
        const uint32_t al = bufb + OFF_AL + (uint32_t)(m0 * ASTRIDE) + aoff;
        const uint32_t bh = bufb + OFF_BH + (uint32_t)(n0 * 2) + boff;
        const uint32_t bl = bufb + OFF_BL + (uint32_t)(n0 * 2) + boff;

#pragma unroll
        for (int ks = 0; ks < 2; ks++) {
            uint32_t fah[4][4], fbh[2][4];
#pragma unroll
            for (int mi = 0; mi < 4; mi++)
                ldsm4(fah[mi], ah + mi * (16 * ASTRIDE) + ks * 32);
#pragma unroll
            for (int np = 0; np < 2; np++)
                ldsm4t(fbh[np], bh + np * 32 + ks * (16 * BSTRIDE));
#pragma unroll
            for (int mi = 0; mi < 4; mi++)
#pragma unroll
                for (int nj = 0; nj < 4; nj++)
                    mma_bf16(acc[mi][nj], fah[mi], &fbh[nj >> 1][(nj & 1) * 2]);

            uint32_t fbl[2][4];
#pragma unroll
            for (int np = 0; np < 2; np++)
                ldsm4t(fbl[np], bl + np * 32 + ks * (16 * BSTRIDE));
#pragma unroll
            for (int mi = 0; mi < 4; mi++)
#pragma unroll
                for (int nj = 0; nj < 4; nj++)
                    mma_bf16(acc[mi][nj], fah[mi], &fbl[nj >> 1][(nj & 1) * 2]);

            uint32_t fal[4][4];
#pragma unroll
            for (int mi = 0; mi < 4; mi++)
                ldsm4(fal[mi], al + mi * (16 * ASTRIDE) + ks * 32);
#pragma unroll
            for (int mi = 0; mi < 4; mi++)
#pragma unroll
                for (int nj = 0; nj < 4; nj++)
                    mma_bf16(acc[mi][nj], fal[mi], &fbh[nj >> 1][(nj & 1) * 2]);
        }

        if (++buf >= 3) buf = 0;
    }
#undef ISSUE

    // epilogue
    const int g  = lane >> 2;
    const int tc = (lane & 3) * 2;
#pragma unroll
    for (int mi = 0; mi < 4; mi++) {
        const int row = mBase + m0 + mi * 16 + g;
#pragma unroll
        for (int nj = 0; nj < 4; nj++) {
            const int col = nBase + n0 + nj * 8 + tc;
            float2 bv = make_float2(0.f, 0.f);
            if (BIAS) bv = *(const float2*)(bias + col);
            float v0 = acc[mi][nj][0] + bv.x;
            float v1 = acc[mi][nj][1] + bv.y;
            float v2 = acc[mi][nj][2] + bv.x;
            float v3 = acc[mi][nj][3] + bv.y;
            if (RES) {
                float2 e0 = *(const float2*)(res + (size_t)row * N + col);
                float2 e1 = *(const float2*)(res + (size_t)(row + 8) * N + col);
                v0 += e0.x; v1 += e0.y; v2 += e1.x; v3 += e1.y;
            }
            if (SILU) {   // res slot carries gate (fp32): out = silu(gate) * acc
                float2 g0 = *(const float2*)(res + (size_t)row * N + col);
                float2 g1 = *(const float2*)(res + (size_t)(row + 8) * N + col);
                v0 *= g0.x / (1.f + __expf(-g0.x));
                v1 *= g0.y / (1.f + __expf(-g0.y));
                v2 *= g1.x / (1.f + __expf(-g1.x));
                v3 *= g1.y / (1.f + __expf(-g1.y));
            }
            if (SPLIT) {
                *(uint32_t*)(Chi + (size_t)row * N + col)       = pk(v0, v1);
                *(uint32_t*)(Clo + (size_t)row * N + col)       = pk(v0 - bfv(v0), v1 - bfv(v1));
                *(uint32_t*)(Chi + (size_t)(row + 8) * N + col) = pk(v2, v3);
                *(uint32_t*)(Clo + (size_t)(row + 8) * N + col) = pk(v2 - bfv(v2), v3 - bfv(v3));
            } else {
                *(float2*)(C + (size_t)row * N + col)       = make_float2(v0, v1);
                *(float2*)(C + (size_t)(row + 8) * N + col) = make_float2(v2, v3);
            }
        }
    }
}

// ---------------------------------------------------------------------------
// Tensor-core flash attention: 64q x 64k tiles, HD=64, 128 threads (4 warps).
// ---------------------------------------------------------------------------
#define FQ_STRIDE 144                    // 64 bf16 data (128B) + 16B pad
#define F_OFF_QH 0
#define F_OFF_QL 9216
#define F_OFF_ST 18432                   // stage base
#define F_STAGE  36864                   // Kh,Kl,Vh,Vl (9216 each)
#define F_OFF_MK 92160                   // 2 x 256B mask
#define FLASH_SMEM 92672

__global__ __launch_bounds__(128)
void flash_mma(const __nv_bfloat16* __restrict__ Qh, const __nv_bfloat16* __restrict__ Ql,
               const __nv_bfloat16* __restrict__ Kh, const __nv_bfloat16* __restrict__ Kl,
               const __nv_bfloat16* __restrict__ Vh, const __nv_bfloat16* __restrict__ Vl,
               const int* __restrict__ amask,
               __nv_bfloat16* __restrict__ Oh, __nv_bfloat16* __restrict__ Ol) {
    extern __shared__ char smem[];
    const uint32_t sb = smem_u32(smem);

    const int tid  = threadIdx.x;
    const int lane = tid & 31;
    const int wid  = tid >> 5;
    const int qb   = blockIdx.x * 64;
    const int h    = blockIdx.y;
    const int b    = blockIdx.z;
    const int bS   = b * SS;
    const int hcol = h * HDIM;
    const int nt   = qb / 64 + 1;

#pragma unroll
    for (int i = 0; i < 4; i++) {
        const int idx = tid + i * 128;
        const int r = idx >> 3, c16 = idx & 7;
        const size_t so = (size_t)(bS + qb + r) * DD + hcol + c16 * 8;
        const uint32_t d = sb + (uint32_t)(r * FQ_STRIDE + c16 * 16);
        CP16(d + F_OFF_QH, Qh + so);
        CP16(d + F_OFF_QL, Ql + so);
    }

#define KVISSUE(kt, st)                                                       \
    do {                                                                      \
        const int kb_ = (kt) * 64;                                            \
        const uint32_t stb = sb + F_OFF_ST + (uint32_t)((st) * F_STAGE);      \
        _Pragma("unroll")                                                     \
        for (int i = 0; i < 4; i++) {                                         \
            const int idx = tid + i * 128;                                    \
            const int r = idx >> 3, c16 = idx & 7;                            \
            const size_t so = (size_t)(bS + kb_ + r) * DD + hcol + c16 * 8;   \
            const uint32_t d = stb + (uint32_t)(r * FQ_STRIDE + c16 * 16);    \
            CP16(d + 0,     Kh + so);                                         \
            CP16(d + 9216,  Kl + so);                                         \
            CP16(d + 18432, Vh + so);                                         \
            CP16(d + 27648, Vl + so);                                         \
        }                                                                     \
        if (tid < 16)                                                         \
            CP16(sb + F_OFF_MK + (uint32_t)((st) * 256 + tid * 16),           \
                 amask + bS + kb_ + tid * 4);                                 \
        CPCOMMIT();                                                           \
    } while (0)

    KVISSUE(0, 0);
    if (nt > 1) KVISSUE(1, 1);
    cpwait(nt > 1);
    __syncthreads();

    const int qr0 = wid * 16;
    const uint32_t qaddr = sb + (uint32_t)((qr0 + (lane & 15)) * FQ_STRIDE + (lane >> 4) * 16);
    uint32_t qfh[4][4], qfl[4][4];
#pragma unroll
    for (int kc = 0; kc < 4; kc++) {
        ldsm4(qfh[kc], qaddr + F_OFF_QH + kc * 32);
        ldsm4(qfl[kc], qaddr + F_OFF_QL + kc * 32);
    }

    const int rloc0 = qr0 + (lane >> 2);
    const int tc2   = (lane & 3) * 2;
    const int r0g   = qb + rloc0;
    const int r1g   = r0g + 8;

    float o[8][4];
#pragma unroll
    for (int dt = 0; dt < 8; dt++)
#pragma unroll
        for (int e = 0; e < 4; e++) o[dt][e] = 0.f;
    float m0 = -1e30f, m1 = -1e30f, l0 = 0.f, l1 = 0.f;

    for (int kt = 0; kt < nt; kt++) {
        if (kt > 0) { cpwait(kt + 1 < nt); __syncthreads(); }
        const int kb = kt * 64;
        const uint32_t stb = sb + F_OFF_ST + (uint32_t)((kt & 1) * F_STAGE);
        const uint32_t kaddr = stb + (uint32_t)(((lane & 7) + ((lane >> 4) << 3)) * FQ_STRIDE
                                                + ((lane >> 3) & 1) * 16);
        const uint32_t vaddr = stb + 18432u + (uint32_t)((lane & 15) * FQ_STRIDE + (lane >> 4) * 16);
        const int* smk = (const int*)(smem + F_OFF_MK + (kt & 1) * 256);

        float s[8][4];
#pragma unroll
        for (int jt = 0; jt < 8; jt++)
#pragma unroll
            for (int e = 0; e < 4; e++) s[jt][e] = 0.f;

#pragma unroll
        for (int kc = 0; kc < 4; kc++)
#pragma unroll
            for (int g2 = 0; g2 < 4; g2++) {
                uint32_t kf[4], kfl[4];
                ldsm4(kf,  kaddr + g2 * (16 * FQ_STRIDE) + kc * 32);
                mma_bf16(s[2 * g2],     qfh[kc], kf + 0);
                mma_bf16(s[2 * g2 + 1], qfh[kc], kf + 2);
                ldsm4(kfl, kaddr + 9216 + g2 * (16 * FQ_STRIDE) + kc * 32);
                mma_bf16(s[2 * g2],     qfh[kc], kfl + 0);
                mma_bf16(s[2 * g2 + 1], qfh[kc], kfl + 2);
                mma_bf16(s[2 * g2],     qfl[kc], kf + 0);
                mma_bf16(s[2 * g2 + 1], qfl[kc], kf + 2);
            }

#pragma unroll
        for (int jt = 0; jt < 8; jt++) {
            const int c0 = kb + jt * 8 + tc2;
            const int c1 = c0 + 1;
            const bool k0 = smk[jt * 8 + tc2] != 0;
            const bool k1 = smk[jt * 8 + tc2 + 1] != 0;
            s[jt][0] = (c0 <= r0g && k0) ? s[jt][0] * 0.125f : -1e30f;
            s[jt][1] = (c1 <= r0g && k1) ? s[jt][1] * 0.125f : -1e30f;
            s[jt][2] = (c0 <= r1g && k0) ? s[jt][2] * 0.125f : -1e30f;
            s[jt][3] = (c1 <= r1g && k1) ? s[jt][3] * 0.125f : -1e30f;
        }

        float mx0 = -1e30f, mx1 = -1e30f;
#pragma unroll
        for (int jt = 0; jt < 8; jt++) {
            mx0 = fmaxf(mx0, fmaxf(s[jt][0], s[jt][1]));
            mx1 = fmaxf(mx1, fmaxf(s[jt][2], s[jt][3]));
        }
        mx0 = fmaxf(mx0, __shfl_xor_sync(0xffffffffu, mx0, 1));
        mx0 = fmaxf(mx0, __shfl_xor_sync(0xffffffffu, mx0, 2));
        mx1 = fmaxf(mx1, __shfl_xor_sync(0xffffffffu, mx1, 1));
        mx1 = fmaxf(mx1, __shfl_xor_sync(0xffffffffu, mx1, 2));
        const float mn0 = fmaxf(m0, mx0), mn1 = fmaxf(m1, mx1);
        const float cr0 = __expf(m0 - mn0), cr1 = __expf(m1 - mn1);
        float sum0 = 0.f, sum1 = 0.f;
#pragma unroll
        for (int jt = 0; jt < 8; jt++) {
            s[jt][0] = __expf(s[jt][0] - mn0);
            s[jt][1] = __expf(s[jt][1] - mn0);
            s[jt][2] = __expf(s[jt][2] - mn1);
            s[jt][3] = __expf(s[jt][3] - mn1);
            sum0 += s[jt][0] + s[jt][1];
            sum1 += s[jt][2] + s[jt][3];
        }
        sum0 += __shfl_xor_sync(0xffffffffu, sum0, 1);
        sum0 += __shfl_xor_sync(0xffffffffu, sum0, 2);
        sum1 += __shfl_xor_sync(0xffffffffu, sum1, 1);
        sum1 += __shfl_xor_sync(0xffffffffu, sum1, 2);
        l0 = l0 * cr0 + sum0;
        l1 = l1 * cr1 + sum1;
        m0 = mn0; m1 = mn1;
#pragma unroll
        for (int dt = 0; dt < 8; dt++) {
            o[dt][0] *= cr0; o[dt][1] *= cr0;
            o[dt][2] *= cr1; o[dt][3] *= cr1;
        }

#pragma unroll
        for (int kc2 = 0; kc2 < 4; kc2++) {
            uint32_t ph[4], pl[4];
            {
                const float a0 = s[2 * kc2][0],     a1 = s[2 * kc2][1];
                const float a2 = s[2 * kc2][2],     a3 = s[2 * kc2][3];
                const float a4 = s[2 * kc2 + 1][0], a5 = s[2 * kc2 + 1][1];
                const float a6 = s[2 * kc2 + 1][2], a7 = s[2 * kc2 + 1][3];
                ph[0] = pk(a0, a1); pl[0] = pk(a0 - bfv(a0), a1 - bfv(a1));
                ph[1] = pk(a2, a3); pl[1] = pk(a2 - bfv(a2), a3 - bfv(a3));
                ph[2] = pk(a4, a5); pl[2] = pk(a4 - bfv(a4), a5 - bfv(a5));
                ph[3] = pk(a6, a7); pl[3] = pk(a6 - bfv(a6), a7 - bfv(a7));
            }
#pragma unroll
            for (int g2 = 0; g2 < 4; g2++) {
                uint32_t vf[4], vfl[4];
                ldsm4t(vf,  vaddr + kc2 * (16 * FQ_STRIDE) + g2 * 32);
                mma_bf16(o[2 * g2],     ph, vf + 0);
                mma_bf16(o[2 * g2 + 1], ph, vf + 2);
                ldsm4t(vfl, vaddr + 9216 + kc2 * (16 * FQ_STRIDE) + g2 * 32);
                mma_bf16(o[2 * g2],     ph, vfl + 0);
                mma_bf16(o[2 * g2 + 1], ph, vfl + 2);
                mma_bf16(o[2 * g2],     pl, vf + 0);
                mma_bf16(o[2 * g2 + 1], pl, vf + 2);
            }
        }

        __syncthreads();
        if (kt + 2 < nt) KVISSUE(kt + 2, kt & 1);
    }
#undef KVISSUE

    const float inv0 = 1.f / l0, inv1 = 1.f / l1;
    const size_t e0 = (size_t)(bS + r0g) * DD + hcol;
    const size_t e1 = (size_t)(bS + r1g) * DD + hcol;
#pragma unroll
    for (int dt = 0; dt < 8; dt++) {
        const int col = dt * 8 + tc2;
        float v0 = o[dt][0] * inv0, v1 = o[dt][1] * inv0;
        float v2 = o[dt][2] * inv1, v3 = o[dt][3] * inv1;
        *(uint32_t*)(Oh + e0 + col) = pk(v0, v1);
        *(uint32_t*)(Ol + e0 + col) = pk(v0 - bfv(v0), v1 - bfv(v1));
        *(uint32_t*)(Oh + e1 + col) = pk(v2, v3);
        *(uint32_t*)(Ol + e1 + col) = pk(v2 - bfv(v2), v3 - bfv(v3));
    }
}

// ---------------------------------------------------------------------------
// RMSNorm with split bf16 output
// ---------------------------------------------------------------------------
__global__ __launch_bounds__(256) void rmsnorm_split(const float* __restrict__ x,
                                                     const float* __restrict__ w,
                                                     __nv_bfloat16* __restrict__ ohi,
                                                     __nv_bfloat16* __restrict__ olo) {
    __shared__ float red[8];
    const int row = blockIdx.x;
    const int tid = threadIdx.x;
    float4 v = ((const float4*)(x + (size_t)row * DD))[tid];
    float ss = v.x * v.x + v.y * v.y + v.z * v.z + v.w * v.w;
#pragma unroll
    for (int off = 16; off > 0; off >>= 1)
        ss += __shfl_xor_sync(0xffffffffu, ss, off);
    if ((tid & 31) == 0) red[tid >> 5] = ss;
    __syncthreads();
    float tot = 0.f;
#pragma unroll
    for (int i = 0; i < 8; i++) tot += red[i];
    const float inv = rsqrtf(tot * (1.0f / DD) + EPS);
    const float4 wv = ((const float4*)w)[tid];
    float o0 = wv.x * (v.x * inv), o1 = wv.y * (v.y * inv);
    float o2 = wv.z * (v.z * inv), o3 = wv.w * (v.w * inv);
    const size_t e = (size_t)row * DD + tid * 4;
    *(uint2*)(ohi + e) = make_uint2(pk(o0, o1), pk(o2, o3));
    *(uint2*)(olo + e) = make_uint2(pk(o0 - bfv(o0), o1 - bfv(o1)),
                                    pk(o2 - bfv(o2), o3 - bfv(o3)));
}

// ---------------------------------------------------------------------------
// fp32 -> bf16 hi/lo split (weights): 4 float4 per thread, uint2 stores
// ---------------------------------------------------------------------------
__global__ __launch_bounds__(256) void split_k(const float* __restrict__ s,
                                               __nv_bfloat16* __restrict__ hi,
                                               __nv_bfloat16* __restrict__ lo) {
    const size_t base = (size_t)blockIdx.x * 1024 + threadIdx.x;
#pragma unroll
    for (int i = 0; i < 4; i++) {
        const size_t idx = base + i * 256;
        float4 v = ((const float4*)s)[idx];
        const size_t e = idx * 4;
        *(uint2*)(hi + e) = make_uint2(pk(v.x, v.y), pk(v.z, v.w));
        *(uint2*)(lo + e) = make_uint2(pk(v.x - bfv(v.x), v.y - bfv(v.y)),
                                       pk(v.z - bfv(v.z), v.w - bfv(v.w)));
    }
}

// ---------------------------------------------------------------------------
// Launch
// ---------------------------------------------------------------------------
extern "C" void kernel_launch(void* const* d_in, const int* in_sizes, int n_in,
                              void* d_out, int out_size) {
    const float* x       = (const float*)d_in[0];
    const int*   amask   = (const int*)  d_in[1];
    const float* w_norm1 = (const float*)d_in[2];
    const float* wq      = (const float*)d_in[3];
    const float* bq      = (const float*)d_in[4];
    const float* wk      = (const float*)d_in[5];
    const float* bk      = (const float*)d_in[6];
    const float* wv      = (const float*)d_in[7];
    const float* bv      = (const float*)d_in[8];
    const float* wo      = (const float*)d_in[9];
    const float* bo      = (const float*)d_in[10];
    const float* w_norm2 = (const float*)d_in[11];
    const float* w_gate  = (const float*)d_in[12];
    const float* w_up    = (const float*)d_in[13];
    const float* w_down  = (const float*)d_in[14];
    float* out = (float*)d_out;

    float *gate, *x1;
    cudaGetSymbolAddress((void**)&gate, g_gate);
    cudaGetSymbolAddress((void**)&x1,   g_x1);

    __nv_bfloat16 *hbh, *hbl, *qh, *ql, *kh, *kl, *vh, *vl, *ah, *al, *h2h, *h2l,
                  *gah, *gal, *wqh, *wql, *wkh, *wkl, *wvh, *wvl, *woh, *wol,
                  *wgh, *wgl, *wuh, *wul, *wdh, *wdl;
    cudaGetSymbolAddress((void**)&hbh, g_hbh);  cudaGetSymbolAddress((void**)&hbl, g_hbl);
    cudaGetSymbolAddress((void**)&qh,  g_qh);   cudaGetSymbolAddress((void**)&ql,  g_ql);
    cudaGetSymbolAddress((void**)&kh,  g_kh);   cudaGetSymbolAddress((void**)&kl,  g_kl);
    cudaGetSymbolAddress((void**)&vh,  g_vh);   cudaGetSymbolAddress((void**)&vl,  g_vl);
    cudaGetSymbolAddress((void**)&ah,  g_ah);   cudaGetSymbolAddress((void**)&al,  g_al);
    cudaGetSymbolAddress((void**)&h2h, g_h2h);  cudaGetSymbolAddress((void**)&h2l, g_h2l);
    cudaGetSymbolAddress((void**)&gah, g_gah);  cudaGetSymbolAddress((void**)&gal, g_gal);
    cudaGetSymbolAddress((void**)&wqh, g_wqh);  cudaGetSymbolAddress((void**)&wql, g_wql);
    cudaGetSymbolAddress((void**)&wkh, g_wkh);  cudaGetSymbolAddress((void**)&wkl, g_wkl);
    cudaGetSymbolAddress((void**)&wvh, g_wvh);  cudaGetSymbolAddress((void**)&wvl, g_wvl);
    cudaGetSymbolAddress((void**)&woh, g_woh);  cudaGetSymbolAddress((void**)&wol, g_wol);
    cudaGetSymbolAddress((void**)&wgh, g_wgh);  cudaGetSymbolAddress((void**)&wgl, g_wgl);
    cudaGetSymbolAddress((void**)&wuh, g_wuh);  cudaGetSymbolAddress((void**)&wul, g_wul);
    cudaGetSymbolAddress((void**)&wdh, g_wdh);  cudaGetSymbolAddress((void**)&wdl, g_wdl);

    cudaFuncSetAttribute(mmgemm<true,  false, true,  false>, cudaFuncAttributeMaxDynamicSharedMemorySize, GEMM_SMEM);
    cudaFuncSetAttribute(mmgemm<true,  true,  false, false>, cudaFuncAttributeMaxDynamicSharedMemorySize, GEMM_SMEM);
    cudaFuncSetAttribute(mmgemm<false, false, false, false>, cudaFuncAttributeMaxDynamicSharedMemorySize, GEMM_SMEM);
    cudaFuncSetAttribute(mmgemm<false, false, true,  true >, cudaFuncAttributeMaxDynamicSharedMemorySize, GEMM_SMEM);
    cudaFuncSetAttribute(mmgemm<false, true,  false, false>, cudaFuncAttributeMaxDynamicSharedMemorySize, GEMM_SMEM);
    cudaFuncSetAttribute(flash_mma, cudaFuncAttributeMaxDynamicSharedMemorySize, FLASH_SMEM);

    // weight splits
    split_k<<<DD * DD / 4096, 256>>>(wq, wqh, wql);
    split_k<<<DD * DD / 4096, 256>>>(wk, wkh, wkl);
    split_k<<<DD * DD / 4096, 256>>>(wv, wvh, wvl);
    split_k<<<DD * DD / 4096, 256>>>(wo, woh, wol);
    split_k<<<DD * FF / 4096, 256>>>(w_gate, wgh, wgl);
    split_k<<<DD * FF / 4096, 256>>>(w_up,   wuh, wul);
    split_k<<<FF * DD / 4096, 256>>>(w_down, wdh, wdl);

    const dim3 gD(DD / 128, MROWS / 128);   // (8, 32)
    const dim3 gF(FF / 128, MROWS / 128);   // (32, 32)

    // attention sub-block
    rmsnorm_split<<<MROWS, 256>>>(x, w_norm1, hbh, hbl);
    mmgemm<true, false, true, false><<<gD, 256, GEMM_SMEM>>>(hbh, hbl, wqh, wql, bq, nullptr,
                                                             nullptr, qh, ql, MROWS, DD, DD);
    mmgemm<true, false, true, false><<<gD, 256, GEMM_SMEM>>>(hbh, hbl, wkh, wkl, bk, nullptr,
                                                             nullptr, kh, kl, MROWS, DD, DD);
    mmgemm<true, false, true, false><<<gD, 256, GEMM_SMEM>>>(hbh, hbl, wvh, wvl, bv, nullptr,
                                                             nullptr, vh, vl, MROWS, DD, DD);
    flash_mma<<<dim3(SS / 64, HH, BB), 128, FLASH_SMEM>>>(qh, ql, kh, kl, vh, vl,
                                                          amask, ah, al);
    mmgemm<true, true, false, false><<<gD, 256, GEMM_SMEM>>>(ah, al, woh, wol, bo, x,
                                                             x1, nullptr, nullptr, MROWS, DD, DD);

    // MLP sub-block
    rmsnorm_split<<<MROWS, 256>>>(x1, w_norm2, h2h, h2l);
    mmgemm<false, false, false, false><<<gF, 256, GEMM_SMEM>>>(h2h, h2l, wgh, wgl, nullptr, nullptr,
                                                               gate, nullptr, nullptr, MROWS, FF, DD);
    mmgemm<false, false, true, true><<<gF, 256, GEMM_SMEM>>>(h2h, h2l, wuh, wul, nullptr, gate,
                                                             nullptr, gah, gal, MROWS, FF, DD);
    mmgemm<false, true, false, false><<<gD, 256, GEMM_SMEM>>>(gah, gal, wdh, wdl, nullptr, x1,
                                                              out, nullptr, nullptr, MROWS, DD, FF);
}

// round 8
// speedup vs baseline: 2.9790x; 1.0038x over previous
#include <cuda_runtime.h>
#include <cuda_bf16.h>
#include <cstdint>
#include <cstddef>

// ---------------------------------------------------------------------------
// Problem constants
// ---------------------------------------------------------------------------
#define BB 2
#define SS 2048
#define DD 1024
#define HH 16
#define HDIM 64
#define FF 4096
#define MROWS (BB * SS)          // 4096
#define EPS 1e-6f

// ---------------------------------------------------------------------------
// Device scratch
// ---------------------------------------------------------------------------
__device__ float g_gate[MROWS * FF];
__device__ float g_x1  [MROWS * DD];

__device__ __nv_bfloat16 g_hbh[MROWS * DD],  g_hbl[MROWS * DD];
__device__ __nv_bfloat16 g_qh [MROWS * DD],  g_ql [MROWS * DD];
__device__ __nv_bfloat16 g_kh [MROWS * DD],  g_kl [MROWS * DD];
__device__ __nv_bfloat16 g_vh [MROWS * DD],  g_vl [MROWS * DD];
__device__ __nv_bfloat16 g_ah [MROWS * DD],  g_al [MROWS * DD];
__device__ __nv_bfloat16 g_h2h[MROWS * DD],  g_h2l[MROWS * DD];
__device__ __nv_bfloat16 g_gah[MROWS * FF],  g_gal[MROWS * FF];

__device__ __nv_bfloat16 g_wqh[DD * DD], g_wql[DD * DD];
__device__ __nv_bfloat16 g_wkh[DD * DD], g_wkl[DD * DD];
__device__ __nv_bfloat16 g_wvh[DD * DD], g_wvl[DD * DD];
__device__ __nv_bfloat16 g_woh[DD * DD], g_wol[DD * DD];
__device__ __nv_bfloat16 g_wgh[DD * FF], g_wgl[DD * FF];
__device__ __nv_bfloat16 g_wuh[DD * FF], g_wul[DD * FF];
__device__ __nv_bfloat16 g_wdh[FF * DD], g_wdl[FF * DD];

// ---------------------------------------------------------------------------
// Helpers (sm_80+ ISA only)
// ---------------------------------------------------------------------------
__device__ __forceinline__ uint32_t smem_u32(const void* p) {
    uint32_t a;
    asm("{ .reg .u64 t; cvta.to.shared.u64 t, %1; cvt.u32.u64 %0, t; }"
        : "=r"(a) : "l"(p));
    return a;
}

__device__ __forceinline__ void ldsm4(uint32_t* r, uint32_t addr) {
    asm volatile("ldmatrix.sync.aligned.m8n8.x4.shared.b16 {%0,%1,%2,%3}, [%4];"
                 : "=r"(r[0]), "=r"(r[1]), "=r"(r[2]), "=r"(r[3]) : "r"(addr));
}

__device__ __forceinline__ void ldsm4t(uint32_t* r, uint32_t addr) {
    asm volatile("ldmatrix.sync.aligned.m8n8.x4.trans.shared.b16 {%0,%1,%2,%3}, [%4];"
                 : "=r"(r[0]), "=r"(r[1]), "=r"(r[2]), "=r"(r[3]) : "r"(addr));
}

__device__ __forceinline__ void mma_bf16(float* d, const uint32_t* a,
                                         const uint32_t* b) {
    asm volatile(
        "mma.sync.aligned.m16n8k16.row.col.f32.bf16.bf16.f32 "
        "{%0,%1,%2,%3}, {%4,%5,%6,%7}, {%8,%9}, {%0,%1,%2,%3};"
        : "+f"(d[0]), "+f"(d[1]), "+f"(d[2]), "+f"(d[3])
        : "r"(a[0]), "r"(a[1]), "r"(a[2]), "r"(a[3]), "r"(b[0]), "r"(b[1]));
}

__device__ __forceinline__ uint32_t pk(float x, float y) {
    __nv_bfloat162 h = __floats2bfloat162_rn(x, y);
    return *(uint32_t*)&h;
}

__device__ __forceinline__ float bfv(float x) {
    return __bfloat162float(__float2bfloat16_rn(x));
}

#define CP16(dst, src) \
    asm volatile("cp.async.cg.shared.global [%0], [%1], 16;" \
                 :: "r"(dst), "l"(src) : "memory")
#define CPCOMMIT() asm volatile("cp.async.commit_group;" ::: "memory")

__device__ __forceinline__ void cpwait(int keep) {
    if (keep) asm volatile("cp.async.wait_group 1;" ::: "memory");
    else      asm volatile("cp.async.wait_group 0;" ::: "memory");
}

// ---------------------------------------------------------------------------
// bf16x3 tensor GEMM, 3-stage cp.async pipeline, pre-split inputs.
// C[M,N] = A[M,K] @ B[K,N] (+bias) (+gate-SiLU) (+res); out fp32 or split bf16.
// CTA 128x128, K-chunk 32, 256 threads (8 warps of 64x32).
// ---------------------------------------------------------------------------
#define BKC 32
#define ASTRIDE 80
#define BSTRIDE 272
#define OFF_AH 0
#define OFF_AL 10240
#define OFF_BH 20480
#define OFF_BL 29184
#define BUFSZ  37888
#define GEMM_SMEM (3 * BUFSZ)

template <bool BIAS, bool RES, bool SPLIT, bool SILU>
__global__ __launch_bounds__(256, 2)
void mmgemm(const __nv_bfloat16* __restrict__ Ah, const __nv_bfloat16* __restrict__ Al,
            const __nv_bfloat16* __restrict__ Bh, const __nv_bfloat16* __restrict__ Bl,
            const float* __restrict__ bias, const float* __restrict__ res,
            float* __restrict__ C,
            __nv_bfloat16* __restrict__ Chi, __nv_bfloat16* __restrict__ Clo,
            int M, int N, int K) {
    extern __shared__ char smem[];
    const uint32_t sb = smem_u32(smem);

    const int tid  = threadIdx.x;
    const int lane = tid & 31;
    const int wid  = tid >> 5;
    const int m0   = (wid >> 2) * 64;
    const int n0   = (wid & 3) * 32;
    const int mBase = blockIdx.y * 128;
    const int nBase = blockIdx.x * 128;

    const uint32_t aoff = (uint32_t)((lane & 15) * ASTRIDE + (lane >> 4) * 16);
    const uint32_t boff = (uint32_t)((lane & 15) * BSTRIDE + (lane >> 4) * 16);

    float acc[4][4][4];
#pragma unroll
    for (int i = 0; i < 4; i++)
#pragma unroll
        for (int j = 0; j < 4; j++)
#pragma unroll
            for (int t = 0; t < 4; t++) acc[i][j][t] = 0.f;

    const int nch = K / BKC;

#define ISSUE(c, buf)                                                         \
    do {                                                                      \
        const int k0_ = (c) * BKC;                                            \
        const uint32_t bp = sb + (uint32_t)((buf) * BUFSZ);                   \
        _Pragma("unroll")                                                     \
        for (int i = 0; i < 2; i++) {                                         \
            const int idx = tid + i * 256;                                    \
            const int r = idx >> 2, c16 = idx & 3;                            \
            const size_t so = (size_t)(mBase + r) * K + k0_ + c16 * 8;        \
            const uint32_t d = bp + (uint32_t)(r * ASTRIDE + c16 * 16);       \
            CP16(d + OFF_AH, Ah + so);                                        \
            CP16(d + OFF_AL, Al + so);                                        \
        }                                                                     \
        _Pragma("unroll")                                                     \
        for (int i = 0; i < 2; i++) {                                         \
            const int idx = tid + i * 256;                                    \
            const int kk = idx >> 4, c16 = idx & 15;                          \
            const size_t so = (size_t)(k0_ + kk) * N + nBase + c16 * 8;       \
            const uint32_t d = bp + (uint32_t)(kk * BSTRIDE + c16 * 16);      \
            CP16(d + OFF_BH, Bh + so);                                        \
            CP16(d + OFF_BL, Bl + so);                                        \
        }                                                                     \
        CPCOMMIT();                                                           \
    } while (0)

    ISSUE(0, 0);
    if (nch > 1) ISSUE(1, 1);

    int buf = 0;
    for (int c = 0; c < nch; c++) {
        cpwait(c + 1 < nch);
        __syncthreads();
        if (c + 2 < nch) {
            int nb = buf + 2; if (nb >= 3) nb -= 3;
            ISSUE(c + 2, nb);
        }

        const uint32_t bufb = sb + (uint32_t)(buf * BUFSZ);
        const uint32_t ah = bufb + OFF_AH + (uint32_t)(m0 * ASTRIDE) + aoff;
        const uint32_t al = bufb + OFF_AL + (uint32_t)(m0 * ASTRIDE) + aoff;
        const uint32_t bh = bufb + OFF_BH + (uint32_t)(n0 * 2) + boff;
        const uint32_t bl = bufb + OFF_BL + (uint32_t)(n0 * 2) + boff;

#pragma unroll
        for (int ks = 0; ks < 2; ks++) {
            uint32_t fah[4][4], fbh[2][4];
#pragma unroll
            for (int mi = 0; mi < 4; mi++)
                ldsm4(fah[mi], ah + mi * (16 * ASTRIDE) + ks * 32);
#pragma unroll
            for (int np = 0; np < 2; np++)
                ldsm4t(fbh[np], bh + np * 32 + ks * (16 * BSTRIDE));
#pragma unroll
            for (int mi = 0; mi < 4; mi++)
#pragma unroll
                for (int nj = 0; nj < 4; nj++)
                    mma_bf16(acc[mi][nj], fah[mi], &fbh[nj >> 1][(nj & 1) * 2]);

            uint32_t fbl[2][4];
#pragma unroll
            for (int np = 0; np < 2; np++)
                ldsm4t(fbl[np], bl + np * 32 + ks * (16 * BSTRIDE));
#pragma unroll
            for (int mi = 0; mi < 4; mi++)
#pragma unroll
                for (int nj = 0; nj < 4; nj++)
                    mma_bf16(acc[mi][nj], fah[mi], &fbl[nj >> 1][(nj & 1) * 2]);

            uint32_t fal[4][4];
#pragma unroll
            for (int mi = 0; mi < 4; mi++)
                ldsm4(fal[mi], al + mi * (16 * ASTRIDE) + ks * 32);
#pragma unroll
            for (int mi = 0; mi < 4; mi++)
#pragma unroll
                for (int nj = 0; nj < 4; nj++)
                    mma_bf16(acc[mi][nj], fal[mi], &fbh[nj >> 1][(nj & 1) * 2]);
        }

        if (++buf >= 3) buf = 0;
    }
#undef ISSUE

    const int g  = lane >> 2;
    const int tc = (lane & 3) * 2;
#pragma unroll
    for (int mi = 0; mi < 4; mi++) {
        const int row = mBase + m0 + mi * 16 + g;
#pragma unroll
        for (int nj = 0; nj < 4; nj++) {
            const int col = nBase + n0 + nj * 8 + tc;
            float2 bv = make_float2(0.f, 0.f);
            if (BIAS) bv = *(const float2*)(bias + col);
            float v0 = acc[mi][nj][0] + bv.x;
            float v1 = acc[mi][nj][1] + bv.y;
            float v2 = acc[mi][nj][2] + bv.x;
            float v3 = acc[mi][nj][3] + bv.y;
            if (RES) {
                float2 e0 = *(const float2*)(res + (size_t)row * N + col);
                float2 e1 = *(const float2*)(res + (size_t)(row + 8) * N + col);
                v0 += e0.x; v1 += e0.y; v2 += e1.x; v3 += e1.y;
            }
            if (SILU) {
                float2 g0 = *(const float2*)(res + (size_t)row * N + col);
                float2 g1 = *(const float2*)(res + (size_t)(row + 8) * N + col);
                v0 *= g0.x / (1.f + __expf(-g0.x));
                v1 *= g0.y / (1.f + __expf(-g0.y));
                v2 *= g1.x / (1.f + __expf(-g1.x));
                v3 *= g1.y / (1.f + __expf(-g1.y));
            }
            if (SPLIT) {
                *(uint32_t*)(Chi + (size_t)row * N + col)       = pk(v0, v1);
                *(uint32_t*)(Clo + (size_t)row * N + col)       = pk(v0 - bfv(v0), v1 - bfv(v1));
                *(uint32_t*)(Chi + (size_t)(row + 8) * N + col) = pk(v2, v3);
                *(uint32_t*)(Clo + (size_t)(row + 8) * N + col) = pk(v2 - bfv(v2), v3 - bfv(v3));
            } else {
                *(float2*)(C + (size_t)row * N + col)       = make_float2(v0, v1);
                *(float2*)(C + (size_t)(row + 8) * N + col) = make_float2(v2, v3);
            }
        }
    }
}

// ---------------------------------------------------------------------------
// Tensor-core flash attention: 64q x 64k tiles, HD=64, 128 threads (4 warps).
// Longest-first CTA order (reversed qb) to pack the causal imbalance.
// ---------------------------------------------------------------------------
#define FQ_STRIDE 144
#define F_OFF_QH 0
#define F_OFF_QL 9216
#define F_OFF_ST 18432
#define F_STAGE  36864
#define F_OFF_MK 92160
#define FLASH_SMEM 92672

__global__ __launch_bounds__(128)
void flash_mma(const __nv_bfloat16* __restrict__ Qh, const __nv_bfloat16* __restrict__ Ql,
               const __nv_bfloat16* __restrict__ Kh, const __nv_bfloat16* __restrict__ Kl,
               const __nv_bfloat16* __restrict__ Vh, const __nv_bfloat16* __restrict__ Vl,
               const int* __restrict__ amask,
               __nv_bfloat16* __restrict__ Oh, __nv_bfloat16* __restrict__ Ol) {
    extern __shared__ char smem[];
    const uint32_t sb = smem_u32(smem);

    const int tid  = threadIdx.x;
    const int lane = tid & 31;
    const int wid  = tid >> 5;
    const int qb   = (gridDim.x - 1 - blockIdx.x) * 64;   // longest-first
    const int h    = blockIdx.y;
    const int b    = blockIdx.z;
    const int bS   = b * SS;
    const int hcol = h * HDIM;
    const int nt   = qb / 64 + 1;

#pragma unroll
    for (int i = 0; i < 4; i++) {
        const int idx = tid + i * 128;
        const int r = idx >> 3, c16 = idx & 7;
        const size_t so = (size_t)(bS + qb + r) * DD + hcol + c16 * 8;
        const uint32_t d = sb + (uint32_t)(r * FQ_STRIDE + c16 * 16);
        CP16(d + F_OFF_QH, Qh + so);
        CP16(d + F_OFF_QL, Ql + so);
    }

#define KVISSUE(kt, st)                                                       \
    do {                                                                      \
        const int kb_ = (kt) * 64;                                            \
        const uint32_t stb = sb + F_OFF_ST + (uint32_t)((st) * F_STAGE);      \
        _Pragma("unroll")                                                     \
        for (int i = 0; i < 4; i++) {                                         \
            const int idx = tid + i * 128;                                    \
            const int r = idx >> 3, c16 = idx & 7;                            \
            const size_t so = (size_t)(bS + kb_ + r) * DD + hcol + c16 * 8;   \
            const uint32_t d = stb + (uint32_t)(r * FQ_STRIDE + c16 * 16);    \
            CP16(d + 0,     Kh + so);                                         \
            CP16(d + 9216,  Kl + so);                                         \
            CP16(d + 18432, Vh + so);                                         \
            CP16(d + 27648, Vl + so);                                         \
        }                                                                     \
        if (tid < 16)                                                         \
            CP16(sb + F_OFF_MK + (uint32_t)((st) * 256 + tid * 16),           \
                 amask + bS + kb_ + tid * 4);                                 \
        CPCOMMIT();                                                           \
    } while (0)

    KVISSUE(0, 0);
    if (nt > 1) KVISSUE(1, 1);
    cpwait(nt > 1);
    __syncthreads();

    const int qr0 = wid * 16;
    const uint32_t qaddr = sb + (uint32_t)((qr0 + (lane & 15)) * FQ_STRIDE + (lane >> 4) * 16);
    uint32_t qfh[4][4], qfl[4][4];
#pragma unroll
    for (int kc = 0; kc < 4; kc++) {
        ldsm4(qfh[kc], qaddr + F_OFF_QH + kc * 32);
        ldsm4(qfl[kc], qaddr + F_OFF_QL + kc * 32);
    }

    const int rloc0 = qr0 + (lane >> 2);
    const int tc2   = (lane & 3) * 2;
    const int r0g   = qb + rloc0;
    const int r1g   = r0g + 8;

    float o[8][4];
#pragma unroll
    for (int dt = 0; dt < 8; dt++)
#pragma unroll
        for (int e = 0; e < 4; e++) o[dt][e] = 0.f;
    float m0 = -1e30f, m1 = -1e30f, l0 = 0.f, l1 = 0.f;

    for (int kt = 0; kt < nt; kt++) {
        if (kt > 0) { cpwait(kt + 1 < nt); __syncthreads(); }
        const int kb = kt * 64;
        const uint32_t stb = sb + F_OFF_ST + (uint32_t)((kt & 1) * F_STAGE);
        const uint32_t kaddr = stb + (uint32_t)(((lane & 7) + ((lane >> 4) << 3)) * FQ_STRIDE
                                                + ((lane >> 3) & 1) * 16);
        const uint32_t vaddr = stb + 18432u + (uint32_t)((lane & 15) * FQ_STRIDE + (lane >> 4) * 16);
        const int* smk = (const int*)(smem + F_OFF_MK + (kt & 1) * 256);

        float s[8][4];
#pragma unroll
        for (int jt = 0; jt < 8; jt++)
#pragma unroll
            for (int e = 0; e < 4; e++) s[jt][e] = 0.f;

#pragma unroll
        for (int kc = 0; kc < 4; kc++)
#pragma unroll
            for (int g2 = 0; g2 < 4; g2++) {
                uint32_t kf[4], kfl[4];
                ldsm4(kf,  kaddr + g2 * (16 * FQ_STRIDE) + kc * 32);
                mma_bf16(s[2 * g2],     qfh[kc], kf + 0);
                mma_bf16(s[2 * g2 + 1], qfh[kc], kf + 2);
                ldsm4(kfl, kaddr + 9216 + g2 * (16 * FQ_STRIDE) + kc * 32);
                mma_bf16(s[2 * g2],     qfh[kc], kfl + 0);
                mma_bf16(s[2 * g2 + 1], qfh[kc], kfl + 2);
                mma_bf16(s[2 * g2],     qfl[kc], kf + 0);
                mma_bf16(s[2 * g2 + 1], qfl[kc], kf + 2);
            }

#pragma unroll
        for (int jt = 0; jt < 8; jt++) {
            const int c0 = kb + jt * 8 + tc2;
            const int c1 = c0 + 1;
            const bool k0 = smk[jt * 8 + tc2] != 0;
            const bool k1 = smk[jt * 8 + tc2 + 1] != 0;
            s[jt][0] = (c0 <= r0g && k0) ? s[jt][0] * 0.125f : -1e30f;
            s[jt][1] = (c1 <= r0g && k1) ? s[jt][1] * 0.125f : -1e30f;
            s[jt][2] = (c0 <= r1g && k0) ? s[jt][2] * 0.125f : -1e30f;
            s[jt][3] = (c1 <= r1g && k1) ? s[jt][3] * 0.125f : -1e30f;
        }

        float mx0 = -1e30f, mx1 = -1e30f;
#pragma unroll
        for (int jt = 0; jt < 8; jt++) {
            mx0 = fmaxf(mx0, fmaxf(s[jt][0], s[jt][1]));
            mx1 = fmaxf(mx1, fmaxf(s[jt][2], s[jt][3]));
        }
        mx0 = fmaxf(mx0, __shfl_xor_sync(0xffffffffu, mx0, 1));
        mx0 = fmaxf(mx0, __shfl_xor_sync(0xffffffffu, mx0, 2));
        mx1 = fmaxf(mx1, __shfl_xor_sync(0xffffffffu, mx1, 1));
        mx1 = fmaxf(mx1, __shfl_xor_sync(0xffffffffu, mx1, 2));
        const float mn0 = fmaxf(m0, mx0), mn1 = fmaxf(m1, mx1);
        const float cr0 = __expf(m0 - mn0), cr1 = __expf(m1 - mn1);
        float sum0 = 0.f, sum1 = 0.f;
#pragma unroll
        for (int jt = 0; jt < 8; jt++) {
            s[jt][0] = __expf(s[jt][0] - mn0);
            s[jt][1] = __expf(s[jt][1] - mn0);
            s[jt][2] = __expf(s[jt][2] - mn1);
            s[jt][3] = __expf(s[jt][3] - mn1);
            sum0 += s[jt][0] + s[jt][1];
            sum1 += s[jt][2] + s[jt][3];
        }
        sum0 += __shfl_xor_sync(0xffffffffu, sum0, 1);
        sum0 += __shfl_xor_sync(0xffffffffu, sum0, 2);
        sum1 += __shfl_xor_sync(0xffffffffu, sum1, 1);
        sum1 += __shfl_xor_sync(0xffffffffu, sum1, 2);
        l0 = l0 * cr0 + sum0;
        l1 = l1 * cr1 + sum1;
        m0 = mn0; m1 = mn1;
#pragma unroll
        for (int dt = 0; dt < 8; dt++) {
            o[dt][0] *= cr0; o[dt][1] *= cr0;
            o[dt][2] *= cr1; o[dt][3] *= cr1;
        }

#pragma unroll
        for (int kc2 = 0; kc2 < 4; kc2++) {
            uint32_t ph[4], pl[4];
            {
                const float a0 = s[2 * kc2][0],     a1 = s[2 * kc2][1];
                const float a2 = s[2 * kc2][2],     a3 = s[2 * kc2][3];
                const float a4 = s[2 * kc2 + 1][0], a5 = s[2 * kc2 + 1][1];
                const float a6 = s[2 * kc2 + 1][2], a7 = s[2 * kc2 + 1][3];
                ph[0] = pk(a0, a1); pl[0] = pk(a0 - bfv(a0), a1 - bfv(a1));
                ph[1] = pk(a2, a3); pl[1] = pk(a2 - bfv(a2), a3 - bfv(a3));
                ph[2] = pk(a4, a5); pl[2] = pk(a4 - bfv(a4), a5 - bfv(a5));
                ph[3] = pk(a6, a7); pl[3] = pk(a6 - bfv(a6), a7 - bfv(a7));
            }
#pragma unroll
            for (int g2 = 0; g2 < 4; g2++) {
                uint32_t vf[4], vfl[4];
                ldsm4t(vf,  vaddr + kc2 * (16 * FQ_STRIDE) + g2 * 32);
                mma_bf16(o[2 * g2],     ph, vf + 0);
                mma_bf16(o[2 * g2 + 1], ph, vf + 2);
                ldsm4t(vfl, vaddr + 9216 + kc2 * (16 * FQ_STRIDE) + g2 * 32);
                mma_bf16(o[2 * g2],     ph, vfl + 0);
                mma_bf16(o[2 * g2 + 1], ph, vfl + 2);
                mma_bf16(o[2 * g2],     pl, vf + 0);
                mma_bf16(o[2 * g2 + 1], pl, vf + 2);
            }
        }

        __syncthreads();
        if (kt + 2 < nt) KVISSUE(kt + 2, kt & 1);
    }
#undef KVISSUE

    const float inv0 = 1.f / l0, inv1 = 1.f / l1;
    const size_t e0 = (size_t)(bS + r0g) * DD + hcol;
    const size_t e1 = (size_t)(bS + r1g) * DD + hcol;
#pragma unroll
    for (int dt = 0; dt < 8; dt++) {
        const int col = dt * 8 + tc2;
        float v0 = o[dt][0] * inv0, v1 = o[dt][1] * inv0;
        float v2 = o[dt][2] * inv1, v3 = o[dt][3] * inv1;
        *(uint32_t*)(Oh + e0 + col) = pk(v0, v1);
        *(uint32_t*)(Ol + e0 + col) = pk(v0 - bfv(v0), v1 - bfv(v1));
        *(uint32_t*)(Oh + e1 + col) = pk(v2, v3);
        *(uint32_t*)(Ol + e1 + col) = pk(v2 - bfv(v2), v3 - bfv(v3));
    }
}

// ---------------------------------------------------------------------------
// RMSNorm with split bf16 output
// ---------------------------------------------------------------------------
__global__ __launch_bounds__(256) void rmsnorm_split(const float* __restrict__ x,
                                                     const float* __restrict__ w,
                                                     __nv_bfloat16* __restrict__ ohi,
                                                     __nv_bfloat16* __restrict__ olo) {
    __shared__ float red[8];
    const int row = blockIdx.x;
    const int tid = threadIdx.x;
    float4 v = ((const float4*)(x + (size_t)row * DD))[tid];
    float ss = v.x * v.x + v.y * v.y + v.z * v.z + v.w * v.w;
#pragma unroll
    for (int off = 16; off > 0; off >>= 1)
        ss += __shfl_xor_sync(0xffffffffu, ss, off);
    if ((tid & 31) == 0) red[tid >> 5] = ss;
    __syncthreads();
    float tot = 0.f;
#pragma unroll
    for (int i = 0; i < 8; i++) tot += red[i];
    const float inv = rsqrtf(tot * (1.0f / DD) + EPS);
    const float4 wv = ((const float4*)w)[tid];
    float o0 = wv.x * (v.x * inv), o1 = wv.y * (v.y * inv);
    float o2 = wv.z * (v.z * inv), o3 = wv.w * (v.w * inv);
    const size_t e = (size_t)row * DD + tid * 4;
    *(uint2*)(ohi + e) = make_uint2(pk(o0, o1), pk(o2, o3));
    *(uint2*)(olo + e) = make_uint2(pk(o0 - bfv(o0), o1 - bfv(o1)),
                                    pk(o2 - bfv(o2), o3 - bfv(o3)));
}

// ---------------------------------------------------------------------------
// fp32 -> bf16 hi/lo split (weights): 4 float4 per thread, uint2 stores
// ---------------------------------------------------------------------------
__global__ __launch_bounds__(256) void split_k(const float* __restrict__ s,
                                               __nv_bfloat16* __restrict__ hi,
                                               __nv_bfloat16* __restrict__ lo) {
    const size_t base = (size_t)blockIdx.x * 1024 + threadIdx.x;
#pragma unroll
    for (int i = 0; i < 4; i++) {
        const size_t idx = base + i * 256;
        float4 v = ((const float4*)s)[idx];
        const size_t e = idx * 4;
        *(uint2*)(hi + e) = make_uint2(pk(v.x, v.y), pk(v.z, v.w));
        *(uint2*)(lo + e) = make_uint2(pk(v.x - bfv(v.x), v.y - bfv(v.y)),
                                       pk(v.z - bfv(v.z), v.w - bfv(v.w)));
    }
}

// ---------------------------------------------------------------------------
// Launch
// ---------------------------------------------------------------------------
extern "C" void kernel_launch(void* const* d_in, const int* in_sizes, int n_in,
                              void* d_out, int out_size) {
    const float* x       = (const float*)d_in[0];
    const int*   amask   = (const int*)  d_in[1];
    const float* w_norm1 = (const float*)d_in[2];
    const float* wq      = (const float*)d_in[3];
    const float* bq      = (const float*)d_in[4];
    const float* wk      = (const float*)d_in[5];
    const float* bk      = (const float*)d_in[6];
    const float* wv      = (const float*)d_in[7];
    const float* bv      = (const float*)d_in[8];
    const float* wo      = (const float*)d_in[9];
    const float* bo      = (const float*)d_in[10];
    const float* w_norm2 = (const float*)d_in[11];
    const float* w_gate  = (const float*)d_in[12];
    const float* w_up    = (const float*)d_in[13];
    const float* w_down  = (const float*)d_in[14];
    float* out = (float*)d_out;

    float *gate, *x1;
    cudaGetSymbolAddress((void**)&gate, g_gate);
    cudaGetSymbolAddress((void**)&x1,   g_x1);

    __nv_bfloat16 *hbh, *hbl, *qh, *ql, *kh, *kl, *vh, *vl, *ah, *al, *h2h, *h2l,
                  *gah, *gal, *wqh, *wql, *wkh, *wkl, *wvh, *wvl, *woh, *wol,
                  *wgh, *wgl, *wuh, *wul, *wdh, *wdl;
    cudaGetSymbolAddress((void**)&hbh, g_hbh);  cudaGetSymbolAddress((void**)&hbl, g_hbl);
    cudaGetSymbolAddress((void**)&qh,  g_qh);   cudaGetSymbolAddress((void**)&ql,  g_ql);
    cudaGetSymbolAddress((void**)&kh,  g_kh);   cudaGetSymbolAddress((void**)&kl,  g_kl);
    cudaGetSymbolAddress((void**)&vh,  g_vh);   cudaGetSymbolAddress((void**)&vl,  g_vl);
    cudaGetSymbolAddress((void**)&ah,  g_ah);   cudaGetSymbolAddress((void**)&al,  g_al);
    cudaGetSymbolAddress((void**)&h2h, g_h2h);  cudaGetSymbolAddress((void**)&h2l, g_h2l);
    cudaGetSymbolAddress((void**)&gah, g_gah);  cudaGetSymbolAddress((void**)&gal, g_gal);
    cudaGetSymbolAddress((void**)&wqh, g_wqh);  cudaGetSymbolAddress((void**)&wql, g_wql);
    cudaGetSymbolAddress((void**)&wkh, g_wkh);  cudaGetSymbolAddress((void**)&wkl, g_wkl);
    cudaGetSymbolAddress((void**)&wvh, g_wvh);  cudaGetSymbolAddress((void**)&wvl, g_wvl);
    cudaGetSymbolAddress((void**)&woh, g_woh);  cudaGetSymbolAddress((void**)&wol, g_wol);
    cudaGetSymbolAddress((void**)&wgh, g_wgh);  cudaGetSymbolAddress((void**)&wgl, g_wgl);
    cudaGetSymbolAddress((void**)&wuh, g_wuh);  cudaGetSymbolAddress((void**)&wul, g_wul);
    cudaGetSymbolAddress((void**)&wdh, g_wdh);  cudaGetSymbolAddress((void**)&wdl, g_wdl);

    cudaFuncSetAttribute(mmgemm<true,  false, true,  false>, cudaFuncAttributeMaxDynamicSharedMemorySize, GEMM_SMEM);
    cudaFuncSetAttribute(mmgemm<true,  true,  false, false>, cudaFuncAttributeMaxDynamicSharedMemorySize, GEMM_SMEM);
    cudaFuncSetAttribute(mmgemm<false, false, false, false>, cudaFuncAttributeMaxDynamicSharedMemorySize, GEMM_SMEM);
    cudaFuncSetAttribute(mmgemm<false, false, true,  true >, cudaFuncAttributeMaxDynamicSharedMemorySize, GEMM_SMEM);
    cudaFuncSetAttribute(mmgemm<false, true,  false, false>, cudaFuncAttributeMaxDynamicSharedMemorySize, GEMM_SMEM);
    cudaFuncSetAttribute(flash_mma, cudaFuncAttributeMaxDynamicSharedMemorySize, FLASH_SMEM);

    // weight splits
    split_k<<<DD * DD / 4096, 256>>>(wq, wqh, wql);
    split_k<<<DD * DD / 4096, 256>>>(wk, wkh, wkl);
    split_k<<<DD * DD / 4096, 256>>>(wv, wvh, wvl);
    split_k<<<DD * DD / 4096, 256>>>(wo, woh, wol);
    split_k<<<DD * FF / 4096, 256>>>(w_gate, wgh, wgl);
    split_k<<<DD * FF / 4096, 256>>>(w_up,   wuh, wul);
    split_k<<<FF * DD / 4096, 256>>>(w_down, wdh, wdl);

    const dim3 gD(DD / 128, MROWS / 128);   // (8, 32)
    const dim3 gF(FF / 128, MROWS / 128);   // (32, 32)

    // attention sub-block
    rmsnorm_split<<<MROWS, 256>>>(x, w_norm1, hbh, hbl);
    mmgemm<true, false, true, false><<<gD, 256, GEMM_SMEM>>>(hbh, hbl, wqh, wql, bq, nullptr,
                                                             nullptr, qh, ql, MROWS, DD, DD);
    mmgemm<true, false, true, false><<<gD, 256, GEMM_SMEM>>>(hbh, hbl, wkh, wkl, bk, nullptr,
                                                             nullptr, kh, kl, MROWS, DD, DD);
    mmgemm<true, false, true, false><<<gD, 256, GEMM_SMEM>>>(hbh, hbl, wvh, wvl, bv, nullptr,
                                                             nullptr, vh, vl, MROWS, DD, DD);
    flash_mma<<<dim3(SS / 64, HH, BB), 128, FLASH_SMEM>>>(qh, ql, kh, kl, vh, vl,
                                                          amask, ah, al);
    mmgemm<true, true, false, false><<<gD, 256, GEMM_SMEM>>>(ah, al, woh, wol, bo, x,
                                                             x1, nullptr, nullptr, MROWS, DD, DD);

    // MLP sub-block
    rmsnorm_split<<<MROWS, 256>>>(x1, w_norm2, h2h, h2l);
    mmgemm<false, false, false, false><<<gF, 256, GEMM_SMEM>>>(h2h, h2l, wgh, wgl, nullptr, nullptr,
                                                               gate, nullptr, nullptr, MROWS, FF, DD);
    mmgemm<false, false, true, true><<<gF, 256, GEMM_SMEM>>>(h2h, h2l, wuh, wul, nullptr, gate,
                                                             nullptr, gah, gal, MROWS, FF, DD);
    mmgemm<false, true, false, false><<<gD, 256, GEMM_SMEM>>>(gah, gal, wdh, wdl, nullptr, x1,
                                                              out, nullptr, nullptr, MROWS, DD, FF);
}

// round 9
// speedup vs baseline: 3.0060x; 1.0091x over previous
#include <cuda_runtime.h>
#include <cuda_bf16.h>
#include <cstdint>
#include <cstddef>

// ---------------------------------------------------------------------------
// Problem constants
// ---------------------------------------------------------------------------
#define BB 2
#define SS 2048
#define DD 1024
#define HH 16
#define HDIM 64
#define FF 4096
#define MROWS (BB * SS)          // 4096
#define NQKV 3072
#define EPS 1e-6f

// ---------------------------------------------------------------------------
// Device scratch
// ---------------------------------------------------------------------------
__device__ float g_gate[MROWS * FF];
__device__ float g_x1  [MROWS * DD];
__device__ float g_bqkv[NQKV];

__device__ __nv_bfloat16 g_hbh [MROWS * DD],   g_hbl [MROWS * DD];
__device__ __nv_bfloat16 g_qkvh[MROWS * NQKV], g_qkvl[MROWS * NQKV];
__device__ __nv_bfloat16 g_ah  [MROWS * DD],   g_al  [MROWS * DD];
__device__ __nv_bfloat16 g_h2h [MROWS * DD],   g_h2l [MROWS * DD];
__device__ __nv_bfloat16 g_gah [MROWS * FF],   g_gal [MROWS * FF];

__device__ __nv_bfloat16 g_wqkvh[DD * NQKV], g_wqkvl[DD * NQKV];
__device__ __nv_bfloat16 g_woh[DD * DD], g_wol[DD * DD];
__device__ __nv_bfloat16 g_wgh[DD * FF], g_wgl[DD * FF];
__device__ __nv_bfloat16 g_wuh[DD * FF], g_wul[DD * FF];
__device__ __nv_bfloat16 g_wdh[FF * DD], g_wdl[FF * DD];

// ---------------------------------------------------------------------------
// Helpers (sm_80+ ISA only)
// ---------------------------------------------------------------------------
__device__ __forceinline__ uint32_t smem_u32(const void* p) {
    uint32_t a;
    asm("{ .reg .u64 t; cvta.to.shared.u64 t, %1; cvt.u32.u64 %0, t; }"
        : "=r"(a) : "l"(p));
    return a;
}

__device__ __forceinline__ void ldsm4(uint32_t* r, uint32_t addr) {
    asm volatile("ldmatrix.sync.aligned.m8n8.x4.shared.b16 {%0,%1,%2,%3}, [%4];"
                 : "=r"(r[0]), "=r"(r[1]), "=r"(r[2]), "=r"(r[3]) : "r"(addr));
}

__device__ __forceinline__ void ldsm4t(uint32_t* r, uint32_t addr) {
    asm volatile("ldmatrix.sync.aligned.m8n8.x4.trans.shared.b16 {%0,%1,%2,%3}, [%4];"
                 : "=r"(r[0]), "=r"(r[1]), "=r"(r[2]), "=r"(r[3]) : "r"(addr));
}

__device__ __forceinline__ void mma_bf16(float* d, const uint32_t* a,
                                         const uint32_t* b) {
    asm volatile(
        "mma.sync.aligned.m16n8k16.row.col.f32.bf16.bf16.f32 "
        "{%0,%1,%2,%3}, {%4,%5,%6,%7}, {%8,%9}, {%0,%1,%2,%3};"
        : "+f"(d[0]), "+f"(d[1]), "+f"(d[2]), "+f"(d[3])
        : "r"(a[0]), "r"(a[1]), "r"(a[2]), "r"(a[3]), "r"(b[0]), "r"(b[1]));
}

__device__ __forceinline__ uint32_t pk(float x, float y) {
    __nv_bfloat162 h = __floats2bfloat162_rn(x, y);
    return *(uint32_t*)&h;
}

__device__ __forceinline__ float bfv(float x) {
    return __bfloat162float(__float2bfloat16_rn(x));
}

#define CP16(dst, src) \
    asm volatile("cp.async.cg.shared.global [%0], [%1], 16;" \
                 :: "r"(dst), "l"(src) : "memory")
#define CPCOMMIT() asm volatile("cp.async.commit_group;" ::: "memory")

__device__ __forceinline__ void cpwait(int keep) {
    if (keep) asm volatile("cp.async.wait_group 1;" ::: "memory");
    else      asm volatile("cp.async.wait_group 0;" ::: "memory");
}

// ---------------------------------------------------------------------------
// bf16x3 tensor GEMM, 3-stage cp.async pipeline, pre-split inputs.
// ---------------------------------------------------------------------------
#define BKC 32
#define ASTRIDE 80
#define BSTRIDE 272
#define OFF_AH 0
#define OFF_AL 10240
#define OFF_BH 20480
#define OFF_BL 29184
#define BUFSZ  37888
#define GEMM_SMEM (3 * BUFSZ)

template <bool BIAS, bool RES, bool SPLIT, bool SILU>
__global__ __launch_bounds__(256, 2)
void mmgemm(const __nv_bfloat16* __restrict__ Ah, const __nv_bfloat16* __restrict__ Al,
            const __nv_bfloat16* __restrict__ Bh, const __nv_bfloat16* __restrict__ Bl,
            const float* __restrict__ bias, const float* __restrict__ res,
            float* __restrict__ C,
            __nv_bfloat16* __restrict__ Chi, __nv_bfloat16* __restrict__ Clo,
            int M, int N, int K) {
    extern __shared__ char smem[];
    const uint32_t sb = smem_u32(smem);

    const int tid  = threadIdx.x;
    const int lane = tid & 31;
    const int wid  = tid >> 5;
    const int m0   = (wid >> 2) * 64;
    const int n0   = (wid & 3) * 32;
    const int mBase = blockIdx.y * 128;
    const int nBase = blockIdx.x * 128;

    const uint32_t aoff = (uint32_t)((lane & 15) * ASTRIDE + (lane >> 4) * 16);
    const uint32_t boff = (uint32_t)((lane & 15) * BSTRIDE + (lane >> 4) * 16);

    float acc[4][4][4];
#pragma unroll
    for (int i = 0; i < 4; i++)
#pragma unroll
        for (int j = 0; j < 4; j++)
#pragma unroll
            for (int t = 0; t < 4; t++) acc[i][j][t] = 0.f;

    const int nch = K / BKC;

#define ISSUE(c, buf)                                                         \
    do {                                                                      \
        const int k0_ = (c) * BKC;                                            \
        const uint32_t bp = sb + (uint32_t)((buf) * BUFSZ);                   \
        _Pragma("unroll")                                                     \
        for (int i = 0; i < 2; i++) {                                         \
            const int idx = tid + i * 256;                                    \
            const int r = idx >> 2, c16 = idx & 3;                            \
            const size_t so = (size_t)(mBase + r) * K + k0_ + c16 * 8;        \
            const uint32_t d = bp + (uint32_t)(r * ASTRIDE + c16 * 16);       \
            CP16(d + OFF_AH, Ah + so);                                        \
            CP16(d + OFF_AL, Al + so);                                        \
        }                                                                     \
        _Pragma("unroll")                                                     \
        for (int i = 0; i < 2; i++) {                                         \
            const int idx = tid + i * 256;                                    \
            const int kk = idx >> 4, c16 = idx & 15;                          \
            const size_t so = (size_t)(k0_ + kk) * N + nBase + c16 * 8;       \
            const uint32_t d = bp + (uint32_t)(kk * BSTRIDE + c16 * 16);      \
            CP16(d + OFF_BH, Bh + so);                                        \
            CP16(d + OFF_BL, Bl + so);                                        \
        }                                                                     \
        CPCOMMIT();                                                           \
    } while (0)

    ISSUE(0, 0);
    if (nch > 1) ISSUE(1, 1);

    int buf = 0;
    for (int c = 0; c < nch; c++) {
        cpwait(c + 1 < nch);
        __syncthreads();
        if (c + 2 < nch) {
            int nb = buf + 2; if (nb >= 3) nb -= 3;
            ISSUE(c + 2, nb);
        }

        const uint32_t bufb = sb + (uint32_t)(buf * BUFSZ);
        const uint32_t ah = bufb + OFF_AH + (uint32_t)(m0 * ASTRIDE) + aoff;
        const uint32_t al = bufb + OFF_AL + (uint32_t)(m0 * ASTRIDE) + aoff;
        const uint32_t bh = bufb + OFF_BH + (uint32_t)(n0 * 2) + boff;
        const uint32_t bl = bufb + OFF_BL + (uint32_t)(n0 * 2) + boff;

#pragma unroll
        for (int ks = 0; ks < 2; ks++) {
            uint32_t fah[4][4], fbh[2][4];
#pragma unroll
            for (int mi = 0; mi < 4; mi++)
                ldsm4(fah[mi], ah + mi * (16 * ASTRIDE) + ks * 32);
#pragma unroll
            for (int np = 0; np < 2; np++)
                ldsm4t(fbh[np], bh + np * 32 + ks * (16 * BSTRIDE));
#pragma unroll
            for (int mi = 0; mi < 4; mi++)
#pragma unroll
                for (int nj = 0; nj < 4; nj++)
                    mma_bf16(acc[mi][nj], fah[mi], &fbh[nj >> 1][(nj & 1) * 2]);

            uint32_t fbl[2][4];
#pragma unroll
            for (int np = 0; np < 2; np++)
                ldsm4t(fbl[np], bl + np * 32 + ks * (16 * BSTRIDE));
#pragma unroll
            for (int mi = 0; mi < 4; mi++)
#pragma unroll
                for (int nj = 0; nj < 4; nj++)
                    mma_bf16(acc[mi][nj], fah[mi], &fbl[nj >> 1][(nj & 1) * 2]);

            uint32_t fal[4][4];
#pragma unroll
            for (int mi = 0; mi < 4; mi++)
                ldsm4(fal[mi], al + mi * (16 * ASTRIDE) + ks * 32);
#pragma unroll
            for (int mi = 0; mi < 4; mi++)
#pragma unroll
                for (int nj = 0; nj < 4; nj++)
                    mma_bf16(acc[mi][nj], fal[mi], &fbh[nj >> 1][(nj & 1) * 2]);
        }

        if (++buf >= 3) buf = 0;
    }
#undef ISSUE

    const int g  = lane >> 2;
    const int tc = (lane & 3) * 2;
#pragma unroll
    for (int mi = 0; mi < 4; mi++) {
        const int row = mBase + m0 + mi * 16 + g;
#pragma unroll
        for (int nj = 0; nj < 4; nj++) {
            const int col = nBase + n0 + nj * 8 + tc;
            float2 bv = make_float2(0.f, 0.f);
            if (BIAS) bv = *(const float2*)(bias + col);
            float v0 = acc[mi][nj][0] + bv.x;
            float v1 = acc[mi][nj][1] + bv.y;
            float v2 = acc[mi][nj][2] + bv.x;
            float v3 = acc[mi][nj][3] + bv.y;
            if (RES) {
                float2 e0 = *(const float2*)(res + (size_t)row * N + col);
                float2 e1 = *(const float2*)(res + (size_t)(row + 8) * N + col);
                v0 += e0.x; v1 += e0.y; v2 += e1.x; v3 += e1.y;
            }
            if (SILU) {
                float2 g0 = *(const float2*)(res + (size_t)row * N + col);
                float2 g1 = *(const float2*)(res + (size_t)(row + 8) * N + col);
                v0 *= g0.x / (1.f + __expf(-g0.x));
                v1 *= g0.y / (1.f + __expf(-g0.y));
                v2 *= g1.x / (1.f + __expf(-g1.x));
                v3 *= g1.y / (1.f + __expf(-g1.y));
            }
            if (SPLIT) {
                *(uint32_t*)(Chi + (size_t)row * N + col)       = pk(v0, v1);
                *(uint32_t*)(Clo + (size_t)row * N + col)       = pk(v0 - bfv(v0), v1 - bfv(v1));
                *(uint32_t*)(Chi + (size_t)(row + 8) * N + col) = pk(v2, v3);
                *(uint32_t*)(Clo + (size_t)(row + 8) * N + col) = pk(v2 - bfv(v2), v3 - bfv(v3));
            } else {
                *(float2*)(C + (size_t)row * N + col)       = make_float2(v0, v1);
                *(float2*)(C + (size_t)(row + 8) * N + col) = make_float2(v2, v3);
            }
        }
    }
}

// ---------------------------------------------------------------------------
// Tensor-core flash attention: 64q x 64k tiles, HD=64, 128 threads.
// Q/K/V live in the fused [M, 3072] QKV buffer (row stride NQKV).
// ---------------------------------------------------------------------------
#define FQ_STRIDE 144
#define F_OFF_QH 0
#define F_OFF_QL 9216
#define F_OFF_ST 18432
#define F_STAGE  36864
#define F_OFF_MK 92160
#define FLASH_SMEM 92672

__global__ __launch_bounds__(128)
void flash_mma(const __nv_bfloat16* __restrict__ QKVh,
               const __nv_bfloat16* __restrict__ QKVl,
               const int* __restrict__ amask,
               __nv_bfloat16* __restrict__ Oh, __nv_bfloat16* __restrict__ Ol) {
    extern __shared__ char smem[];
    const uint32_t sb = smem_u32(smem);

    const int tid  = threadIdx.x;
    const int lane = tid & 31;
    const int wid  = tid >> 5;
    const int qb   = (gridDim.x - 1 - blockIdx.x) * 64;   // longest-first
    const int h    = blockIdx.y;
    const int b    = blockIdx.z;
    const int bS   = b * SS;
    const int hcol = h * HDIM;
    const int nt   = qb / 64 + 1;

    const __nv_bfloat16* Qh = QKVh;
    const __nv_bfloat16* Ql = QKVl;
    const __nv_bfloat16* Kh = QKVh + DD;
    const __nv_bfloat16* Kl = QKVl + DD;
    const __nv_bfloat16* Vh = QKVh + 2 * DD;
    const __nv_bfloat16* Vl = QKVl + 2 * DD;

#pragma unroll
    for (int i = 0; i < 4; i++) {
        const int idx = tid + i * 128;
        const int r = idx >> 3, c16 = idx & 7;
        const size_t so = (size_t)(bS + qb + r) * NQKV + hcol + c16 * 8;
        const uint32_t d = sb + (uint32_t)(r * FQ_STRIDE + c16 * 16);
        CP16(d + F_OFF_QH, Qh + so);
        CP16(d + F_OFF_QL, Ql + so);
    }

#define KVISSUE(kt, st)                                                       \
    do {                                                                      \
        const int kb_ = (kt) * 64;                                            \
        const uint32_t stb = sb + F_OFF_ST + (uint32_t)((st) * F_STAGE);      \
        _Pragma("unroll")                                                     \
        for (int i = 0; i < 4; i++) {                                         \
            const int idx = tid + i * 128;                                    \
            const int r = idx >> 3, c16 = idx & 7;                            \
            const size_t so = (size_t)(bS + kb_ + r) * NQKV + hcol + c16 * 8; \
            const uint32_t d = stb + (uint32_t)(r * FQ_STRIDE + c16 * 16);    \
            CP16(d + 0,     Kh + so);                                         \
            CP16(d + 9216,  Kl + so);                                         \
            CP16(d + 18432, Vh + so);                                         \
            CP16(d + 27648, Vl + so);                                         \
        }                                                                     \
        if (tid < 16)                                                         \
            CP16(sb + F_OFF_MK + (uint32_t)((st) * 256 + tid * 16),           \
                 amask + bS + kb_ + tid * 4);                                 \
        CPCOMMIT();                                                           \
    } while (0)

    KVISSUE(0, 0);
    if (nt > 1) KVISSUE(1, 1);
    cpwait(nt > 1);
    __syncthreads();

    const int qr0 = wid * 16;
    const uint32_t qaddr = sb + (uint32_t)((qr0 + (lane & 15)) * FQ_STRIDE + (lane >> 4) * 16);
    uint32_t qfh[4][4], qfl[4][4];
#pragma unroll
    for (int kc = 0; kc < 4; kc++) {
        ldsm4(qfh[kc], qaddr + F_OFF_QH + kc * 32);
        ldsm4(qfl[kc], qaddr + F_OFF_QL + kc * 32);
    }

    const int rloc0 = qr0 + (lane >> 2);
    const int tc2   = (lane & 3) * 2;
    const int r0g   = qb + rloc0;
    const int r1g   = r0g + 8;

    float o[8][4];
#pragma unroll
    for (int dt = 0; dt < 8; dt++)
#pragma unroll
        for (int e = 0; e < 4; e++) o[dt][e] = 0.f;
    float m0 = -1e30f, m1 = -1e30f, l0 = 0.f, l1 = 0.f;

    for (int kt = 0; kt < nt; kt++) {
        if (kt > 0) { cpwait(kt + 1 < nt); __syncthreads(); }
        const int kb = kt * 64;
        const uint32_t stb = sb + F_OFF_ST + (uint32_t)((kt & 1) * F_STAGE);
        const uint32_t kaddr = stb + (uint32_t)(((lane & 7) + ((lane >> 4) << 3)) * FQ_STRIDE
                                                + ((lane >> 3) & 1) * 16);
        const uint32_t vaddr = stb + 18432u + (uint32_t)((lane & 15) * FQ_STRIDE + (lane >> 4) * 16);
        const int* smk = (const int*)(smem + F_OFF_MK + (kt & 1) * 256);

        float s[8][4];
#pragma unroll
        for (int jt = 0; jt < 8; jt++)
#pragma unroll
            for (int e = 0; e < 4; e++) s[jt][e] = 0.f;

#pragma unroll
        for (int kc = 0; kc < 4; kc++)
#pragma unroll
            for (int g2 = 0; g2 < 4; g2++) {
                uint32_t kf[4], kfl[4];
                ldsm4(kf,  kaddr + g2 * (16 * FQ_STRIDE) + kc * 32);
                mma_bf16(s[2 * g2],     qfh[kc], kf + 0);
                mma_bf16(s[2 * g2 + 1], qfh[kc], kf + 2);
                ldsm4(kfl, kaddr + 9216 + g2 * (16 * FQ_STRIDE) + kc * 32);
                mma_bf16(s[2 * g2],     qfh[kc], kfl + 0);
                mma_bf16(s[2 * g2 + 1], qfh[kc], kfl + 2);
                mma_bf16(s[2 * g2],     qfl[kc], kf + 0);
                mma_bf16(s[2 * g2 + 1], qfl[kc], kf + 2);
            }

#pragma unroll
        for (int jt = 0; jt < 8; jt++) {
            const int c0 = kb + jt * 8 + tc2;
            const int c1 = c0 + 1;
            const bool k0 = smk[jt * 8 + tc2] != 0;
            const bool k1 = smk[jt * 8 + tc2 + 1] != 0;
            s[jt][0] = (c0 <= r0g && k0) ? s[jt][0] * 0.125f : -1e30f;
            s[jt][1] = (c1 <= r0g && k1) ? s[jt][1] * 0.125f : -1e30f;
            s[jt][2] = (c0 <= r1g && k0) ? s[jt][2] * 0.125f : -1e30f;
            s[jt][3] = (c1 <= r1g && k1) ? s[jt][3] * 0.125f : -1e30f;
        }

        float mx0 = -1e30f, mx1 = -1e30f;
#pragma unroll
        for (int jt = 0; jt < 8; jt++) {
            mx0 = fmaxf(mx0, fmaxf(s[jt][0], s[jt][1]));
            mx1 = fmaxf(mx1, fmaxf(s[jt][2], s[jt][3]));
        }
        mx0 = fmaxf(mx0, __shfl_xor_sync(0xffffffffu, mx0, 1));
        mx0 = fmaxf(mx0, __shfl_xor_sync(0xffffffffu, mx0, 2));
        mx1 = fmaxf(mx1, __shfl_xor_sync(0xffffffffu, mx1, 1));
        mx1 = fmaxf(mx1, __shfl_xor_sync(0xffffffffu, mx1, 2));
        const float mn0 = fmaxf(m0, mx0), mn1 = fmaxf(m1, mx1);
        const float cr0 = __expf(m0 - mn0), cr1 = __expf(m1 - mn1);
        float sum0 = 0.f, sum1 = 0.f;
#pragma unroll
        for (int jt = 0; jt < 8; jt++) {
            s[jt][0] = __expf(s[jt][0] - mn0);
            s[jt][1] = __expf(s[jt][1] - mn0);
            s[jt][2] = __expf(s[jt][2] - mn1);
            s[jt][3] = __expf(s[jt][3] - mn1);
            sum0 += s[jt][0] + s[jt][1];
            sum1 += s[jt][2] + s[jt][3];
        }
        sum0 += __shfl_xor_sync(0xffffffffu, sum0, 1);
        sum0 += __shfl_xor_sync(0xffffffffu, sum0, 2);
        sum1 += __shfl_xor_sync(0xffffffffu, sum1, 1);
        sum1 += __shfl_xor_sync(0xffffffffu, sum1, 2);
        l0 = l0 * cr0 + sum0;
        l1 = l1 * cr1 + sum1;
        m0 = mn0; m1 = mn1;
#pragma unroll
        for (int dt = 0; dt < 8; dt++) {
            o[dt][0] *= cr0; o[dt][1] *= cr0;
            o[dt][2] *= cr1; o[dt][3] *= cr1;
        }

#pragma unroll
        for (int kc2 = 0; kc2 < 4; kc2++) {
            uint32_t ph[4], pl[4];
            {
                const float a0 = s[2 * kc2][0],     a1 = s[2 * kc2][1];
                const float a2 = s[2 * kc2][2],     a3 = s[2 * kc2][3];
                const float a4 = s[2 * kc2 + 1][0], a5 = s[2 * kc2 + 1][1];
                const float a6 = s[2 * kc2 + 1][2], a7 = s[2 * kc2 + 1][3];
                ph[0] = pk(a0, a1); pl[0] = pk(a0 - bfv(a0), a1 - bfv(a1));
                ph[1] = pk(a2, a3); pl[1] = pk(a2 - bfv(a2), a3 - bfv(a3));
                ph[2] = pk(a4, a5); pl[2] = pk(a4 - bfv(a4), a5 - bfv(a5));
                ph[3] = pk(a6, a7); pl[3] = pk(a6 - bfv(a6), a7 - bfv(a7));
            }
#pragma unroll
            for (int g2 = 0; g2 < 4; g2++) {
                uint32_t vf[4], vfl[4];
                ldsm4t(vf,  vaddr + kc2 * (16 * FQ_STRIDE) + g2 * 32);
                mma_bf16(o[2 * g2],     ph, vf + 0);
                mma_bf16(o[2 * g2 + 1], ph, vf + 2);
                ldsm4t(vfl, vaddr + 9216 + kc2 * (16 * FQ_STRIDE) + g2 * 32);
                mma_bf16(o[2 * g2],     ph, vfl + 0);
                mma_bf16(o[2 * g2 + 1], ph, vfl + 2);
                mma_bf16(o[2 * g2],     pl, vf + 0);
                mma_bf16(o[2 * g2 + 1], pl, vf + 2);
            }
        }

        __syncthreads();
        if (kt + 2 < nt) KVISSUE(kt + 2, kt & 1);
    }
#undef KVISSUE

    const float inv0 = 1.f / l0, inv1 = 1.f / l1;
    const size_t e0 = (size_t)(bS + r0g) * DD + hcol;
    const size_t e1 = (size_t)(bS + r1g) * DD + hcol;
#pragma unroll
    for (int dt = 0; dt < 8; dt++) {
        const int col = dt * 8 + tc2;
        float v0 = o[dt][0] * inv0, v1 = o[dt][1] * inv0;
        float v2 = o[dt][2] * inv1, v3 = o[dt][3] * inv1;
        *(uint32_t*)(Oh + e0 + col) = pk(v0, v1);
        *(uint32_t*)(Ol + e0 + col) = pk(v0 - bfv(v0), v1 - bfv(v1));
        *(uint32_t*)(Oh + e1 + col) = pk(v2, v3);
        *(uint32_t*)(Ol + e1 + col) = pk(v2 - bfv(v2), v3 - bfv(v3));
    }
}

// ---------------------------------------------------------------------------
// RMSNorm with split bf16 output
// ---------------------------------------------------------------------------
__global__ __launch_bounds__(256) void rmsnorm_split(const float* __restrict__ x,
                                                     const float* __restrict__ w,
                                                     __nv_bfloat16* __restrict__ ohi,
                                                     __nv_bfloat16* __restrict__ olo) {
    __shared__ float red[8];
    const int row = blockIdx.x;
    const int tid = threadIdx.x;
    float4 v = ((const float4*)(x + (size_t)row * DD))[tid];
    float ss = v.x * v.x + v.y * v.y + v.z * v.z + v.w * v.w;
#pragma unroll
    for (int off = 16; off > 0; off >>= 1)
        ss += __shfl_xor_sync(0xffffffffu, ss, off);
    if ((tid & 31) == 0) red[tid >> 5] = ss;
    __syncthreads();
    float tot = 0.f;
#pragma unroll
    for (int i = 0; i < 8; i++) tot += red[i];
    const float inv = rsqrtf(tot * (1.0f / DD) + EPS);
    const float4 wv = ((const float4*)w)[tid];
    float o0 = wv.x * (v.x * inv), o1 = wv.y * (v.y * inv);
    float o2 = wv.z * (v.z * inv), o3 = wv.w * (v.w * inv);
    const size_t e = (size_t)row * DD + tid * 4;
    *(uint2*)(ohi + e) = make_uint2(pk(o0, o1), pk(o2, o3));
    *(uint2*)(olo + e) = make_uint2(pk(o0 - bfv(o0), o1 - bfv(o1)),
                                    pk(o2 - bfv(o2), o3 - bfv(o3)));
}

// ---------------------------------------------------------------------------
// fp32 -> bf16 hi/lo split with destination column remap:
// src [K, srcN] -> dst [K, dstN] at column offset dstOff.
// ---------------------------------------------------------------------------
__global__ __launch_bounds__(256) void split_seg(const float* __restrict__ s,
                                                 __nv_bfloat16* __restrict__ hi,
                                                 __nv_bfloat16* __restrict__ lo,
                                                 int srcN, int dstN, int dstOff) {
    const size_t base4 = (size_t)blockIdx.x * 1024 + threadIdx.x;
#pragma unroll
    for (int i = 0; i < 4; i++) {
        const size_t idx4 = base4 + i * 256;          // float4 index
        float4 v = ((const float4*)s)[idx4];
        const size_t el = idx4 * 4;
        const size_t k  = el / srcN;
        const size_t n  = el - k * srcN;
        const size_t e  = k * dstN + dstOff + n;
        *(uint2*)(hi + e) = make_uint2(pk(v.x, v.y), pk(v.z, v.w));
        *(uint2*)(lo + e) = make_uint2(pk(v.x - bfv(v.x), v.y - bfv(v.y)),
                                       pk(v.z - bfv(v.z), v.w - bfv(v.w)));
    }
}

// concat biases bq|bk|bv -> g_bqkv[3072]
__global__ __launch_bounds__(256) void concat_bias(const float* __restrict__ bq,
                                                   const float* __restrict__ bk,
                                                   const float* __restrict__ bv,
                                                   float* __restrict__ dst) {
    const int i = blockIdx.x * 256 + threadIdx.x;
    if (i >= NQKV) return;
    float v = (i < DD) ? bq[i] : (i < 2 * DD) ? bk[i - DD] : bv[i - 2 * DD];
    dst[i] = v;
}

// ---------------------------------------------------------------------------
// Launch (stream-forked: side stream does MLP/O weight splits during attention)
// ---------------------------------------------------------------------------
extern "C" void kernel_launch(void* const* d_in, const int* in_sizes, int n_in,
                              void* d_out, int out_size) {
    const float* x       = (const float*)d_in[0];
    const int*   amask   = (const int*)  d_in[1];
    const float* w_norm1 = (const float*)d_in[2];
    const float* wq      = (const float*)d_in[3];
    const float* bq      = (const float*)d_in[4];
    const float* wk      = (const float*)d_in[5];
    const float* bk      = (const float*)d_in[6];
    const float* wv      = (const float*)d_in[7];
    const float* bv      = (const float*)d_in[8];
    const float* wo      = (const float*)d_in[9];
    const float* bo      = (const float*)d_in[10];
    const float* w_norm2 = (const float*)d_in[11];
    const float* w_gate  = (const float*)d_in[12];
    const float* w_up    = (const float*)d_in[13];
    const float* w_down  = (const float*)d_in[14];
    float* out = (float*)d_out;

    float *gate, *x1, *bqkv;
    cudaGetSymbolAddress((void**)&gate, g_gate);
    cudaGetSymbolAddress((void**)&x1,   g_x1);
    cudaGetSymbolAddress((void**)&bqkv, g_bqkv);

    __nv_bfloat16 *hbh, *hbl, *qkvh, *qkvl, *ah, *al, *h2h, *h2l, *gah, *gal,
                  *wqkvh, *wqkvl, *woh, *wol, *wgh, *wgl, *wuh, *wul, *wdh, *wdl;
    cudaGetSymbolAddress((void**)&hbh,   g_hbh);   cudaGetSymbolAddress((void**)&hbl,   g_hbl);
    cudaGetSymbolAddress((void**)&qkvh,  g_qkvh);  cudaGetSymbolAddress((void**)&qkvl,  g_qkvl);
    cudaGetSymbolAddress((void**)&ah,    g_ah);    cudaGetSymbolAddress((void**)&al,    g_al);
    cudaGetSymbolAddress((void**)&h2h,   g_h2h);   cudaGetSymbolAddress((void**)&h2l,   g_h2l);
    cudaGetSymbolAddress((void**)&gah,   g_gah);   cudaGetSymbolAddress((void**)&gal,   g_gal);
    cudaGetSymbolAddress((void**)&wqkvh, g_wqkvh); cudaGetSymbolAddress((void**)&wqkvl, g_wqkvl);
    cudaGetSymbolAddress((void**)&woh,   g_woh);   cudaGetSymbolAddress((void**)&wol,   g_wol);
    cudaGetSymbolAddress((void**)&wgh,   g_wgh);   cudaGetSymbolAddress((void**)&wgl,   g_wgl);
    cudaGetSymbolAddress((void**)&wuh,   g_wuh);   cudaGetSymbolAddress((void**)&wul,   g_wul);
    cudaGetSymbolAddress((void**)&wdh,   g_wdh);   cudaGetSymbolAddress((void**)&wdl,   g_wdl);

    cudaFuncSetAttribute(mmgemm<true,  false, true,  false>, cudaFuncAttributeMaxDynamicSharedMemorySize, GEMM_SMEM);
    cudaFuncSetAttribute(mmgemm<true,  true,  false, false>, cudaFuncAttributeMaxDynamicSharedMemorySize, GEMM_SMEM);
    cudaFuncSetAttribute(mmgemm<false, false, false, false>, cudaFuncAttributeMaxDynamicSharedMemorySize, GEMM_SMEM);
    cudaFuncSetAttribute(mmgemm<false, false, true,  true >, cudaFuncAttributeMaxDynamicSharedMemorySize, GEMM_SMEM);
    cudaFuncSetAttribute(mmgemm<false, true,  false, false>, cudaFuncAttributeMaxDynamicSharedMemorySize, GEMM_SMEM);
    cudaFuncSetAttribute(flash_mma, cudaFuncAttributeMaxDynamicSharedMemorySize, FLASH_SMEM);

    // Side stream for weight splits not needed until the O-proj / MLP phase.
    // (Created fresh per call; leaked intentionally — host-side resources only,
    //  kernel_launch is invoked O(1) times per run.)
    cudaStream_t s2;
    cudaStreamCreate(&s2);
    cudaEvent_t evFork, evJoin;
    cudaEventCreateWithFlags(&evFork, cudaEventDisableTiming);
    cudaEventCreateWithFlags(&evJoin, cudaEventDisableTiming);

    // fork at graph root
    cudaEventRecord(evFork, 0);
    cudaStreamWaitEvent(s2, evFork, 0);

    // side stream: wo / wg / wu / wd splits (consumed at O-proj and later)
    split_seg<<<DD * DD / 4096, 256, 0, s2>>>(wo, woh, wol, DD, DD, 0);
    split_seg<<<DD * FF / 4096, 256, 0, s2>>>(w_gate, wgh, wgl, FF, FF, 0);
    split_seg<<<DD * FF / 4096, 256, 0, s2>>>(w_up,   wuh, wul, FF, FF, 0);
    split_seg<<<FF * DD / 4096, 256, 0, s2>>>(w_down, wdh, wdl, DD, DD, 0);
    cudaEventRecord(evJoin, s2);

    // main stream: QKV weight splits + bias + rmsnorm (all needed immediately)
    split_seg<<<DD * DD / 4096, 256>>>(wq, wqkvh, wqkvl, DD, NQKV, 0);
    split_seg<<<DD * DD / 4096, 256>>>(wk, wqkvh, wqkvl, DD, NQKV, DD);
    split_seg<<<DD * DD / 4096, 256>>>(wv, wqkvh, wqkvl, DD, NQKV, 2 * DD);
    concat_bias<<<(NQKV + 255) / 256, 256>>>(bq, bk, bv, bqkv);
    rmsnorm_split<<<MROWS, 256>>>(x, w_norm1, hbh, hbl);

    const dim3 gQKV(NQKV / 128, MROWS / 128);  // (24, 32)
    const dim3 gD(DD / 128, MROWS / 128);      // (8, 32)
    const dim3 gF(FF / 128, MROWS / 128);      // (32, 32)

    // fused QKV GEMM + flash attention (side-stream splits overlap these)
    mmgemm<true, false, true, false><<<gQKV, 256, GEMM_SMEM>>>(hbh, hbl, wqkvh, wqkvl, bqkv,
                                                               nullptr, nullptr, qkvh, qkvl,
                                                               MROWS, NQKV, DD);
    flash_mma<<<dim3(SS / 64, HH, BB), 128, FLASH_SMEM>>>(qkvh, qkvl, amask, ah, al);

    // join: O-proj is the first consumer of side-stream outputs
    cudaStreamWaitEvent(0, evJoin, 0);
    mmgemm<true, true, false, false><<<gD, 256, GEMM_SMEM>>>(ah, al, woh, wol, bo, x,
                                                             x1, nullptr, nullptr, MROWS, DD, DD);

    // MLP sub-block
    rmsnorm_split<<<MROWS, 256>>>(x1, w_norm2, h2h, h2l);
    mmgemm<false, false, false, false><<<gF, 256, GEMM_SMEM>>>(h2h, h2l, wgh, wgl, nullptr, nullptr,
                                                               gate, nullptr, nullptr, MROWS, FF, DD);
    mmgemm<false, false, true, true><<<gF, 256, GEMM_SMEM>>>(h2h, h2l, wuh, wul, nullptr, gate,
                                                             nullptr, gah, gal, MROWS, FF, DD);
    mmgemm<false, true, false, false><<<gD, 256, GEMM_SMEM>>>(gah, gal, wdh, wdl, nullptr, x1,
                                                              out, nullptr, nullptr, MROWS, DD, FF);
}

// round 10
// speedup vs baseline: 4.0313x; 1.3411x over previous
#include <cuda_runtime.h>
#include <cuda_fp16.h>
#include <cstdint>
#include <cstddef>

// ---------------------------------------------------------------------------
// Problem constants
// ---------------------------------------------------------------------------
#define BB 2
#define SS 2048
#define DD 1024
#define HH 16
#define HDIM 64
#define FF 4096
#define MROWS (BB * SS)          // 4096
#define NQKV 3072
#define EPS 1e-6f

// ---------------------------------------------------------------------------
// Device scratch (activations: fp16 hi/lo; weights: single fp16)
// ---------------------------------------------------------------------------
__device__ float g_gate[MROWS * FF];
__device__ float g_x1  [MROWS * DD];
__device__ float g_bqkv[NQKV];

__device__ __half g_hbh [MROWS * DD],   g_hbl [MROWS * DD];
__device__ __half g_qkvh[MROWS * NQKV], g_qkvl[MROWS * NQKV];
__device__ __half g_ah  [MROWS * DD],   g_al  [MROWS * DD];
__device__ __half g_h2h [MROWS * DD],   g_h2l [MROWS * DD];
__device__ __half g_gah [MROWS * FF],   g_gal [MROWS * FF];

__device__ __half g_wqkvh[DD * NQKV];
__device__ __half g_woh[DD * DD];
__device__ __half g_wgh[DD * FF];
__device__ __half g_wuh[DD * FF];
__device__ __half g_wdh[FF * DD];

// ---------------------------------------------------------------------------
// Helpers (sm_80+ ISA only)
// ---------------------------------------------------------------------------
__device__ __forceinline__ uint32_t smem_u32(const void* p) {
    uint32_t a;
    asm("{ .reg .u64 t; cvta.to.shared.u64 t, %1; cvt.u32.u64 %0, t; }"
        : "=r"(a) : "l"(p));
    return a;
}

__device__ __forceinline__ void ldsm4(uint32_t* r, uint32_t addr) {
    asm volatile("ldmatrix.sync.aligned.m8n8.x4.shared.b16 {%0,%1,%2,%3}, [%4];"
                 : "=r"(r[0]), "=r"(r[1]), "=r"(r[2]), "=r"(r[3]) : "r"(addr));
}

__device__ __forceinline__ void ldsm4t(uint32_t* r, uint32_t addr) {
    asm volatile("ldmatrix.sync.aligned.m8n8.x4.trans.shared.b16 {%0,%1,%2,%3}, [%4];"
                 : "=r"(r[0]), "=r"(r[1]), "=r"(r[2]), "=r"(r[3]) : "r"(addr));
}

__device__ __forceinline__ void mma_f16(float* d, const uint32_t* a,
                                        const uint32_t* b) {
    asm volatile(
        "mma.sync.aligned.m16n8k16.row.col.f32.f16.f16.f32 "
        "{%0,%1,%2,%3}, {%4,%5,%6,%7}, {%8,%9}, {%0,%1,%2,%3};"
        : "+f"(d[0]), "+f"(d[1]), "+f"(d[2]), "+f"(d[3])
        : "r"(a[0]), "r"(a[1]), "r"(a[2]), "r"(a[3]), "r"(b[0]), "r"(b[1]));
}

__device__ __forceinline__ uint32_t pkh(float x, float y) {
    __half2 h = __floats2half2_rn(x, y);
    return *(uint32_t*)&h;
}

__device__ __forceinline__ float hfv(float x) {
    return __half2float(__float2half_rn(x));
}

#define CP16(dst, src) \
    asm volatile("cp.async.cg.shared.global [%0], [%1], 16;" \
                 :: "r"(dst), "l"(src) : "memory")
#define CPCOMMIT() asm volatile("cp.async.commit_group;" ::: "memory")

__device__ __forceinline__ void cpwait(int keep) {
    if (keep) asm volatile("cp.async.wait_group 1;" ::: "memory");
    else      asm volatile("cp.async.wait_group 0;" ::: "memory");
}

// ---------------------------------------------------------------------------
// fp16 asymmetric 2-pass tensor GEMM: C = (Ah + Al) @ Bh
// A split fp16 hi/lo (exact to 2^-22); B single fp16 (2^-11 rounding).
// CTA 128x128, K-chunk 32, 256 threads (8 warps of 64x32), 3-stage cp.async.
// ---------------------------------------------------------------------------
#define BKC 32
#define ASTRIDE 80
#define BSTRIDE 272
#define OFF_AH 0
#define OFF_AL 10240
#define OFF_BH 20480
#define BUFSZ  29184
#define GEMM_SMEM (3 * BUFSZ)

template <bool BIAS, bool RES, bool SPLIT, bool SILU>
__global__ __launch_bounds__(256, 2)
void mmgemm(const __half* __restrict__ Ah, const __half* __restrict__ Al,
            const __half* __restrict__ Bh,
            const float* __restrict__ bias, const float* __restrict__ res,
            float* __restrict__ C,
            __half* __restrict__ Chi, __half* __restrict__ Clo,
            int M, int N, int K) {
    extern __shared__ char smem[];
    const uint32_t sb = smem_u32(smem);

    const int tid  = threadIdx.x;
    const int lane = tid & 31;
    const int wid  = tid >> 5;
    const int m0   = (wid >> 2) * 64;
    const int n0   = (wid & 3) * 32;
    const int mBase = blockIdx.y * 128;
    const int nBase = blockIdx.x * 128;

    const uint32_t aoff = (uint32_t)((lane & 15) * ASTRIDE + (lane >> 4) * 16);
    const uint32_t boff = (uint32_t)((lane & 15) * BSTRIDE + (lane >> 4) * 16);

    float acc[4][4][4];
#pragma unroll
    for (int i = 0; i < 4; i++)
#pragma unroll
        for (int j = 0; j < 4; j++)
#pragma unroll
            for (int t = 0; t < 4; t++) acc[i][j][t] = 0.f;

    const int nch = K / BKC;

#define ISSUE(c, buf)                                                         \
    do {                                                                      \
        const int k0_ = (c) * BKC;                                            \
        const uint32_t bp = sb + (uint32_t)((buf) * BUFSZ);                   \
        _Pragma("unroll")                                                     \
        for (int i = 0; i < 2; i++) {                                         \
            const int idx = tid + i * 256;                                    \
            const int r = idx >> 2, c16 = idx & 3;                            \
            const size_t so = (size_t)(mBase + r) * K + k0_ + c16 * 8;        \
            const uint32_t d = bp + (uint32_t)(r * ASTRIDE + c16 * 16);       \
            CP16(d + OFF_AH, Ah + so);                                        \
            CP16(d + OFF_AL, Al + so);                                        \
        }                                                                     \
        _Pragma("unroll")                                                     \
        for (int i = 0; i < 2; i++) {                                         \
            const int idx = tid + i * 256;                                    \
            const int kk = idx >> 4, c16 = idx & 15;                          \
            const size_t so = (size_t)(k0_ + kk) * N + nBase + c16 * 8;       \
            const uint32_t d = bp + (uint32_t)(kk * BSTRIDE + c16 * 16);      \
            CP16(d + OFF_BH, Bh + so);                                        \
        }                                                                     \
        CPCOMMIT();                                                           \
    } while (0)

    ISSUE(0, 0);
    if (nch > 1) ISSUE(1, 1);

    int buf = 0;
    for (int c = 0; c < nch; c++) {
        cpwait(c + 1 < nch);
        __syncthreads();
        if (c + 2 < nch) {
            int nb = buf + 2; if (nb >= 3) nb -= 3;
            ISSUE(c + 2, nb);
        }

        const uint32_t bufb = sb + (uint32_t)(buf * BUFSZ);
        const uint32_t ah = bufb + OFF_AH + (uint32_t)(m0 * ASTRIDE) + aoff;
        const uint32_t al = bufb + OFF_AL + (uint32_t)(m0 * ASTRIDE) + aoff;
        const uint32_t bh = bufb + OFF_BH + (uint32_t)(n0 * 2) + boff;

#pragma unroll
        for (int ks = 0; ks < 2; ks++) {
            uint32_t fah[4][4], fbh[2][4];
#pragma unroll
            for (int mi = 0; mi < 4; mi++)
                ldsm4(fah[mi], ah + mi * (16 * ASTRIDE) + ks * 32);
#pragma unroll
            for (int np = 0; np < 2; np++)
                ldsm4t(fbh[np], bh + np * 32 + ks * (16 * BSTRIDE));
#pragma unroll
            for (int mi = 0; mi < 4; mi++)
#pragma unroll
                for (int nj = 0; nj < 4; nj++)
                    mma_f16(acc[mi][nj], fah[mi], &fbh[nj >> 1][(nj & 1) * 2]);

            uint32_t fal[4][4];
#pragma unroll
            for (int mi = 0; mi < 4; mi++)
                ldsm4(fal[mi], al + mi * (16 * ASTRIDE) + ks * 32);
#pragma unroll
            for (int mi = 0; mi < 4; mi++)
#pragma unroll
                for (int nj = 0; nj < 4; nj++)
                    mma_f16(acc[mi][nj], fal[mi], &fbh[nj >> 1][(nj & 1) * 2]);
        }

        if (++buf >= 3) buf = 0;
    }
#undef ISSUE

    const int g  = lane >> 2;
    const int tc = (lane & 3) * 2;
#pragma unroll
    for (int mi = 0; mi < 4; mi++) {
        const int row = mBase + m0 + mi * 16 + g;
#pragma unroll
        for (int nj = 0; nj < 4; nj++) {
            const int col = nBase + n0 + nj * 8 + tc;
            float2 bv = make_float2(0.f, 0.f);
            if (BIAS) bv = *(const float2*)(bias + col);
            float v0 = acc[mi][nj][0] + bv.x;
            float v1 = acc[mi][nj][1] + bv.y;
            float v2 = acc[mi][nj][2] + bv.x;
            float v3 = acc[mi][nj][3] + bv.y;
            if (RES) {
                float2 e0 = *(const float2*)(res + (size_t)row * N + col);
                float2 e1 = *(const float2*)(res + (size_t)(row + 8) * N + col);
                v0 += e0.x; v1 += e0.y; v2 += e1.x; v3 += e1.y;
            }
            if (SILU) {
                float2 g0 = *(const float2*)(res + (size_t)row * N + col);
                float2 g1 = *(const float2*)(res + (size_t)(row + 8) * N + col);
                v0 *= g0.x / (1.f + __expf(-g0.x));
                v1 *= g0.y / (1.f + __expf(-g0.y));
                v2 *= g1.x / (1.f + __expf(-g1.x));
                v3 *= g1.y / (1.f + __expf(-g1.y));
            }
            if (SPLIT) {
                *(uint32_t*)(Chi + (size_t)row * N + col)       = pkh(v0, v1);
                *(uint32_t*)(Clo + (size_t)row * N + col)       = pkh(v0 - hfv(v0), v1 - hfv(v1));
                *(uint32_t*)(Chi + (size_t)(row + 8) * N + col) = pkh(v2, v3);
                *(uint32_t*)(Clo + (size_t)(row + 8) * N + col) = pkh(v2 - hfv(v2), v3 - hfv(v3));
            } else {
                *(float2*)(C + (size_t)row * N + col)       = make_float2(v0, v1);
                *(float2*)(C + (size_t)(row + 8) * N + col) = make_float2(v2, v3);
            }
        }
    }
}

// ---------------------------------------------------------------------------
// fp16 flash attention: Q split hi/lo, K/V single fp16 (2-pass QK^T and PV).
// 64q x 64k tiles, HD=64, 128 threads, fused QKV buffer (row stride 3072).
// ---------------------------------------------------------------------------
#define FQ_STRIDE 144
#define F_OFF_QH 0
#define F_OFF_QL 9216
#define F_OFF_ST 18432
#define F_STAGE  18432          // K (9216) + V (9216)
#define F_OFF_MK 55296          // 2 x 256B mask
#define FLASH_SMEM 55808

__global__ __launch_bounds__(128)
void flash_mma(const __half* __restrict__ QKVh,
               const __half* __restrict__ QKVl,
               const int* __restrict__ amask,
               __half* __restrict__ Oh, __half* __restrict__ Ol) {
    extern __shared__ char smem[];
    const uint32_t sb = smem_u32(smem);

    const int tid  = threadIdx.x;
    const int lane = tid & 31;
    const int wid  = tid >> 5;
    const int qb   = (gridDim.x - 1 - blockIdx.x) * 64;   // longest-first
    const int h    = blockIdx.y;
    const int b    = blockIdx.z;
    const int bS   = b * SS;
    const int hcol = h * HDIM;
    const int nt   = qb / 64 + 1;

    const __half* Qh = QKVh;
    const __half* Ql = QKVl;
    const __half* Kh = QKVh + DD;
    const __half* Vh = QKVh + 2 * DD;

#pragma unroll
    for (int i = 0; i < 4; i++) {
        const int idx = tid + i * 128;
        const int r = idx >> 3, c16 = idx & 7;
        const size_t so = (size_t)(bS + qb + r) * NQKV + hcol + c16 * 8;
        const uint32_t d = sb + (uint32_t)(r * FQ_STRIDE + c16 * 16);
        CP16(d + F_OFF_QH, Qh + so);
        CP16(d + F_OFF_QL, Ql + so);
    }

#define KVISSUE(kt, st)                                                       \
    do {                                                                      \
        const int kb_ = (kt) * 64;                                            \
        const uint32_t stb = sb + F_OFF_ST + (uint32_t)((st) * F_STAGE);      \
        _Pragma("unroll")                                                     \
        for (int i = 0; i < 4; i++) {                                         \
            const int idx = tid + i * 128;                                    \
            const int r = idx >> 3, c16 = idx & 7;                            \
            const size_t so = (size_t)(bS + kb_ + r) * NQKV + hcol + c16 * 8; \
            const uint32_t d = stb + (uint32_t)(r * FQ_STRIDE + c16 * 16);    \
            CP16(d + 0,    Kh + so);                                          \
            CP16(d + 9216, Vh + so);                                          \
        }                                                                     \
        if (tid < 16)                                                         \
            CP16(sb + F_OFF_MK + (uint32_t)((st) * 256 + tid * 16),           \
                 amask + bS + kb_ + tid * 4);                                 \
        CPCOMMIT();                                                           \
    } while (0)

    KVISSUE(0, 0);
    if (nt > 1) KVISSUE(1, 1);
    cpwait(nt > 1);
    __syncthreads();

    const int qr0 = wid * 16;
    const uint32_t qaddr = sb + (uint32_t)((qr0 + (lane & 15)) * FQ_STRIDE + (lane >> 4) * 16);
    uint32_t qfh[4][4], qfl[4][4];
#pragma unroll
    for (int kc = 0; kc < 4; kc++) {
        ldsm4(qfh[kc], qaddr + F_OFF_QH + kc * 32);
        ldsm4(qfl[kc], qaddr + F_OFF_QL + kc * 32);
    }

    const int rloc0 = qr0 + (lane >> 2);
    const int tc2   = (lane & 3) * 2;
    const int r0g   = qb + rloc0;
    const int r1g   = r0g + 8;

    float o[8][4];
#pragma unroll
    for (int dt = 0; dt < 8; dt++)
#pragma unroll
        for (int e = 0; e < 4; e++) o[dt][e] = 0.f;
    float m0 = -1e30f, m1 = -1e30f, l0 = 0.f, l1 = 0.f;

    for (int kt = 0; kt < nt; kt++) {
        if (kt > 0) { cpwait(kt + 1 < nt); __syncthreads(); }
        const int kb = kt * 64;
        const uint32_t stb = sb + F_OFF_ST + (uint32_t)((kt & 1) * F_STAGE);
        const uint32_t kaddr = stb + (uint32_t)(((lane & 7) + ((lane >> 4) << 3)) * FQ_STRIDE
                                                + ((lane >> 3) & 1) * 16);
        const uint32_t vaddr = stb + 9216u + (uint32_t)((lane & 15) * FQ_STRIDE + (lane >> 4) * 16);
        const int* smk = (const int*)(smem + F_OFF_MK + (kt & 1) * 256);

        float s[8][4];
#pragma unroll
        for (int jt = 0; jt < 8; jt++)
#pragma unroll
            for (int e = 0; e < 4; e++) s[jt][e] = 0.f;

#pragma unroll
        for (int kc = 0; kc < 4; kc++)
#pragma unroll
            for (int g2 = 0; g2 < 4; g2++) {
                uint32_t kf[4];
                ldsm4(kf, kaddr + g2 * (16 * FQ_STRIDE) + kc * 32);
                mma_f16(s[2 * g2],     qfh[kc], kf + 0);
                mma_f16(s[2 * g2 + 1], qfh[kc], kf + 2);
                mma_f16(s[2 * g2],     qfl[kc], kf + 0);
                mma_f16(s[2 * g2 + 1], qfl[kc], kf + 2);
            }

#pragma unroll
        for (int jt = 0; jt < 8; jt++) {
            const int c0 = kb + jt * 8 + tc2;
            const int c1 = c0 + 1;
            const bool k0 = smk[jt * 8 + tc2] != 0;
            const bool k1 = smk[jt * 8 + tc2 + 1] != 0;
            s[jt][0] = (c0 <= r0g && k0) ? s[jt][0] * 0.125f : -1e30f;
            s[jt][1] = (c1 <= r0g && k1) ? s[jt][1] * 0.125f : -1e30f;
            s[jt][2] = (c0 <= r1g && k0) ? s[jt][2] * 0.125f : -1e30f;
            s[jt][3] = (c1 <= r1g && k1) ? s[jt][3] * 0.125f : -1e30f;
        }

        float mx0 = -1e30f, mx1 = -1e30f;
#pragma unroll
        for (int jt = 0; jt < 8; jt++) {
            mx0 = fmaxf(mx0, fmaxf(s[jt][0], s[jt][1]));
            mx1 = fmaxf(mx1, fmaxf(s[jt][2], s[jt][3]));
        }
        mx0 = fmaxf(mx0, __shfl_xor_sync(0xffffffffu, mx0, 1));
        mx0 = fmaxf(mx0, __shfl_xor_sync(0xffffffffu, mx0, 2));
        mx1 = fmaxf(mx1, __shfl_xor_sync(0xffffffffu, mx1, 1));
        mx1 = fmaxf(mx1, __shfl_xor_sync(0xffffffffu, mx1, 2));
        const float mn0 = fmaxf(m0, mx0), mn1 = fmaxf(m1, mx1);
        const float cr0 = __expf(m0 - mn0), cr1 = __expf(m1 - mn1);
        float sum0 = 0.f, sum1 = 0.f;
#pragma unroll
        for (int jt = 0; jt < 8; jt++) {
            s[jt][0] = __expf(s[jt][0] - mn0);
            s[jt][1] = __expf(s[jt][1] - mn0);
            s[jt][2] = __expf(s[jt][2] - mn1);
            s[jt][3] = __expf(s[jt][3] - mn1);
            sum0 += s[jt][0] + s[jt][1];
            sum1 += s[jt][2] + s[jt][3];
        }
        sum0 += __shfl_xor_sync(0xffffffffu, sum0, 1);
        sum0 += __shfl_xor_sync(0xffffffffu, sum0, 2);
        sum1 += __shfl_xor_sync(0xffffffffu, sum1, 1);
        sum1 += __shfl_xor_sync(0xffffffffu, sum1, 2);
        l0 = l0 * cr0 + sum0;
        l1 = l1 * cr1 + sum1;
        m0 = mn0; m1 = mn1;
#pragma unroll
        for (int dt = 0; dt < 8; dt++) {
            o[dt][0] *= cr0; o[dt][1] *= cr0;
            o[dt][2] *= cr1; o[dt][3] *= cr1;
        }

#pragma unroll
        for (int kc2 = 0; kc2 < 4; kc2++) {
            uint32_t ph[4], pl[4];
            {
                const float a0 = s[2 * kc2][0],     a1 = s[2 * kc2][1];
                const float a2 = s[2 * kc2][2],     a3 = s[2 * kc2][3];
                const float a4 = s[2 * kc2 + 1][0], a5 = s[2 * kc2 + 1][1];
                const float a6 = s[2 * kc2 + 1][2], a7 = s[2 * kc2 + 1][3];
                ph[0] = pkh(a0, a1); pl[0] = pkh(a0 - hfv(a0), a1 - hfv(a1));
                ph[1] = pkh(a2, a3); pl[1] = pkh(a2 - hfv(a2), a3 - hfv(a3));
                ph[2] = pkh(a4, a5); pl[2] = pkh(a4 - hfv(a4), a5 - hfv(a5));
                ph[3] = pkh(a6, a7); pl[3] = pkh(a6 - hfv(a6), a7 - hfv(a7));
            }
#pragma unroll
            for (int g2 = 0; g2 < 4; g2++) {
                uint32_t vf[4];
                ldsm4t(vf, vaddr + kc2 * (16 * FQ_STRIDE) + g2 * 32);
                mma_f16(o[2 * g2],     ph, vf + 0);
                mma_f16(o[2 * g2 + 1], ph, vf + 2);
                mma_f16(o[2 * g2],     pl, vf + 0);
                mma_f16(o[2 * g2 + 1], pl, vf + 2);
            }
        }

        __syncthreads();
        if (kt + 2 < nt) KVISSUE(kt + 2, kt & 1);
    }
#undef KVISSUE

    const float inv0 = 1.f / l0, inv1 = 1.f / l1;
    const size_t e0 = (size_t)(bS + r0g) * DD + hcol;
    const size_t e1 = (size_t)(bS + r1g) * DD + hcol;
#pragma unroll
    for (int dt = 0; dt < 8; dt++) {
        const int col = dt * 8 + tc2;
        float v0 = o[dt][0] * inv0, v1 = o[dt][1] * inv0;
        float v2 = o[dt][2] * inv1, v3 = o[dt][3] * inv1;
        *(uint32_t*)(Oh + e0 + col) = pkh(v0, v1);
        *(uint32_t*)(Ol + e0 + col) = pkh(v0 - hfv(v0), v1 - hfv(v1));
        *(uint32_t*)(Oh + e1 + col) = pkh(v2, v3);
        *(uint32_t*)(Ol + e1 + col) = pkh(v2 - hfv(v2), v3 - hfv(v3));
    }
}

// ---------------------------------------------------------------------------
// RMSNorm with fp16 hi/lo output
// ---------------------------------------------------------------------------
__global__ __launch_bounds__(256) void rmsnorm_split(const float* __restrict__ x,
                                                     const float* __restrict__ w,
                                                     __half* __restrict__ ohi,
                                                     __half* __restrict__ olo) {
    __shared__ float red[8];
    const int row = blockIdx.x;
    const int tid = threadIdx.x;
    float4 v = ((const float4*)(x + (size_t)row * DD))[tid];
    float ss = v.x * v.x + v.y * v.y + v.z * v.z + v.w * v.w;
#pragma unroll
    for (int off = 16; off > 0; off >>= 1)
        ss += __shfl_xor_sync(0xffffffffu, ss, off);
    if ((tid & 31) == 0) red[tid >> 5] = ss;
    __syncthreads();
    float tot = 0.f;
#pragma unroll
    for (int i = 0; i < 8; i++) tot += red[i];
    const float inv = rsqrtf(tot * (1.0f / DD) + EPS);
    const float4 wv = ((const float4*)w)[tid];
    float o0 = wv.x * (v.x * inv), o1 = wv.y * (v.y * inv);
    float o2 = wv.z * (v.z * inv), o3 = wv.w * (v.w * inv);
    const size_t e = (size_t)row * DD + tid * 4;
    *(uint2*)(ohi + e) = make_uint2(pkh(o0, o1), pkh(o2, o3));
    *(uint2*)(olo + e) = make_uint2(pkh(o0 - hfv(o0), o1 - hfv(o1)),
                                    pkh(o2 - hfv(o2), o3 - hfv(o3)));
}

// ---------------------------------------------------------------------------
// fp32 -> single fp16 weight convert with destination column remap.
// ---------------------------------------------------------------------------
__global__ __launch_bounds__(256) void splitw_seg(const float* __restrict__ s,
                                                  __half* __restrict__ hi,
                                                  int srcN, int dstN, int dstOff) {
    const size_t base4 = (size_t)blockIdx.x * 1024 + threadIdx.x;
#pragma unroll
    for (int i = 0; i < 4; i++) {
        const size_t idx4 = base4 + i * 256;
        float4 v = ((const float4*)s)[idx4];
        const size_t el = idx4 * 4;
        const size_t k  = el / srcN;
        const size_t n  = el - k * srcN;
        const size_t e  = k * dstN + dstOff + n;
        *(uint2*)(hi + e) = make_uint2(pkh(v.x, v.y), pkh(v.z, v.w));
    }
}

// concat biases bq|bk|bv -> g_bqkv[3072]
__global__ __launch_bounds__(256) void concat_bias(const float* __restrict__ bq,
                                                   const float* __restrict__ bk,
                                                   const float* __restrict__ bv,
                                                   float* __restrict__ dst) {
    const int i = blockIdx.x * 256 + threadIdx.x;
    if (i >= NQKV) return;
    float v = (i < DD) ? bq[i] : (i < 2 * DD) ? bk[i - DD] : bv[i - 2 * DD];
    dst[i] = v;
}

// ---------------------------------------------------------------------------
// Launch
// ---------------------------------------------------------------------------
extern "C" void kernel_launch(void* const* d_in, const int* in_sizes, int n_in,
                              void* d_out, int out_size) {
    const float* x       = (const float*)d_in[0];
    const int*   amask   = (const int*)  d_in[1];
    const float* w_norm1 = (const float*)d_in[2];
    const float* wq      = (const float*)d_in[3];
    const float* bq      = (const float*)d_in[4];
    const float* wk      = (const float*)d_in[5];
    const float* bk      = (const float*)d_in[6];
    const float* wv      = (const float*)d_in[7];
    const float* bv      = (const float*)d_in[8];
    const float* wo      = (const float*)d_in[9];
    const float* bo      = (const float*)d_in[10];
    const float* w_norm2 = (const float*)d_in[11];
    const float* w_gate  = (const float*)d_in[12];
    const float* w_up    = (const float*)d_in[13];
    const float* w_down  = (const float*)d_in[14];
    float* out = (float*)d_out;

    float *gate, *x1, *bqkv;
    cudaGetSymbolAddress((void**)&gate, g_gate);
    cudaGetSymbolAddress((void**)&x1,   g_x1);
    cudaGetSymbolAddress((void**)&bqkv, g_bqkv);

    __half *hbh, *hbl, *qkvh, *qkvl, *ah, *al, *h2h, *h2l, *gah, *gal,
           *wqkvh, *woh, *wgh, *wuh, *wdh;
    cudaGetSymbolAddress((void**)&hbh,   g_hbh);   cudaGetSymbolAddress((void**)&hbl,   g_hbl);
    cudaGetSymbolAddress((void**)&qkvh,  g_qkvh);  cudaGetSymbolAddress((void**)&qkvl,  g_qkvl);
    cudaGetSymbolAddress((void**)&ah,    g_ah);    cudaGetSymbolAddress((void**)&al,    g_al);
    cudaGetSymbolAddress((void**)&h2h,   g_h2h);   cudaGetSymbolAddress((void**)&h2l,   g_h2l);
    cudaGetSymbolAddress((void**)&gah,   g_gah);   cudaGetSymbolAddress((void**)&gal,   g_gal);
    cudaGetSymbolAddress((void**)&wqkvh, g_wqkvh);
    cudaGetSymbolAddress((void**)&woh,   g_woh);
    cudaGetSymbolAddress((void**)&wgh,   g_wgh);
    cudaGetSymbolAddress((void**)&wuh,   g_wuh);
    cudaGetSymbolAddress((void**)&wdh,   g_wdh);

    cudaFuncSetAttribute(mmgemm<true,  false, true,  false>, cudaFuncAttributeMaxDynamicSharedMemorySize, GEMM_SMEM);
    cudaFuncSetAttribute(mmgemm<true,  true,  false, false>, cudaFuncAttributeMaxDynamicSharedMemorySize, GEMM_SMEM);
    cudaFuncSetAttribute(mmgemm<false, false, false, false>, cudaFuncAttributeMaxDynamicSharedMemorySize, GEMM_SMEM);
    cudaFuncSetAttribute(mmgemm<false, false, true,  true >, cudaFuncAttributeMaxDynamicSharedMemorySize, GEMM_SMEM);
    cudaFuncSetAttribute(mmgemm<false, true,  false, false>, cudaFuncAttributeMaxDynamicSharedMemorySize, GEMM_SMEM);
    cudaFuncSetAttribute(flash_mma, cudaFuncAttributeMaxDynamicSharedMemorySize, FLASH_SMEM);

    // Side stream for weight converts not needed until the O-proj / MLP phase.
    cudaStream_t s2;
    cudaStreamCreate(&s2);
    cudaEvent_t evFork, evJoin;
    cudaEventCreateWithFlags(&evFork, cudaEventDisableTiming);
    cudaEventCreateWithFlags(&evJoin, cudaEventDisableTiming);

    cudaEventRecord(evFork, 0);
    cudaStreamWaitEvent(s2, evFork, 0);

    // side stream: wo / wg / wu / wd converts (consumed at O-proj and later)
    splitw_seg<<<DD * DD / 4096, 256, 0, s2>>>(wo, woh, DD, DD, 0);
    splitw_seg<<<DD * FF / 4096, 256, 0, s2>>>(w_gate, wgh, FF, FF, 0);
    splitw_seg<<<DD * FF / 4096, 256, 0, s2>>>(w_up,   wuh, FF, FF, 0);
    splitw_seg<<<FF * DD / 4096, 256, 0, s2>>>(w_down, wdh, DD, DD, 0);
    cudaEventRecord(evJoin, s2);

    // main stream: QKV weight converts + bias + rmsnorm
    splitw_seg<<<DD * DD / 4096, 256>>>(wq, wqkvh, DD, NQKV, 0);
    splitw_seg<<<DD * DD / 4096, 256>>>(wk, wqkvh, DD, NQKV, DD);
    splitw_seg<<<DD * DD / 4096, 256>>>(wv, wqkvh, DD, NQKV, 2 * DD);
    concat_bias<<<(NQKV + 255) / 256, 256>>>(bq, bk, bv, bqkv);
    rmsnorm_split<<<MROWS, 256>>>(x, w_norm1, hbh, hbl);

    const dim3 gQKV(NQKV / 128, MROWS / 128);  // (24, 32)
    const dim3 gD(DD / 128, MROWS / 128);      // (8, 32)
    const dim3 gF(FF / 128, MROWS / 128);      // (32, 32)

    // fused QKV GEMM + flash attention
    mmgemm<true, false, true, false><<<gQKV, 256, GEMM_SMEM>>>(hbh, hbl, wqkvh, bqkv,
                                                               nullptr, nullptr, qkvh, qkvl,
                                                               MROWS, NQKV, DD);
    flash_mma<<<dim3(SS / 64, HH, BB), 128, FLASH_SMEM>>>(qkvh, qkvl, amask, ah, al);

    // join: O-proj is the first consumer of side-stream outputs
    cudaStreamWaitEvent(0, evJoin, 0);
    mmgemm<true, true, false, false><<<gD, 256, GEMM_SMEM>>>(ah, al, woh, bo, x,
                                                             x1, nullptr, nullptr, MROWS, DD, DD);

    // MLP sub-block
    rmsnorm_split<<<MROWS, 256>>>(x1, w_norm2, h2h, h2l);
    mmgemm<false, false, false, false><<<gF, 256, GEMM_SMEM>>>(h2h, h2l, wgh, nullptr, nullptr,
                                                               gate, nullptr, nullptr, MROWS, FF, DD);
    mmgemm<false, false, true, true><<<gF, 256, GEMM_SMEM>>>(h2h, h2l, wuh, nullptr, gate,
                                                             nullptr, gah, gal, MROWS, FF, DD);
    mmgemm<false, true, false, false><<<gD, 256, GEMM_SMEM>>>(gah, gal, wdh, nullptr, x1,
                                                              out, nullptr, nullptr, MROWS, DD, FF);
}

// round 12
// speedup vs baseline: 6.7145x; 1.6656x over previous
#include <cuda_runtime.h>
#include <cuda_fp16.h>
#include <cstdint>
#include <cstddef>

// ---------------------------------------------------------------------------
// Problem constants
// ---------------------------------------------------------------------------
#define BB 2
#define SS 2048
#define DD 1024
#define HH 16
#define HDIM 64
#define FF 4096
#define MROWS (BB * SS)          // 4096
#define NQKV 3072
#define EPS 1e-6f

// ---------------------------------------------------------------------------
// Device scratch (all operands single fp16; residual/gate stay fp32)
// ---------------------------------------------------------------------------
__device__ float g_gate[MROWS * FF];
__device__ float g_x1  [MROWS * DD];
__device__ float g_bqkv[NQKV];

__device__ __half g_hbh [MROWS * DD];
__device__ __half g_qkvh[MROWS * NQKV];
__device__ __half g_ah  [MROWS * DD];
__device__ __half g_h2h [MROWS * DD];
__device__ __half g_gah [MROWS * FF];

__device__ __half g_wqkvh[DD * NQKV];
__device__ __half g_woh[DD * DD];
__device__ __half g_wgh[DD * FF];
__device__ __half g_wuh[DD * FF];
__device__ __half g_wdh[FF * DD];

// ---------------------------------------------------------------------------
// Helpers (sm_80+ ISA only)
// ---------------------------------------------------------------------------
__device__ __forceinline__ uint32_t smem_u32(const void* p) {
    uint32_t a;
    asm("{ .reg .u64 t; cvta.to.shared.u64 t, %1; cvt.u32.u64 %0, t; }"
        : "=r"(a) : "l"(p));
    return a;
}

__device__ __forceinline__ void ldsm4(uint32_t* r, uint32_t addr) {
    asm volatile("ldmatrix.sync.aligned.m8n8.x4.shared.b16 {%0,%1,%2,%3}, [%4];"
                 : "=r"(r[0]), "=r"(r[1]), "=r"(r[2]), "=r"(r[3]) : "r"(addr));
}

__device__ __forceinline__ void ldsm4t(uint32_t* r, uint32_t addr) {
    asm volatile("ldmatrix.sync.aligned.m8n8.x4.trans.shared.b16 {%0,%1,%2,%3}, [%4];"
                 : "=r"(r[0]), "=r"(r[1]), "=r"(r[2]), "=r"(r[3]) : "r"(addr));
}

__device__ __forceinline__ void mma_f16(float* d, const uint32_t* a,
                                        const uint32_t* b) {
    asm volatile(
        "mma.sync.aligned.m16n8k16.row.col.f32.f16.f16.f32 "
        "{%0,%1,%2,%3}, {%4,%5,%6,%7}, {%8,%9}, {%0,%1,%2,%3};"
        : "+f"(d[0]), "+f"(d[1]), "+f"(d[2]), "+f"(d[3])
        : "r"(a[0]), "r"(a[1]), "r"(a[2]), "r"(a[3]), "r"(b[0]), "r"(b[1]));
}

__device__ __forceinline__ uint32_t pkh(float x, float y) {
    __half2 h = __floats2half2_rn(x, y);
    return *(uint32_t*)&h;
}

#define CP16(dst, src) \
    asm volatile("cp.async.cg.shared.global [%0], [%1], 16;" \
                 :: "r"(dst), "l"(src) : "memory")
#define CPCOMMIT() asm volatile("cp.async.commit_group;" ::: "memory")

__device__ __forceinline__ void cpwait(int keep) {
    if (keep) asm volatile("cp.async.wait_group 1;" ::: "memory");
    else      asm volatile("cp.async.wait_group 0;" ::: "memory");
}

// ---------------------------------------------------------------------------
// Single-pass fp16 tensor GEMM: C = A @ B (fp32 accum)
// CTA 128x128, K-chunk 32, 256 threads (8 warps of 64x32), 3-stage cp.async.
// ---------------------------------------------------------------------------
#define BKC 32
#define ASTRIDE 80                 // 32 fp16 (64B) + 16B pad
#define BSTRIDE 272                // 128 fp16 (256B) + 16B pad
#define OFF_AH 0
#define OFF_BH 10240
#define BUFSZ  18944
#define GEMM_SMEM (3 * BUFSZ)

template <bool BIAS, bool RES, bool SPLIT, bool SILU>
__global__ __launch_bounds__(256, 2)
void mmgemm(const __half* __restrict__ Ah,
            const __half* __restrict__ Bh,
            const float* __restrict__ bias, const float* __restrict__ res,
            float* __restrict__ C,
            __half* __restrict__ Chi,
            int M, int N, int K) {
    extern __shared__ char smem[];
    const uint32_t sb = smem_u32(smem);

    const int tid  = threadIdx.x;
    const int lane = tid & 31;
    const int wid  = tid >> 5;
    const int m0   = (wid >> 2) * 64;
    const int n0   = (wid & 3) * 32;
    const int mBase = blockIdx.y * 128;
    const int nBase = blockIdx.x * 128;

    const uint32_t aoff = (uint32_t)((lane & 15) * ASTRIDE + (lane >> 4) * 16);
    const uint32_t boff = (uint32_t)((lane & 15) * BSTRIDE + (lane >> 4) * 16);

    float acc[4][4][4];
#pragma unroll
    for (int i = 0; i < 4; i++)
#pragma unroll
        for (int j = 0; j < 4; j++)
#pragma unroll
            for (int t = 0; t < 4; t++) acc[i][j][t] = 0.f;

    const int nch = K / BKC;

#define ISSUE(c, buf)                                                         \
    do {                                                                      \
        const int k0_ = (c) * BKC;                                            \
        const uint32_t bp = sb + (uint32_t)((buf) * BUFSZ);                   \
        _Pragma("unroll")                                                     \
        for (int i = 0; i < 2; i++) {                                         \
            const int idx = tid + i * 256;                                    \
            const int r = idx >> 2, c16 = idx & 3;                            \
            const size_t so = (size_t)(mBase + r) * K + k0_ + c16 * 8;        \
            CP16(bp + OFF_AH + (uint32_t)(r * ASTRIDE + c16 * 16), Ah + so);  \
        }                                                                     \
        _Pragma("unroll")                                                     \
        for (int i = 0; i < 2; i++) {                                         \
            const int idx = tid + i * 256;                                    \
            const int kk = idx >> 4, c16 = idx & 15;                          \
            const size_t so = (size_t)(k0_ + kk) * N + nBase + c16 * 8;       \
            CP16(bp + OFF_BH + (uint32_t)(kk * BSTRIDE + c16 * 16), Bh + so); \
        }                                                                     \
        CPCOMMIT();                                                           \
    } while (0)

    ISSUE(0, 0);
    if (nch > 1) ISSUE(1, 1);

    int buf = 0;
    for (int c = 0; c < nch; c++) {
        cpwait(c + 1 < nch);
        __syncthreads();
        if (c + 2 < nch) {
            int nb = buf + 2; if (nb >= 3) nb -= 3;
            ISSUE(c + 2, nb);
        }

        const uint32_t bufb = sb + (uint32_t)(buf * BUFSZ);
        const uint32_t ah = bufb + OFF_AH + (uint32_t)(m0 * ASTRIDE) + aoff;
        const uint32_t bh = bufb + OFF_BH + (uint32_t)(n0 * 2) + boff;

#pragma unroll
        for (int ks = 0; ks < 2; ks++) {
            uint32_t fah[4][4], fbh[2][4];
#pragma unroll
            for (int mi = 0; mi < 4; mi++)
                ldsm4(fah[mi], ah + mi * (16 * ASTRIDE) + ks * 32);
#pragma unroll
            for (int np = 0; np < 2; np++)
                ldsm4t(fbh[np], bh + np * 32 + ks * (16 * BSTRIDE));
#pragma unroll
            for (int mi = 0; mi < 4; mi++)
#pragma unroll
                for (int nj = 0; nj < 4; nj++)
                    mma_f16(acc[mi][nj], fah[mi], &fbh[nj >> 1][(nj & 1) * 2]);
        }

        if (++buf >= 3) buf = 0;
    }
#undef ISSUE

    const int g  = lane >> 2;
    const int tc = (lane & 3) * 2;
#pragma unroll
    for (int mi = 0; mi < 4; mi++) {
        const int row = mBase + m0 + mi * 16 + g;
#pragma unroll
        for (int nj = 0; nj < 4; nj++) {
            const int col = nBase + n0 + nj * 8 + tc;
            float2 bv = make_float2(0.f, 0.f);
            if (BIAS) bv = *(const float2*)(bias + col);
            float v0 = acc[mi][nj][0] + bv.x;
            float v1 = acc[mi][nj][1] + bv.y;
            float v2 = acc[mi][nj][2] + bv.x;
            float v3 = acc[mi][nj][3] + bv.y;
            if (RES) {
                float2 e0 = *(const float2*)(res + (size_t)row * N + col);
                float2 e1 = *(const float2*)(res + (size_t)(row + 8) * N + col);
                v0 += e0.x; v1 += e0.y; v2 += e1.x; v3 += e1.y;
            }
            if (SILU) {   // res slot carries gate (fp32): out = silu(gate) * acc
                float2 g0 = *(const float2*)(res + (size_t)row * N + col);
                float2 g1 = *(const float2*)(res + (size_t)(row + 8) * N + col);
                v0 *= g0.x / (1.f + __expf(-g0.x));
                v1 *= g0.y / (1.f + __expf(-g0.y));
                v2 *= g1.x / (1.f + __expf(-g1.x));
                v3 *= g1.y / (1.f + __expf(-g1.y));
            }
            if (SPLIT) {
                *(uint32_t*)(Chi + (size_t)row * N + col)       = pkh(v0, v1);
                *(uint32_t*)(Chi + (size_t)(row + 8) * N + col) = pkh(v2, v3);
            } else {
                *(float2*)(C + (size_t)row * N + col)       = make_float2(v0, v1);
                *(float2*)(C + (size_t)(row + 8) * N + col) = make_float2(v2, v3);
            }
        }
    }
}

// ---------------------------------------------------------------------------
// Single-pass fp16 flash attention: 64q x 64k tiles, HD=64, 128 threads.
// Q/K/V from the fused [M, 3072] QKV buffer (row stride NQKV).
// ---------------------------------------------------------------------------
#define FQ_STRIDE 144
#define F_OFF_QH 0
#define F_OFF_ST 9216
#define F_STAGE  18432          // K (9216) + V (9216)
#define F_OFF_MK 46080          // 2 x 256B mask
#define FLASH_SMEM 46592

__global__ __launch_bounds__(128)
void flash_mma(const __half* __restrict__ QKVh,
               const int* __restrict__ amask,
               __half* __restrict__ Oh) {
    extern __shared__ char smem[];
    const uint32_t sb = smem_u32(smem);

    const int tid  = threadIdx.x;
    const int lane = tid & 31;
    const int wid  = tid >> 5;
    const int qb   = (gridDim.x - 1 - blockIdx.x) * 64;   // longest-first
    const int h    = blockIdx.y;
    const int b    = blockIdx.z;
    const int bS   = b * SS;
    const int hcol = h * HDIM;
    const int nt   = qb / 64 + 1;

    const __half* Qh = QKVh;
    const __half* Kh = QKVh + DD;
    const __half* Vh = QKVh + 2 * DD;

#pragma unroll
    for (int i = 0; i < 4; i++) {
        const int idx = tid + i * 128;
        const int r = idx >> 3, c16 = idx & 7;
        const size_t so = (size_t)(bS + qb + r) * NQKV + hcol + c16 * 8;
        CP16(sb + F_OFF_QH + (uint32_t)(r * FQ_STRIDE + c16 * 16), Qh + so);
    }

#define KVISSUE(kt, st)                                                       \
    do {                                                                      \
        const int kb_ = (kt) * 64;                                            \
        const uint32_t stb = sb + F_OFF_ST + (uint32_t)((st) * F_STAGE);      \
        _Pragma("unroll")                                                     \
        for (int i = 0; i < 4; i++) {                                         \
            const int idx = tid + i * 128;                                    \
            const int r = idx >> 3, c16 = idx & 7;                            \
            const size_t so = (size_t)(bS + kb_ + r) * NQKV + hcol + c16 * 8; \
            const uint32_t d = stb + (uint32_t)(r * FQ_STRIDE + c16 * 16);    \
            CP16(d + 0,    Kh + so);                                          \
            CP16(d + 9216, Vh + so);                                          \
        }                                                                     \
        if (tid < 16)                                                         \
            CP16(sb + F_OFF_MK + (uint32_t)((st) * 256 + tid * 16),           \
                 amask + bS + kb_ + tid * 4);                                 \
        CPCOMMIT();                                                           \
    } while (0)

    KVISSUE(0, 0);
    if (nt > 1) KVISSUE(1, 1);
    cpwait(nt > 1);
    __syncthreads();

    const int qr0 = wid * 16;
    const uint32_t qaddr = sb + (uint32_t)((qr0 + (lane & 15)) * FQ_STRIDE + (lane >> 4) * 16);
    uint32_t qfh[4][4];
#pragma unroll
    for (int kc = 0; kc < 4; kc++)
        ldsm4(qfh[kc], qaddr + F_OFF_QH + kc * 32);

    const int rloc0 = qr0 + (lane >> 2);
    const int tc2   = (lane & 3) * 2;
    const int r0g   = qb + rloc0;
    const int r1g   = r0g + 8;

    float o[8][4];
#pragma unroll
    for (int dt = 0; dt < 8; dt++)
#pragma unroll
        for (int e = 0; e < 4; e++) o[dt][e] = 0.f;
    float m0 = -1e30f, m1 = -1e30f, l0 = 0.f, l1 = 0.f;

    for (int kt = 0; kt < nt; kt++) {
        if (kt > 0) { cpwait(kt + 1 < nt); __syncthreads(); }
        const int kb = kt * 64;
        const uint32_t stb = sb + F_OFF_ST + (uint32_t)((kt & 1) * F_STAGE);
        const uint32_t kaddr = stb + (uint32_t)(((lane & 7) + ((lane >> 4) << 3)) * FQ_STRIDE
                                                + ((lane >> 3) & 1) * 16);
        const uint32_t vaddr = stb + 9216u + (uint32_t)((lane & 15) * FQ_STRIDE + (lane >> 4) * 16);
        const int* smk = (const int*)(smem + F_OFF_MK + (kt & 1) * 256);

        float s[8][4];
#pragma unroll
        for (int jt = 0; jt < 8; jt++)
#pragma unroll
            for (int e = 0; e < 4; e++) s[jt][e] = 0.f;

#pragma unroll
        for (int kc = 0; kc < 4; kc++)
#pragma unroll
            for (int g2 = 0; g2 < 4; g2++) {
                uint32_t kf[4];
                ldsm4(kf, kaddr + g2 * (16 * FQ_STRIDE) + kc * 32);
                mma_f16(s[2 * g2],     qfh[kc], kf + 0);
                mma_f16(s[2 * g2 + 1], qfh[kc], kf + 2);
            }

#pragma unroll
        for (int jt = 0; jt < 8; jt++) {
            const int c0 = kb + jt * 8 + tc2;
            const int c1 = c0 + 1;
            const bool k0 = smk[jt * 8 + tc2] != 0;
            const bool k1 = smk[jt * 8 + tc2 + 1] != 0;
            s[jt][0] = (c0 <= r0g && k0) ? s[jt][0] * 0.125f : -1e30f;
            s[jt][1] = (c1 <= r0g && k1) ? s[jt][1] * 0.125f : -1e30f;
            s[jt][2] = (c0 <= r1g && k0) ? s[jt][2] * 0.125f : -1e30f;
            s[jt][3] = (c1 <= r1g && k1) ? s[jt][3] * 0.125f : -1e30f;
        }

        float mx0 = -1e30f, mx1 = -1e30f;
#pragma unroll
        for (int jt = 0; jt < 8; jt++) {
            mx0 = fmaxf(mx0, fmaxf(s[jt][0], s[jt][1]));
            mx1 = fmaxf(mx1, fmaxf(s[jt][2], s[jt][3]));
        }
        mx0 = fmaxf(mx0, __shfl_xor_sync(0xffffffffu, mx0, 1));
        mx0 = fmaxf(mx0, __shfl_xor_sync(0xffffffffu, mx0, 2));
        mx1 = fmaxf(mx1, __shfl_xor_sync(0xffffffffu, mx1, 1));
        mx1 = fmaxf(mx1, __shfl_xor_sync(0xffffffffu, mx1, 2));
        const float mn0 = fmaxf(m0, mx0), mn1 = fmaxf(m1, mx1);
        const float cr0 = __expf(m0 - mn0), cr1 = __expf(m1 - mn1);
        float sum0 = 0.f, sum1 = 0.f;
#pragma unroll
        for (int jt = 0; jt < 8; jt++) {
            s[jt][0] = __expf(s[jt][0] - mn0);
            s[jt][1] = __expf(s[jt][1] - mn0);
            s[jt][2] = __expf(s[jt][2] - mn1);
            s[jt][3] = __expf(s[jt][3] - mn1);
            sum0 += s[jt][0] + s[jt][1];
            sum1 += s[jt][2] + s[jt][3];
        }
        sum0 += __shfl_xor_sync(0xffffffffu, sum0, 1);
        sum0 += __shfl_xor_sync(0xffffffffu, sum0, 2);
        sum1 += __shfl_xor_sync(0xffffffffu, sum1, 1);
        sum1 += __shfl_xor_sync(0xffffffffu, sum1, 2);
        l0 = l0 * cr0 + sum0;
        l1 = l1 * cr1 + sum1;
        m0 = mn0; m1 = mn1;
#pragma unroll
        for (int dt = 0; dt < 8; dt++) {
            o[dt][0] *= cr0; o[dt][1] *= cr0;
            o[dt][2] *= cr1; o[dt][3] *= cr1;
        }

#pragma unroll
        for (int kc2 = 0; kc2 < 4; kc2++) {
            uint32_t ph[4];
            ph[0] = pkh(s[2 * kc2][0],     s[2 * kc2][1]);
            ph[1] = pkh(s[2 * kc2][2],     s[2 * kc2][3]);
            ph[2] = pkh(s[2 * kc2 + 1][0], s[2 * kc2 + 1][1]);
            ph[3] = pkh(s[2 * kc2 + 1][2], s[2 * kc2 + 1][3]);
#pragma unroll
            for (int g2 = 0; g2 < 4; g2++) {
                uint32_t vf[4];
                ldsm4t(vf, vaddr + kc2 * (16 * FQ_STRIDE) + g2 * 32);
                mma_f16(o[2 * g2],     ph, vf + 0);
                mma_f16(o[2 * g2 + 1], ph, vf + 2);
            }
        }

        __syncthreads();
        if (kt + 2 < nt) KVISSUE(kt + 2, kt & 1);
    }
#undef KVISSUE

    const float inv0 = 1.f / l0, inv1 = 1.f / l1;
    const size_t e0 = (size_t)(bS + r0g) * DD + hcol;
    const size_t e1 = (size_t)(bS + r1g) * DD + hcol;
#pragma unroll
    for (int dt = 0; dt < 8; dt++) {
        const int col = dt * 8 + tc2;
        *(uint32_t*)(Oh + e0 + col) = pkh(o[dt][0] * inv0, o[dt][1] * inv0);
        *(uint32_t*)(Oh + e1 + col) = pkh(o[dt][2] * inv1, o[dt][3] * inv1);
    }
}

// ---------------------------------------------------------------------------
// RMSNorm with fp16 output
// ---------------------------------------------------------------------------
__global__ __launch_bounds__(256) void rmsnorm_h(const float* __restrict__ x,
                                                 const float* __restrict__ w,
                                                 __half* __restrict__ ohi) {
    __shared__ float red[8];
    const int row = blockIdx.x;
    const int tid = threadIdx.x;
    float4 v = ((const float4*)(x + (size_t)row * DD))[tid];
    float ss = v.x * v.x + v.y * v.y + v.z * v.z + v.w * v.w;
#pragma unroll
    for (int off = 16; off > 0; off >>= 1)
        ss += __shfl_xor_sync(0xffffffffu, ss, off);
    if ((tid & 31) == 0) red[tid >> 5] = ss;
    __syncthreads();
    float tot = 0.f;
#pragma unroll
    for (int i = 0; i < 8; i++) tot += red[i];
    const float inv = rsqrtf(tot * (1.0f / DD) + EPS);
    const float4 wv = ((const float4*)w)[tid];
    float o0 = wv.x * (v.x * inv), o1 = wv.y * (v.y * inv);
    float o2 = wv.z * (v.z * inv), o3 = wv.w * (v.w * inv);
    const size_t e = (size_t)row * DD + tid * 4;
    *(uint2*)(ohi + e) = make_uint2(pkh(o0, o1), pkh(o2, o3));
}

// ---------------------------------------------------------------------------
// fp32 -> fp16 weight convert with destination column remap.
// ---------------------------------------------------------------------------
__global__ __launch_bounds__(256) void splitw_seg(const float* __restrict__ s,
                                                  __half* __restrict__ hi,
                                                  int srcN, int dstN, int dstOff) {
    const size_t base4 = (size_t)blockIdx.x * 1024 + threadIdx.x;
#pragma unroll
    for (int i = 0; i < 4; i++) {
        const size_t idx4 = base4 + i * 256;
        float4 v = ((const float4*)s)[idx4];
        const size_t el = idx4 * 4;
        const size_t k  = el / srcN;
        const size_t n  = el - k * srcN;
        const size_t e  = k * dstN + dstOff + n;
        *(uint2*)(hi + e) = make_uint2(pkh(v.x, v.y), pkh(v.z, v.w));
    }
}

// concat biases bq|bk|bv -> g_bqkv[3072]
__global__ __launch_bounds__(256) void concat_bias(const float* __restrict__ bq,
                                                   const float* __restrict__ bk,
                                                   const float* __restrict__ bv,
                                                   float* __restrict__ dst) {
    const int i = blockIdx.x * 256 + threadIdx.x;
    if (i >= NQKV) return;
    float v = (i < DD) ? bq[i] : (i < 2 * DD) ? bk[i - DD] : bv[i - 2 * DD];
    dst[i] = v;
}

// ---------------------------------------------------------------------------
// Launch
// ---------------------------------------------------------------------------
extern "C" void kernel_launch(void* const* d_in, const int* in_sizes, int n_in,
                              void* d_out, int out_size) {
    const float* x       = (const float*)d_in[0];
    const int*   amask   = (const int*)  d_in[1];
    const float* w_norm1 = (const float*)d_in[2];
    const float* wq      = (const float*)d_in[3];
    const float* bq      = (const float*)d_in[4];
    const float* wk      = (const float*)d_in[5];
    const float* bk      = (const float*)d_in[6];
    const float* wv      = (const float*)d_in[7];
    const float* bv      = (const float*)d_in[8];
    const float* wo      = (const float*)d_in[9];
    const float* bo      = (const float*)d_in[10];
    const float* w_norm2 = (const float*)d_in[11];
    const float* w_gate  = (const float*)d_in[12];
    const float* w_up    = (const float*)d_in[13];
    const float* w_down  = (const float*)d_in[14];
    float* out = (float*)d_out;

    float *gate, *x1, *bqkv;
    cudaGetSymbolAddress((void**)&gate, g_gate);
    cudaGetSymbolAddress((void**)&x1,   g_x1);
    cudaGetSymbolAddress((void**)&bqkv, g_bqkv);

    __half *hbh, *qkvh, *ah, *h2h, *gah, *wqkvh, *woh, *wgh, *wuh, *wdh;
    cudaGetSymbolAddress((void**)&hbh,   g_hbh);
    cudaGetSymbolAddress((void**)&qkvh,  g_qkvh);
    cudaGetSymbolAddress((void**)&ah,    g_ah);
    cudaGetSymbolAddress((void**)&h2h,   g_h2h);
    cudaGetSymbolAddress((void**)&gah,   g_gah);
    cudaGetSymbolAddress((void**)&wqkvh, g_wqkvh);
    cudaGetSymbolAddress((void**)&woh,   g_woh);
    cudaGetSymbolAddress((void**)&wgh,   g_wgh);
    cudaGetSymbolAddress((void**)&wuh,   g_wuh);
    cudaGetSymbolAddress((void**)&wdh,   g_wdh);

    cudaFuncSetAttribute(mmgemm<true,  false, true,  false>, cudaFuncAttributeMaxDynamicSharedMemorySize, GEMM_SMEM);
    cudaFuncSetAttribute(mmgemm<true,  true,  false, false>, cudaFuncAttributeMaxDynamicSharedMemorySize, GEMM_SMEM);
    cudaFuncSetAttribute(mmgemm<false, false, false, false>, cudaFuncAttributeMaxDynamicSharedMemorySize, GEMM_SMEM);
    cudaFuncSetAttribute(mmgemm<false, false, true,  true >, cudaFuncAttributeMaxDynamicSharedMemorySize, GEMM_SMEM);
    cudaFuncSetAttribute(mmgemm<false, true,  false, false>, cudaFuncAttributeMaxDynamicSharedMemorySize, GEMM_SMEM);
    cudaFuncSetAttribute(flash_mma, cudaFuncAttributeMaxDynamicSharedMemorySize, FLASH_SMEM);

    // Side stream for weight converts not needed until the O-proj / MLP phase.
    cudaStream_t s2;
    cudaStreamCreate(&s2);
    cudaEvent_t evFork, evJoin;
    cudaEventCreateWithFlags(&evFork, cudaEventDisableTiming);
    cudaEventCreateWithFlags(&evJoin, cudaEventDisableTiming);

    cudaEventRecord(evFork, 0);
    cudaStreamWaitEvent(s2, evFork, 0);

    // side stream: wo / wg / wu / wd converts (consumed at O-proj and later)
    splitw_seg<<<DD * DD / 4096, 256, 0, s2>>>(wo, woh, DD, DD, 0);
    splitw_seg<<<DD * FF / 4096, 256, 0, s2>>>(w_gate, wgh, FF, FF, 0);
    splitw_seg<<<DD * FF / 4096, 256, 0, s2>>>(w_up,   wuh, FF, FF, 0);
    splitw_seg<<<FF * DD / 4096, 256, 0, s2>>>(w_down, wdh, DD, DD, 0);
    cudaEventRecord(evJoin, s2);

    // main stream: QKV weight converts + bias + rmsnorm
    splitw_seg<<<DD * DD / 4096, 256>>>(wq, wqkvh, DD, NQKV, 0);
    splitw_seg<<<DD * DD / 4096, 256>>>(wk, wqkvh, DD, NQKV, DD);
    splitw_seg<<<DD * DD / 4096, 256>>>(wv, wqkvh, DD, NQKV, 2 * DD);
    concat_bias<<<(NQKV + 255) / 256, 256>>>(bq, bk, bv, bqkv);
    rmsnorm_h<<<MROWS, 256>>>(x, w_norm1, hbh);

    const dim3 gQKV(NQKV / 128, MROWS / 128);  // (24, 32)
    const dim3 gD(DD / 128, MROWS / 128);      // (8, 32)
    const dim3 gF(FF / 128, MROWS / 128);      // (32, 32)

    // fused QKV GEMM + flash attention
    mmgemm<true, false, true, false><<<gQKV, 256, GEMM_SMEM>>>(hbh, wqkvh, bqkv,
                                                               nullptr, nullptr, qkvh,
                                                               MROWS, NQKV, DD);
    flash_mma<<<dim3(SS / 64, HH, BB), 128, FLASH_SMEM>>>(qkvh, amask, ah);

    // join: O-proj is the first consumer of side-stream outputs
    cudaStreamWaitEvent(0, evJoin, 0);
    mmgemm<true, true, false, false><<<gD, 256, GEMM_SMEM>>>(ah, woh, bo, x,
                                                             x1, nullptr, MROWS, DD, DD);

    // MLP sub-block
    rmsnorm_h<<<MROWS, 256>>>(x1, w_norm2, h2h);
    mmgemm<false, false, false, false><<<gF, 256, GEMM_SMEM>>>(h2h, wgh, nullptr, nullptr,
                                                               gate, nullptr, MROWS, FF, DD);
    mmgemm<false, false, true, true><<<gF, 256, GEMM_SMEM>>>(h2h, wuh, nullptr, gate,
                                                             nullptr, gah, MROWS, FF, DD);
    mmgemm<false, true, false, false><<<gD, 256, GEMM_SMEM>>>(gah, wdh, nullptr, x1,
                                                              out, nullptr, MROWS, DD, FF);
}